// round 1
// baseline (speedup 1.0000x reference)
#include <cuda_runtime.h>
#include <math.h>

#define S_LEN   1370
#define B_SZ    8
#define D_MODEL 1024
#define H_NUM   16
#define HD      64
#define M_TOT   (B_SZ * S_LEN)   // 10960

// Scratch for projected Q/K/V in [B, H, S, HD] layout (device globals: no allocs).
__device__ float g_Q[(size_t)M_TOT * D_MODEL];
__device__ float g_K[(size_t)M_TOT * D_MODEL];
__device__ float g_V[(size_t)M_TOT * D_MODEL];

// ---------------------------------------------------------------------------
// QKV projection: y = X @ W^T + b, written directly into [B,H,S,HD] layout.
// X: [M_TOT, 1024] row-major.  W: [1024, 1024] row-major (both K-contiguous).
// Classic register-tiled SGEMM: BM=BN=128, BK=16, 8x8 per thread, 256 threads.
// blockIdx.z selects q/k/v.
// ---------------------------------------------------------------------------
#define BM 128
#define BN 128
#define BK 16

__global__ __launch_bounds__(256) void qkv_gemm(
    const float* __restrict__ X,
    const float* __restrict__ Wq, const float* __restrict__ bq,
    const float* __restrict__ Wk, const float* __restrict__ bk,
    const float* __restrict__ Wv, const float* __restrict__ bv)
{
    const float* W;
    const float* bias;
    float* out;
    if (blockIdx.z == 0)      { W = Wq; bias = bq; out = g_Q; }
    else if (blockIdx.z == 1) { W = Wk; bias = bk; out = g_K; }
    else                      { W = Wv; bias = bv; out = g_V; }

    __shared__ float As[BK][BM];
    __shared__ float Bs[BK][BN];

    const int tid = threadIdx.x;
    const int n0 = blockIdx.x * BN;
    const int m0 = blockIdx.y * BM;

    const int ty = tid >> 4;          // 0..15
    const int tx = tid & 15;          // 0..15
    const int tm = ty * 8;
    const int tn = tx * 8;

    float acc[8][8];
#pragma unroll
    for (int i = 0; i < 8; i++)
#pragma unroll
        for (int j = 0; j < 8; j++) acc[i][j] = 0.0f;

    for (int k0 = 0; k0 < D_MODEL; k0 += BK) {
        // ---- load A (X) and B (W) tiles, both transposed into [BK][128] ----
#pragma unroll
        for (int p = 0; p < 2; p++) {
            int idx = tid + 256 * p;          // 0..511
            int row = idx >> 2;               // 0..127
            int c4  = (idx & 3) * 4;          // 0,4,8,12

            // A tile (guard M tail)
            float4 av = make_float4(0.f, 0.f, 0.f, 0.f);
            int gm = m0 + row;
            if (gm < M_TOT)
                av = *reinterpret_cast<const float4*>(X + (size_t)gm * D_MODEL + k0 + c4);
            As[c4 + 0][row] = av.x;
            As[c4 + 1][row] = av.y;
            As[c4 + 2][row] = av.z;
            As[c4 + 3][row] = av.w;

            // B tile (N always in range)
            float4 bv4 = *reinterpret_cast<const float4*>(W + (size_t)(n0 + row) * D_MODEL + k0 + c4);
            Bs[c4 + 0][row] = bv4.x;
            Bs[c4 + 1][row] = bv4.y;
            Bs[c4 + 2][row] = bv4.z;
            Bs[c4 + 3][row] = bv4.w;
        }
        __syncthreads();

#pragma unroll
        for (int k = 0; k < BK; k++) {
            float a[8], b[8];
#pragma unroll
            for (int i = 0; i < 8; i++) a[i] = As[k][tm + i];
#pragma unroll
            for (int j = 0; j < 8; j++) b[j] = Bs[k][tn + j];
#pragma unroll
            for (int i = 0; i < 8; i++)
#pragma unroll
                for (int j = 0; j < 8; j++)
                    acc[i][j] = fmaf(a[i], b[j], acc[i][j]);
        }
        __syncthreads();
    }

    // ---- epilogue: bias + scatter into [B,H,S,HD] ----
    // n within the thread's 8-col strip stays inside one head (tn is 8-aligned).
    const int nbase = n0 + tn;
    const int h = nbase >> 6;          // head
    const int d = nbase & 63;          // dim within head
    float bval[8];
#pragma unroll
    for (int j = 0; j < 8; j++) bval[j] = bias[nbase + j];

#pragma unroll
    for (int i = 0; i < 8; i++) {
        int m = m0 + tm + i;
        if (m >= M_TOT) break;
        int bb = m / S_LEN;
        int ss = m - bb * S_LEN;
        float* orow = out + (((size_t)(bb * H_NUM + h) * S_LEN + ss) * HD + d);
        float4 v0 = make_float4(acc[i][0] + bval[0], acc[i][1] + bval[1],
                                acc[i][2] + bval[2], acc[i][3] + bval[3]);
        float4 v1 = make_float4(acc[i][4] + bval[4], acc[i][5] + bval[5],
                                acc[i][6] + bval[6], acc[i][7] + bval[7]);
        *reinterpret_cast<float4*>(orow)     = v0;
        *reinterpret_cast<float4*>(orow + 4) = v1;
    }
}

// ---------------------------------------------------------------------------
// Flash attention, fp32. One query per thread, 128 queries per block.
// K/V tiles of BC=32 rows staged in smem. Online softmax.
// Output written back in [B, S, H*HD] layout.
// ---------------------------------------------------------------------------
#define BC 32
#define NEG_BIG (-1e30f)

__global__ __launch_bounds__(128) void attn_kernel(float* __restrict__ out)
{
    const int h = blockIdx.y;
    const int b = blockIdx.z;
    const int qi = blockIdx.x * 128 + threadIdx.x;
    const bool valid = (qi < S_LEN);

    const size_t bh_base = (size_t)(b * H_NUM + h) * S_LEN * HD;
    const float* Qb = g_Q + bh_base;
    const float* Kb = g_K + bh_base;
    const float* Vb = g_V + bh_base;

    __shared__ float Ks[BC][HD];
    __shared__ float Vs[BC][HD];

    // Load this thread's query row into registers (zeros if out of range).
    float4 q4[16];
    if (valid) {
        const float4* qp = reinterpret_cast<const float4*>(Qb + (size_t)qi * HD);
#pragma unroll
        for (int i = 0; i < 16; i++) q4[i] = qp[i];
    } else {
#pragma unroll
        for (int i = 0; i < 16; i++) q4[i] = make_float4(0.f, 0.f, 0.f, 0.f);
    }

    float4 o4[16];
#pragma unroll
    for (int i = 0; i < 16; i++) o4[i] = make_float4(0.f, 0.f, 0.f, 0.f);
    float mval = NEG_BIG;
    float lsum = 0.0f;
    const float scale = 0.125f;   // 1/sqrt(64)

    const int tid = threadIdx.x;

    for (int k0 = 0; k0 < S_LEN; k0 += BC) {
        const int rem = min(BC, S_LEN - k0);

        __syncthreads();   // previous tile fully consumed
        // stage K/V tiles: 32x64 floats = 512 float4 each; 4 per thread
#pragma unroll
        for (int p = 0; p < 4; p++) {
            int idx = tid + 128 * p;      // 0..511
            int row = idx >> 4;           // 0..31
            int c4  = idx & 15;           // 0..15
            float4 kv = make_float4(0.f, 0.f, 0.f, 0.f);
            float4 vv = make_float4(0.f, 0.f, 0.f, 0.f);
            if (row < rem) {
                kv = *reinterpret_cast<const float4*>(Kb + (size_t)(k0 + row) * HD + c4 * 4);
                vv = *reinterpret_cast<const float4*>(Vb + (size_t)(k0 + row) * HD + c4 * 4);
            }
            *reinterpret_cast<float4*>(&Ks[row][c4 * 4]) = kv;
            *reinterpret_cast<float4*>(&Vs[row][c4 * 4]) = vv;
        }
        __syncthreads();

        // scores for this tile
        float s[BC];
#pragma unroll 4
        for (int j = 0; j < BC; j++) {
            const float4* kr = reinterpret_cast<const float4*>(&Ks[j][0]);
            float acc = 0.0f;
#pragma unroll
            for (int i = 0; i < 16; i++) {
                float4 kv = kr[i];
                acc = fmaf(q4[i].x, kv.x, acc);
                acc = fmaf(q4[i].y, kv.y, acc);
                acc = fmaf(q4[i].z, kv.z, acc);
                acc = fmaf(q4[i].w, kv.w, acc);
            }
            s[j] = (j < rem) ? acc * scale : NEG_BIG;
        }

        // online softmax update
        float tmax = NEG_BIG;
#pragma unroll
        for (int j = 0; j < BC; j++) tmax = fmaxf(tmax, s[j]);
        float newm = fmaxf(mval, tmax);
        float corr = __expf(mval - newm);
        lsum *= corr;
#pragma unroll
        for (int i = 0; i < 16; i++) {
            o4[i].x *= corr; o4[i].y *= corr; o4[i].z *= corr; o4[i].w *= corr;
        }
#pragma unroll
        for (int j = 0; j < BC; j++) {
            float p = __expf(s[j] - newm);
            s[j] = p;
            lsum += p;
        }
        mval = newm;

        // O += P * V
#pragma unroll 4
        for (int j = 0; j < BC; j++) {
            float p = s[j];
            const float4* vr = reinterpret_cast<const float4*>(&Vs[j][0]);
#pragma unroll
            for (int i = 0; i < 16; i++) {
                float4 vv = vr[i];
                o4[i].x = fmaf(p, vv.x, o4[i].x);
                o4[i].y = fmaf(p, vv.y, o4[i].y);
                o4[i].z = fmaf(p, vv.z, o4[i].z);
                o4[i].w = fmaf(p, vv.w, o4[i].w);
            }
        }
    }

    if (valid) {
        float inv = 1.0f / lsum;
        float4* orow = reinterpret_cast<float4*>(
            out + ((size_t)(b * S_LEN + qi) * D_MODEL + h * HD));
#pragma unroll
        for (int i = 0; i < 16; i++) {
            float4 v = o4[i];
            v.x *= inv; v.y *= inv; v.z *= inv; v.w *= inv;
            orow[i] = v;
        }
    }
}

// ---------------------------------------------------------------------------
extern "C" void kernel_launch(void* const* d_in, const int* in_sizes, int n_in,
                              void* d_out, int out_size)
{
    const float* X  = (const float*)d_in[0];
    const float* Wq = (const float*)d_in[1];
    const float* bq = (const float*)d_in[2];
    const float* Wk = (const float*)d_in[3];
    const float* bk = (const float*)d_in[4];
    const float* Wv = (const float*)d_in[5];
    const float* bv = (const float*)d_in[6];
    float* out = (float*)d_out;

    dim3 g1(D_MODEL / BN, (M_TOT + BM - 1) / BM, 3);
    qkv_gemm<<<g1, 256>>>(X, Wq, bq, Wk, bk, Wv, bv);

    dim3 g2((S_LEN + 127) / 128, H_NUM, B_SZ);
    attn_kernel<<<g2, 128>>>(out);
}

// round 2
// speedup vs baseline: 1.9306x; 1.9306x over previous
#include <cuda_runtime.h>
#include <math.h>

#define S_LEN   1370
#define B_SZ    8
#define D_MODEL 1024
#define H_NUM   16
#define HD      64
#define M_TOT   (B_SZ * S_LEN)   // 10960

// Scratch for projected Q/K/V in [B, H, S, HD] layout.
__device__ float g_Q[(size_t)M_TOT * D_MODEL];
__device__ float g_K[(size_t)M_TOT * D_MODEL];
__device__ float g_V[(size_t)M_TOT * D_MODEL];

// ---------------------------------------------------------------------------
// tf32 helpers
// ---------------------------------------------------------------------------
__device__ __forceinline__ unsigned f2tf(float x) {
    unsigned u;
    asm("cvt.rna.tf32.f32 %0, %1;" : "=r"(u) : "f"(x));
    return u;
}

// D += A * B  (m16n8k8, tf32 in, f32 accum). A: 4 regs, B: 2 regs, C: 4 regs.
__device__ __forceinline__ void mma8(float* c, const unsigned* a, unsigned b0, unsigned b1) {
    asm volatile(
        "mma.sync.aligned.m16n8k8.row.col.f32.tf32.tf32.f32 "
        "{%0,%1,%2,%3},{%4,%5,%6,%7},{%8,%9},{%0,%1,%2,%3};\n"
        : "+f"(c[0]), "+f"(c[1]), "+f"(c[2]), "+f"(c[3])
        : "r"(a[0]), "r"(a[1]), "r"(a[2]), "r"(a[3]), "r"(b0), "r"(b1));
}

// ---------------------------------------------------------------------------
// QKV projection GEMM on tensor cores, 3-term tf32 compensation (near-fp32).
// y = X @ W^T + b, scattered into [B,H,S,HD].
// Block tile 128x128, BK=32, 8 warps, warp tile 64x32.
// smem layout: As[k][m], Bs[k][n], pad 4 -> conflict-free fragment loads.
// ---------------------------------------------------------------------------
__global__ __launch_bounds__(256) void qkv_gemm_tc(
    const float* __restrict__ X,
    const float* __restrict__ Wq, const float* __restrict__ bq,
    const float* __restrict__ Wk, const float* __restrict__ bk,
    const float* __restrict__ Wv, const float* __restrict__ bv)
{
    const float* W; const float* bias; float* out;
    if (blockIdx.z == 0)      { W = Wq; bias = bq; out = g_Q; }
    else if (blockIdx.z == 1) { W = Wk; bias = bk; out = g_K; }
    else                      { W = Wv; bias = bv; out = g_V; }

    __shared__ float As[32][132];
    __shared__ float Bs[32][132];

    const int tid  = threadIdx.x;
    const int lane = tid & 31;
    const int w    = tid >> 5;
    const int wm   = w >> 2;        // 0..1 : m-quadrant (64 rows)
    const int wn   = w & 3;         // 0..3 : n-quadrant (32 cols)
    const int g    = lane >> 2;     // groupID 0..7
    const int tig  = lane & 3;      // thread-in-group 0..3

    const int m0 = blockIdx.y * 128;
    const int n0 = blockIdx.x * 128;

    float c[4][4][4];
#pragma unroll
    for (int mf = 0; mf < 4; mf++)
#pragma unroll
        for (int nf = 0; nf < 4; nf++)
#pragma unroll
            for (int cc = 0; cc < 4; cc++) c[mf][nf][cc] = 0.0f;

    for (int k0 = 0; k0 < D_MODEL; k0 += 32) {
        // ---- stage tiles (transposed to [k][m] / [k][n]) ----
#pragma unroll
        for (int p = 0; p < 4; p++) {
            int li  = tid + 256 * p;      // 0..1023
            int row = li >> 3;            // 0..127
            int c4  = (li & 7) * 4;       // 0,4,...,28

            float4 av = make_float4(0.f, 0.f, 0.f, 0.f);
            if (m0 + row < M_TOT)
                av = *reinterpret_cast<const float4*>(X + (size_t)(m0 + row) * D_MODEL + k0 + c4);
            As[c4 + 0][row] = av.x; As[c4 + 1][row] = av.y;
            As[c4 + 2][row] = av.z; As[c4 + 3][row] = av.w;

            float4 bv4 = *reinterpret_cast<const float4*>(W + (size_t)(n0 + row) * D_MODEL + k0 + c4);
            Bs[c4 + 0][row] = bv4.x; Bs[c4 + 1][row] = bv4.y;
            Bs[c4 + 2][row] = bv4.z; Bs[c4 + 3][row] = bv4.w;
        }
        __syncthreads();

#pragma unroll
        for (int kk = 0; kk < 4; kk++) {
            // A fragments (hi/lo)
            unsigned ah[4][4], al[4][4];
#pragma unroll
            for (int mf = 0; mf < 4; mf++) {
                int mrow = wm * 64 + mf * 16 + g;
                float f0 = As[kk * 8 + tig    ][mrow];
                float f1 = As[kk * 8 + tig    ][mrow + 8];
                float f2 = As[kk * 8 + tig + 4][mrow];
                float f3 = As[kk * 8 + tig + 4][mrow + 8];
                ah[mf][0] = f2tf(f0); al[mf][0] = f2tf(f0 - __uint_as_float(ah[mf][0]));
                ah[mf][1] = f2tf(f1); al[mf][1] = f2tf(f1 - __uint_as_float(ah[mf][1]));
                ah[mf][2] = f2tf(f2); al[mf][2] = f2tf(f2 - __uint_as_float(ah[mf][2]));
                ah[mf][3] = f2tf(f3); al[mf][3] = f2tf(f3 - __uint_as_float(ah[mf][3]));
            }
            // B fragments (hi/lo)
            unsigned bh[4][2], bl[4][2];
#pragma unroll
            for (int nf = 0; nf < 4; nf++) {
                int ncol = wn * 32 + nf * 8 + g;
                float f0 = Bs[kk * 8 + tig    ][ncol];
                float f1 = Bs[kk * 8 + tig + 4][ncol];
                bh[nf][0] = f2tf(f0); bl[nf][0] = f2tf(f0 - __uint_as_float(bh[nf][0]));
                bh[nf][1] = f2tf(f1); bl[nf][1] = f2tf(f1 - __uint_as_float(bh[nf][1]));
            }
            // 3-term compensated mma
#pragma unroll
            for (int mf = 0; mf < 4; mf++)
#pragma unroll
                for (int nf = 0; nf < 4; nf++) {
                    mma8(c[mf][nf], ah[mf], bh[nf][0], bh[nf][1]);
                    mma8(c[mf][nf], ah[mf], bl[nf][0], bl[nf][1]);
                    mma8(c[mf][nf], al[mf], bh[nf][0], bh[nf][1]);
                }
        }
        __syncthreads();
    }

    // ---- epilogue: bias + scatter into [B,H,S,HD] ----
#pragma unroll
    for (int mf = 0; mf < 4; mf++) {
#pragma unroll
        for (int nf = 0; nf < 4; nf++) {
            int n = n0 + wn * 32 + nf * 8 + 2 * tig;
            int h = n >> 6, d = n & 63;
            float bv0 = bias[n], bv1 = bias[n + 1];
#pragma unroll
            for (int half = 0; half < 2; half++) {
                int m = m0 + wm * 64 + mf * 16 + g + half * 8;
                if (m < M_TOT) {
                    int bb = m / S_LEN;
                    int ss = m - bb * S_LEN;
                    float2 v;
                    v.x = c[mf][nf][half * 2 + 0] + bv0;
                    v.y = c[mf][nf][half * 2 + 1] + bv1;
                    *reinterpret_cast<float2*>(
                        out + (((size_t)(bb * H_NUM + h) * S_LEN + ss) * HD + d)) = v;
                }
            }
        }
    }
}

// ---------------------------------------------------------------------------
// Flash attention on tensor cores (single-pass tf32).
// CTA: 64 queries (4 warps x 16), key tiles of 64. S/P in registers,
// P re-fragmented through the K smem tile for the PV mma.
// ---------------------------------------------------------------------------
#define NEG_BIG (-1e30f)

__global__ __launch_bounds__(128) void attn_tc(float* __restrict__ out)
{
    __shared__ float Ks[64][68];   // K tile, reused as P after scores
    __shared__ float Vs[64][68];

    const int h  = blockIdx.y;
    const int b  = blockIdx.z;
    const int qt = blockIdx.x;
    const int tid  = threadIdx.x;
    const int lane = tid & 31;
    const int w    = tid >> 5;
    const int g    = lane >> 2;
    const int tig  = lane & 3;

    const size_t base = (size_t)(b * H_NUM + h) * S_LEN * HD;
    const float* Qb = g_Q + base;
    const float* Kb = g_K + base;
    const float* Vb = g_V + base;

    const int q0 = qt * 64 + w * 16;
    const int r1 = q0 + g;
    const int r2 = q0 + g + 8;

    // Q fragments with 1/sqrt(64) folded in (exact power of two).
    unsigned qa[8][4];
#pragma unroll
    for (int kk = 0; kk < 8; kk++) {
        int c0 = kk * 8 + tig;
        qa[kk][0] = (r1 < S_LEN) ? f2tf(Qb[(size_t)r1 * HD + c0    ] * 0.125f) : 0u;
        qa[kk][1] = (r2 < S_LEN) ? f2tf(Qb[(size_t)r2 * HD + c0    ] * 0.125f) : 0u;
        qa[kk][2] = (r1 < S_LEN) ? f2tf(Qb[(size_t)r1 * HD + c0 + 4] * 0.125f) : 0u;
        qa[kk][3] = (r2 < S_LEN) ? f2tf(Qb[(size_t)r2 * HD + c0 + 4] * 0.125f) : 0u;
    }

    float oc[8][4];
#pragma unroll
    for (int nf = 0; nf < 8; nf++)
#pragma unroll
        for (int cc = 0; cc < 4; cc++) oc[nf][cc] = 0.0f;
    float m1 = NEG_BIG, m2 = NEG_BIG, l1 = 0.0f, l2 = 0.0f;

    const int ntiles = (S_LEN + 63) / 64;   // 22
    for (int kt = 0; kt < ntiles; kt++) {
        const int rem = min(64, S_LEN - kt * 64);

        // ---- stage K/V tiles ----
#pragma unroll
        for (int p = 0; p < 8; p++) {
            int li  = tid + 128 * p;       // 0..1023
            int row = li >> 4;             // 0..63
            int c4  = (li & 15) * 4;
            float4 kv = make_float4(0.f, 0.f, 0.f, 0.f);
            float4 vv = make_float4(0.f, 0.f, 0.f, 0.f);
            if (row < rem) {
                kv = *reinterpret_cast<const float4*>(Kb + (size_t)(kt * 64 + row) * HD + c4);
                vv = *reinterpret_cast<const float4*>(Vb + (size_t)(kt * 64 + row) * HD + c4);
            }
            *reinterpret_cast<float4*>(&Ks[row][c4]) = kv;
            *reinterpret_cast<float4*>(&Vs[row][c4]) = vv;
        }
        __syncthreads();

        // ---- S = Q * K^T (pre-scaled) ----
        float sc[8][4];
#pragma unroll
        for (int nf = 0; nf < 8; nf++)
#pragma unroll
            for (int cc = 0; cc < 4; cc++) sc[nf][cc] = 0.0f;

#pragma unroll
        for (int kk = 0; kk < 8; kk++) {
#pragma unroll
            for (int nf = 0; nf < 8; nf++) {
                unsigned b0 = f2tf(Ks[nf * 8 + g][kk * 8 + tig    ]);
                unsigned b1 = f2tf(Ks[nf * 8 + g][kk * 8 + tig + 4]);
                mma8(sc[nf], qa[kk], b0, b1);
            }
        }

        // ---- mask tail columns ----
        if (rem < 64) {
#pragma unroll
            for (int nf = 0; nf < 8; nf++) {
                int col = nf * 8 + 2 * tig;
                if (col     >= rem) { sc[nf][0] = NEG_BIG; sc[nf][2] = NEG_BIG; }
                if (col + 1 >= rem) { sc[nf][1] = NEG_BIG; sc[nf][3] = NEG_BIG; }
            }
        }

        // ---- online softmax (rows g and g+8) ----
        float rmax1 = NEG_BIG, rmax2 = NEG_BIG;
#pragma unroll
        for (int nf = 0; nf < 8; nf++) {
            rmax1 = fmaxf(rmax1, fmaxf(sc[nf][0], sc[nf][1]));
            rmax2 = fmaxf(rmax2, fmaxf(sc[nf][2], sc[nf][3]));
        }
        rmax1 = fmaxf(rmax1, __shfl_xor_sync(0xffffffffu, rmax1, 1));
        rmax1 = fmaxf(rmax1, __shfl_xor_sync(0xffffffffu, rmax1, 2));
        rmax2 = fmaxf(rmax2, __shfl_xor_sync(0xffffffffu, rmax2, 1));
        rmax2 = fmaxf(rmax2, __shfl_xor_sync(0xffffffffu, rmax2, 2));

        float nm1 = fmaxf(m1, rmax1);
        float nm2 = fmaxf(m2, rmax2);
        float corr1 = __expf(m1 - nm1);
        float corr2 = __expf(m2 - nm2);

        float ps1 = 0.0f, ps2 = 0.0f;
#pragma unroll
        for (int nf = 0; nf < 8; nf++) {
            sc[nf][0] = __expf(sc[nf][0] - nm1); ps1 += sc[nf][0];
            sc[nf][1] = __expf(sc[nf][1] - nm1); ps1 += sc[nf][1];
            sc[nf][2] = __expf(sc[nf][2] - nm2); ps2 += sc[nf][2];
            sc[nf][3] = __expf(sc[nf][3] - nm2); ps2 += sc[nf][3];
        }
        ps1 += __shfl_xor_sync(0xffffffffu, ps1, 1);
        ps1 += __shfl_xor_sync(0xffffffffu, ps1, 2);
        ps2 += __shfl_xor_sync(0xffffffffu, ps2, 1);
        ps2 += __shfl_xor_sync(0xffffffffu, ps2, 2);

        l1 = l1 * corr1 + ps1;
        l2 = l2 * corr2 + ps2;
#pragma unroll
        for (int nf = 0; nf < 8; nf++) {
            oc[nf][0] *= corr1; oc[nf][1] *= corr1;
            oc[nf][2] *= corr2; oc[nf][3] *= corr2;
        }
        m1 = nm1; m2 = nm2;

        __syncthreads();   // all warps finished reading Ks as K

        // ---- write P into Ks (each warp its own 16 rows) ----
#pragma unroll
        for (int nf = 0; nf < 8; nf++) {
            int col = nf * 8 + 2 * tig;
            Ks[w * 16 + g    ][col    ] = sc[nf][0];
            Ks[w * 16 + g    ][col + 1] = sc[nf][1];
            Ks[w * 16 + g + 8][col    ] = sc[nf][2];
            Ks[w * 16 + g + 8][col + 1] = sc[nf][3];
        }
        __syncwarp();

        // ---- O += P * V ----
#pragma unroll
        for (int kk = 0; kk < 8; kk++) {
            unsigned pa[4];
            pa[0] = f2tf(Ks[w * 16 + g    ][kk * 8 + tig    ]);
            pa[1] = f2tf(Ks[w * 16 + g + 8][kk * 8 + tig    ]);
            pa[2] = f2tf(Ks[w * 16 + g    ][kk * 8 + tig + 4]);
            pa[3] = f2tf(Ks[w * 16 + g + 8][kk * 8 + tig + 4]);
#pragma unroll
            for (int nf = 0; nf < 8; nf++) {
                unsigned b0 = f2tf(Vs[kk * 8 + tig    ][nf * 8 + g]);
                unsigned b1 = f2tf(Vs[kk * 8 + tig + 4][nf * 8 + g]);
                mma8(oc[nf], pa, b0, b1);
            }
        }
        __syncthreads();   // before next tile overwrites Ks/Vs
    }

    // ---- normalize + write out [B,S,H*HD] ----
    float inv1 = 1.0f / l1;
    float inv2 = 1.0f / l2;
#pragma unroll
    for (int nf = 0; nf < 8; nf++) {
        int d = nf * 8 + 2 * tig;
        if (r1 < S_LEN) {
            float2 v; v.x = oc[nf][0] * inv1; v.y = oc[nf][1] * inv1;
            *reinterpret_cast<float2*>(out + (size_t)(b * S_LEN + r1) * D_MODEL + h * HD + d) = v;
        }
        if (r2 < S_LEN) {
            float2 v; v.x = oc[nf][2] * inv2; v.y = oc[nf][3] * inv2;
            *reinterpret_cast<float2*>(out + (size_t)(b * S_LEN + r2) * D_MODEL + h * HD + d) = v;
        }
    }
}

// ---------------------------------------------------------------------------
extern "C" void kernel_launch(void* const* d_in, const int* in_sizes, int n_in,
                              void* d_out, int out_size)
{
    const float* X  = (const float*)d_in[0];
    const float* Wq = (const float*)d_in[1];
    const float* bq = (const float*)d_in[2];
    const float* Wk = (const float*)d_in[3];
    const float* bk = (const float*)d_in[4];
    const float* Wv = (const float*)d_in[5];
    const float* bv = (const float*)d_in[6];
    float* out = (float*)d_out;

    dim3 g1(D_MODEL / 128, (M_TOT + 127) / 128, 3);
    qkv_gemm_tc<<<g1, 256>>>(X, Wq, bq, Wk, bk, Wv, bv);

    dim3 g2((S_LEN + 63) / 64, H_NUM, B_SZ);
    attn_tc<<<g2, 128>>>(out);
}

// round 4
// speedup vs baseline: 2.2588x; 1.1700x over previous
#include <cuda_runtime.h>
#include <cuda_bf16.h>
#include <math.h>
#include <stdint.h>

#define S_LEN   1370
#define B_SZ    8
#define D_MODEL 1024
#define H_NUM   16
#define HD      64
#define M_TOT   (B_SZ * S_LEN)   // 10960

__device__ float g_Q[(size_t)M_TOT * D_MODEL];
__device__ float g_K[(size_t)M_TOT * D_MODEL];
__device__ float g_V[(size_t)M_TOT * D_MODEL];

// ---------------------------------------------------------------------------
// helpers
// ---------------------------------------------------------------------------
__device__ __forceinline__ unsigned f2tf(float x) {
    unsigned u;
    asm("cvt.rna.tf32.f32 %0, %1;" : "=r"(u) : "f"(x));
    return u;
}
__device__ __forceinline__ float tf32f(float x) { return __uint_as_float(f2tf(x)); }

// tf32 m16n8k8 (attention)
__device__ __forceinline__ void mma8(float* c, const unsigned* a, unsigned b0, unsigned b1) {
    asm volatile(
        "mma.sync.aligned.m16n8k8.row.col.f32.tf32.tf32.f32 "
        "{%0,%1,%2,%3},{%4,%5,%6,%7},{%8,%9},{%0,%1,%2,%3};\n"
        : "+f"(c[0]), "+f"(c[1]), "+f"(c[2]), "+f"(c[3])
        : "r"(a[0]), "r"(a[1]), "r"(a[2]), "r"(a[3]), "r"(b0), "r"(b1));
}

// bf16 m16n8k16 (projection GEMM)
__device__ __forceinline__ void mma16(float* c, const uint32_t* a, uint32_t b0, uint32_t b1) {
    asm volatile(
        "mma.sync.aligned.m16n8k16.row.col.f32.bf16.bf16.f32 "
        "{%0,%1,%2,%3},{%4,%5,%6,%7},{%8,%9},{%0,%1,%2,%3};\n"
        : "+f"(c[0]), "+f"(c[1]), "+f"(c[2]), "+f"(c[3])
        : "r"(a[0]), "r"(a[1]), "r"(a[2]), "r"(a[3]), "r"(b0), "r"(b1));
}

__device__ __forceinline__ void ldm_x4(uint32_t& r0, uint32_t& r1, uint32_t& r2, uint32_t& r3,
                                       uint32_t addr) {
    asm volatile("ldmatrix.sync.aligned.m8n8.x4.shared.b16 {%0,%1,%2,%3}, [%4];"
                 : "=r"(r0), "=r"(r1), "=r"(r2), "=r"(r3) : "r"(addr));
}

__device__ __forceinline__ uint32_t smem_u32(const void* p) {
    return (uint32_t)__cvta_generic_to_shared(p);
}

// ---------------------------------------------------------------------------
// QKV projection GEMM: y = X @ W^T + b  scattered into [B,H,S,HD].
// bf16 3-term compensation on m16n8k16 HMMA.
// Block 128x128, 512 threads (16 warps, 4x4), warp tile 32x32, K slab = 32.
// smem: hi/lo bf16 tiles, 32 bf16 per row padded to 80B (ldmatrix
// conflict-free: bank step 20 mod 32).
// ---------------------------------------------------------------------------
#define PITCH    80
#define A_HI_OFF 0
#define A_LO_OFF (128 * PITCH)
#define B_HI_OFF (2 * 128 * PITCH)
#define B_LO_OFF (3 * 128 * PITCH)
#define GEMM_SMEM (4 * 128 * PITCH)   // 40960

__global__ __launch_bounds__(512, 1) void qkv_bf16(
    const float* __restrict__ X,
    const float* __restrict__ Wq, const float* __restrict__ bq,
    const float* __restrict__ Wk, const float* __restrict__ bk,
    const float* __restrict__ Wv, const float* __restrict__ bv)
{
    __shared__ char smem[GEMM_SMEM];
    const uint32_t sb = smem_u32(smem);

    const float* W; const float* bias; float* out;
    if (blockIdx.z == 0)      { W = Wq; bias = bq; out = g_Q; }
    else if (blockIdx.z == 1) { W = Wk; bias = bk; out = g_K; }
    else                      { W = Wv; bias = bv; out = g_V; }

    const int tid  = threadIdx.x;
    const int lane = tid & 31;
    const int wid  = tid >> 5;
    const int wm   = wid >> 2;      // 0..3 : 32-row strip
    const int wn   = wid & 3;       // 0..3 : 32-col strip
    const int g    = lane >> 2;
    const int tig  = lane & 3;

    const int m0 = blockIdx.y * 128;
    const int n0 = blockIdx.x * 128;

    // staging coords: each thread handles 8 elements of one row
    const int srow = tid >> 2;            // 0..127
    const int sc8  = (tid & 3) * 8;       // 0,8,16,24

    // ldmatrix address components (per-thread)
    const int mat = lane >> 3;            // 0..3
    const int mr  = lane & 7;             // 0..7

    float c[2][4][4];
#pragma unroll
    for (int mf = 0; mf < 2; mf++)
#pragma unroll
        for (int nf = 0; nf < 4; nf++)
#pragma unroll
            for (int cc = 0; cc < 4; cc++) c[mf][nf][cc] = 0.0f;

    for (int s = 0; s < 32; s++) {
        const int k0 = s * 32;

        // ---- stage A and B slabs as hi/lo bf16 ----
        {
            // A
            float v[8];
            int gm = m0 + srow;
            if (gm < M_TOT) {
                const float4* src = reinterpret_cast<const float4*>(
                    X + (size_t)gm * D_MODEL + k0 + sc8);
                float4 t0 = src[0], t1 = src[1];
                v[0]=t0.x; v[1]=t0.y; v[2]=t0.z; v[3]=t0.w;
                v[4]=t1.x; v[5]=t1.y; v[6]=t1.z; v[7]=t1.w;
            } else {
#pragma unroll
                for (int q = 0; q < 8; q++) v[q] = 0.0f;
            }
            uint32_t hi[4], lo[4];
#pragma unroll
            for (int e = 0; e < 4; e++) {
                float f0 = v[2*e], f1 = v[2*e+1];
                __nv_bfloat16 h0 = __float2bfloat16(f0);
                __nv_bfloat16 h1 = __float2bfloat16(f1);
                __nv_bfloat16 l0 = __float2bfloat16(f0 - __bfloat162float(h0));
                __nv_bfloat16 l1 = __float2bfloat16(f1 - __bfloat162float(h1));
                hi[e] = ((uint32_t)__bfloat16_as_ushort(h1) << 16) | __bfloat16_as_ushort(h0);
                lo[e] = ((uint32_t)__bfloat16_as_ushort(l1) << 16) | __bfloat16_as_ushort(l0);
            }
            uint32_t boff = (uint32_t)srow * PITCH + sc8 * 2;
            *reinterpret_cast<uint4*>(smem + A_HI_OFF + boff) = make_uint4(hi[0],hi[1],hi[2],hi[3]);
            *reinterpret_cast<uint4*>(smem + A_LO_OFF + boff) = make_uint4(lo[0],lo[1],lo[2],lo[3]);
        }
        {
            // B (n rows always in range)
            const float4* src = reinterpret_cast<const float4*>(
                W + (size_t)(n0 + srow) * D_MODEL + k0 + sc8);
            float4 t0 = src[0], t1 = src[1];
            float v[8] = {t0.x, t0.y, t0.z, t0.w, t1.x, t1.y, t1.z, t1.w};
            uint32_t hi[4], lo[4];
#pragma unroll
            for (int e = 0; e < 4; e++) {
                float f0 = v[2*e], f1 = v[2*e+1];
                __nv_bfloat16 h0 = __float2bfloat16(f0);
                __nv_bfloat16 h1 = __float2bfloat16(f1);
                __nv_bfloat16 l0 = __float2bfloat16(f0 - __bfloat162float(h0));
                __nv_bfloat16 l1 = __float2bfloat16(f1 - __bfloat162float(h1));
                hi[e] = ((uint32_t)__bfloat16_as_ushort(h1) << 16) | __bfloat16_as_ushort(h0);
                lo[e] = ((uint32_t)__bfloat16_as_ushort(l1) << 16) | __bfloat16_as_ushort(l0);
            }
            uint32_t boff = (uint32_t)srow * PITCH + sc8 * 2;
            *reinterpret_cast<uint4*>(smem + B_HI_OFF + boff) = make_uint4(hi[0],hi[1],hi[2],hi[3]);
            *reinterpret_cast<uint4*>(smem + B_LO_OFF + boff) = make_uint4(lo[0],lo[1],lo[2],lo[3]);
        }
        __syncthreads();

        // ---- compute: 2 k16-steps ----
#pragma unroll
        for (int t = 0; t < 2; t++) {
            // A fragments: mats (rows0-7,k0-7)(rows8-15,k0-7)(rows0-7,k8-15)(rows8-15,k8-15)
            uint32_t ahi[2][4], alo[2][4];
#pragma unroll
            for (int mf = 0; mf < 2; mf++) {
                int arow = wm * 32 + mf * 16 + (mat & 1) * 8 + mr;
                uint32_t koff = t * 32 + (mat >> 1) * 16;
                uint32_t addr = sb + (uint32_t)arow * PITCH + koff;
                ldm_x4(ahi[mf][0], ahi[mf][1], ahi[mf][2], ahi[mf][3], addr + A_HI_OFF);
                ldm_x4(alo[mf][0], alo[mf][1], alo[mf][2], alo[mf][3], addr + A_LO_OFF);
            }
            // B fragments: mats (n0-7,k0-7)(n0-7,k8-15)(n8-15,k0-7)(n8-15,k8-15)
            uint32_t bhi[4][2], blo[4][2];
#pragma unroll
            for (int nfp = 0; nfp < 2; nfp++) {
                int nrow = wn * 32 + nfp * 16 + (mat >> 1) * 8 + mr;
                uint32_t koff = t * 32 + (mat & 1) * 16;
                uint32_t addr = sb + (uint32_t)nrow * PITCH + koff;
                ldm_x4(bhi[2*nfp][0], bhi[2*nfp][1], bhi[2*nfp+1][0], bhi[2*nfp+1][1],
                       addr + B_HI_OFF);
                ldm_x4(blo[2*nfp][0], blo[2*nfp][1], blo[2*nfp+1][0], blo[2*nfp+1][1],
                       addr + B_LO_OFF);
            }
            // 3-term compensated mma
#pragma unroll
            for (int mf = 0; mf < 2; mf++)
#pragma unroll
                for (int nf = 0; nf < 4; nf++) {
                    mma16(c[mf][nf], ahi[mf], bhi[nf][0], bhi[nf][1]);
                    mma16(c[mf][nf], ahi[mf], blo[nf][0], blo[nf][1]);
                    mma16(c[mf][nf], alo[mf], bhi[nf][0], bhi[nf][1]);
                }
        }
        __syncthreads();
    }

    // ---- epilogue: bias + scatter into [B,H,S,HD] ----
#pragma unroll
    for (int mf = 0; mf < 2; mf++) {
#pragma unroll
        for (int nf = 0; nf < 4; nf++) {
            int n = n0 + wn * 32 + nf * 8 + 2 * tig;
            int h = n >> 6, d = n & 63;
            float bv0 = __ldg(bias + n), bv1 = __ldg(bias + n + 1);
#pragma unroll
            for (int half = 0; half < 2; half++) {
                int m = m0 + wm * 32 + mf * 16 + g + half * 8;
                if (m < M_TOT) {
                    int bb = m / S_LEN;
                    int ss = m - bb * S_LEN;
                    float2 v;
                    v.x = c[mf][nf][half * 2 + 0] + bv0;
                    v.y = c[mf][nf][half * 2 + 1] + bv1;
                    *reinterpret_cast<float2*>(
                        out + (((size_t)(bb * H_NUM + h) * S_LEN + ss) * HD + d)) = v;
                }
            }
        }
    }
}

// ---------------------------------------------------------------------------
// Flash attention on tensor cores (single-pass tf32), K/V/P pre-rounded
// to tf32 at staging so inner loops load raw bits.
// ---------------------------------------------------------------------------
#define NEG_BIG (-1e30f)

__global__ __launch_bounds__(128) void attn_tc(float* __restrict__ out)
{
    __shared__ float Ks[64][68];   // K tile (tf32-rounded), reused as P
    __shared__ float Vs[64][68];   // V tile (tf32-rounded)

    const int h  = blockIdx.y;
    const int b  = blockIdx.z;
    const int qt = blockIdx.x;
    const int tid  = threadIdx.x;
    const int lane = tid & 31;
    const int w    = tid >> 5;
    const int g    = lane >> 2;
    const int tig  = lane & 3;

    const size_t base = (size_t)(b * H_NUM + h) * S_LEN * HD;
    const float* Qb = g_Q + base;
    const float* Kb = g_K + base;
    const float* Vb = g_V + base;

    const int q0 = qt * 64 + w * 16;
    const int r1 = q0 + g;
    const int r2 = q0 + g + 8;

    unsigned qa[8][4];
#pragma unroll
    for (int kk = 0; kk < 8; kk++) {
        int c0 = kk * 8 + tig;
        qa[kk][0] = (r1 < S_LEN) ? f2tf(Qb[(size_t)r1 * HD + c0    ] * 0.125f) : 0u;
        qa[kk][1] = (r2 < S_LEN) ? f2tf(Qb[(size_t)r2 * HD + c0    ] * 0.125f) : 0u;
        qa[kk][2] = (r1 < S_LEN) ? f2tf(Qb[(size_t)r1 * HD + c0 + 4] * 0.125f) : 0u;
        qa[kk][3] = (r2 < S_LEN) ? f2tf(Qb[(size_t)r2 * HD + c0 + 4] * 0.125f) : 0u;
    }

    float oc[8][4];
#pragma unroll
    for (int nf = 0; nf < 8; nf++)
#pragma unroll
        for (int cc = 0; cc < 4; cc++) oc[nf][cc] = 0.0f;
    float m1 = NEG_BIG, m2 = NEG_BIG, l1 = 0.0f, l2 = 0.0f;

    const int ntiles = (S_LEN + 63) / 64;   // 22
    for (int kt = 0; kt < ntiles; kt++) {
        const int rem = min(64, S_LEN - kt * 64);

#pragma unroll
        for (int p = 0; p < 8; p++) {
            int li  = tid + 128 * p;
            int row = li >> 4;
            int c4  = (li & 15) * 4;
            float4 kv = make_float4(0.f, 0.f, 0.f, 0.f);
            float4 vv = make_float4(0.f, 0.f, 0.f, 0.f);
            if (row < rem) {
                kv = *reinterpret_cast<const float4*>(Kb + (size_t)(kt * 64 + row) * HD + c4);
                vv = *reinterpret_cast<const float4*>(Vb + (size_t)(kt * 64 + row) * HD + c4);
            }
            kv.x = tf32f(kv.x); kv.y = tf32f(kv.y); kv.z = tf32f(kv.z); kv.w = tf32f(kv.w);
            vv.x = tf32f(vv.x); vv.y = tf32f(vv.y); vv.z = tf32f(vv.z); vv.w = tf32f(vv.w);
            *reinterpret_cast<float4*>(&Ks[row][c4]) = kv;
            *reinterpret_cast<float4*>(&Vs[row][c4]) = vv;
        }
        __syncthreads();

        float sc[8][4];
#pragma unroll
        for (int nf = 0; nf < 8; nf++)
#pragma unroll
            for (int cc = 0; cc < 4; cc++) sc[nf][cc] = 0.0f;

#pragma unroll
        for (int kk = 0; kk < 8; kk++) {
#pragma unroll
            for (int nf = 0; nf < 8; nf++) {
                unsigned b0 = __float_as_uint(Ks[nf * 8 + g][kk * 8 + tig    ]);
                unsigned b1 = __float_as_uint(Ks[nf * 8 + g][kk * 8 + tig + 4]);
                mma8(sc[nf], qa[kk], b0, b1);
            }
        }

        if (rem < 64) {
#pragma unroll
            for (int nf = 0; nf < 8; nf++) {
                int col = nf * 8 + 2 * tig;
                if (col     >= rem) { sc[nf][0] = NEG_BIG; sc[nf][2] = NEG_BIG; }
                if (col + 1 >= rem) { sc[nf][1] = NEG_BIG; sc[nf][3] = NEG_BIG; }
            }
        }

        float rmax1 = NEG_BIG, rmax2 = NEG_BIG;
#pragma unroll
        for (int nf = 0; nf < 8; nf++) {
            rmax1 = fmaxf(rmax1, fmaxf(sc[nf][0], sc[nf][1]));
            rmax2 = fmaxf(rmax2, fmaxf(sc[nf][2], sc[nf][3]));
        }
        rmax1 = fmaxf(rmax1, __shfl_xor_sync(0xffffffffu, rmax1, 1));
        rmax1 = fmaxf(rmax1, __shfl_xor_sync(0xffffffffu, rmax1, 2));
        rmax2 = fmaxf(rmax2, __shfl_xor_sync(0xffffffffu, rmax2, 1));
        rmax2 = fmaxf(rmax2, __shfl_xor_sync(0xffffffffu, rmax2, 2));

        float nm1 = fmaxf(m1, rmax1);
        float nm2 = fmaxf(m2, rmax2);
        float corr1 = __expf(m1 - nm1);
        float corr2 = __expf(m2 - nm2);

        float ps1 = 0.0f, ps2 = 0.0f;
#pragma unroll
        for (int nf = 0; nf < 8; nf++) {
            sc[nf][0] = __expf(sc[nf][0] - nm1); ps1 += sc[nf][0];
            sc[nf][1] = __expf(sc[nf][1] - nm1); ps1 += sc[nf][1];
            sc[nf][2] = __expf(sc[nf][2] - nm2); ps2 += sc[nf][2];
            sc[nf][3] = __expf(sc[nf][3] - nm2); ps2 += sc[nf][3];
        }
        ps1 += __shfl_xor_sync(0xffffffffu, ps1, 1);
        ps1 += __shfl_xor_sync(0xffffffffu, ps1, 2);
        ps2 += __shfl_xor_sync(0xffffffffu, ps2, 1);
        ps2 += __shfl_xor_sync(0xffffffffu, ps2, 2);

        l1 = l1 * corr1 + ps1;
        l2 = l2 * corr2 + ps2;
#pragma unroll
        for (int nf = 0; nf < 8; nf++) {
            oc[nf][0] *= corr1; oc[nf][1] *= corr1;
            oc[nf][2] *= corr2; oc[nf][3] *= corr2;
        }
        m1 = nm1; m2 = nm2;

        __syncthreads();   // all warps finished reading Ks as K

        // write P (tf32-rounded) into Ks
#pragma unroll
        for (int nf = 0; nf < 8; nf++) {
            int col = nf * 8 + 2 * tig;
            Ks[w * 16 + g    ][col    ] = tf32f(sc[nf][0]);
            Ks[w * 16 + g    ][col + 1] = tf32f(sc[nf][1]);
            Ks[w * 16 + g + 8][col    ] = tf32f(sc[nf][2]);
            Ks[w * 16 + g + 8][col + 1] = tf32f(sc[nf][3]);
        }
        __syncwarp();

#pragma unroll
        for (int kk = 0; kk < 8; kk++) {
            unsigned pa[4];
            pa[0] = __float_as_uint(Ks[w * 16 + g    ][kk * 8 + tig    ]);
            pa[1] = __float_as_uint(Ks[w * 16 + g + 8][kk * 8 + tig    ]);
            pa[2] = __float_as_uint(Ks[w * 16 + g    ][kk * 8 + tig + 4]);
            pa[3] = __float_as_uint(Ks[w * 16 + g + 8][kk * 8 + tig + 4]);
#pragma unroll
            for (int nf = 0; nf < 8; nf++) {
                unsigned b0 = __float_as_uint(Vs[kk * 8 + tig    ][nf * 8 + g]);
                unsigned b1 = __float_as_uint(Vs[kk * 8 + tig + 4][nf * 8 + g]);
                mma8(oc[nf], pa, b0, b1);
            }
        }
        __syncthreads();
    }

    float inv1 = 1.0f / l1;
    float inv2 = 1.0f / l2;
#pragma unroll
    for (int nf = 0; nf < 8; nf++) {
        int d = nf * 8 + 2 * tig;
        if (r1 < S_LEN) {
            float2 v; v.x = oc[nf][0] * inv1; v.y = oc[nf][1] * inv1;
            *reinterpret_cast<float2*>(out + (size_t)(b * S_LEN + r1) * D_MODEL + h * HD + d) = v;
        }
        if (r2 < S_LEN) {
            float2 v; v.x = oc[nf][2] * inv2; v.y = oc[nf][3] * inv2;
            *reinterpret_cast<float2*>(out + (size_t)(b * S_LEN + r2) * D_MODEL + h * HD + d) = v;
        }
    }
}

// ---------------------------------------------------------------------------
extern "C" void kernel_launch(void* const* d_in, const int* in_sizes, int n_in,
                              void* d_out, int out_size)
{
    const float* X  = (const float*)d_in[0];
    const float* Wq = (const float*)d_in[1];
    const float* bq = (const float*)d_in[2];
    const float* Wk = (const float*)d_in[3];
    const float* bk = (const float*)d_in[4];
    const float* Wv = (const float*)d_in[5];
    const float* bv = (const float*)d_in[6];
    float* out = (float*)d_out;

    dim3 g1(D_MODEL / 128, (M_TOT + 127) / 128, 3);
    qkv_bf16<<<g1, 512>>>(X, Wq, bq, Wk, bk, Wv, bv);

    dim3 g2((S_LEN + 63) / 64, H_NUM, B_SZ);
    attn_tc<<<g2, 128>>>(out);
}

// round 5
// speedup vs baseline: 4.1784x; 1.8498x over previous
#include <cuda_runtime.h>
#include <cuda_bf16.h>
#include <cuda_fp16.h>
#include <stdint.h>

#define S_LEN   1370
#define B_SZ    8
#define D_MODEL 1024
#define H_NUM   16
#define HD      64
#define M_TOT   (B_SZ * S_LEN)   // 10960

// pre-converted GEMM operands (bf16 hi/lo split)
__device__ __nv_bfloat16 gXhi[(size_t)M_TOT * D_MODEL];
__device__ __nv_bfloat16 gXlo[(size_t)M_TOT * D_MODEL];
__device__ __nv_bfloat16 gWhi[3ull * D_MODEL * D_MODEL];
__device__ __nv_bfloat16 gWlo[3ull * D_MODEL * D_MODEL];
// projected Q/K/V in fp16, [B,H,S,HD]; Q pre-scaled by 1/sqrt(64)
__device__ __half g_Q[(size_t)M_TOT * D_MODEL];
__device__ __half g_K[(size_t)M_TOT * D_MODEL];
__device__ __half g_V[(size_t)M_TOT * D_MODEL];

// ---------------------------------------------------------------------------
// helpers
// ---------------------------------------------------------------------------
__device__ __forceinline__ uint32_t smem_u32(const void* p) {
    return (uint32_t)__cvta_generic_to_shared(p);
}
__device__ __forceinline__ void cp16(uint32_t dst, const void* src, int sz) {
    asm volatile("cp.async.cg.shared.global [%0], [%1], 16, %2;"
                 :: "r"(dst), "l"(src), "r"(sz) : "memory");
}
__device__ __forceinline__ void cp_commit() {
    asm volatile("cp.async.commit_group;" ::: "memory");
}
__device__ __forceinline__ void cp_wait1() {
    asm volatile("cp.async.wait_group 1;" ::: "memory");
}
__device__ __forceinline__ void cp_wait0() {
    asm volatile("cp.async.wait_group 0;" ::: "memory");
}
__device__ __forceinline__ void ldm_x4(uint32_t& r0, uint32_t& r1, uint32_t& r2, uint32_t& r3,
                                       uint32_t addr) {
    asm volatile("ldmatrix.sync.aligned.m8n8.x4.shared.b16 {%0,%1,%2,%3}, [%4];"
                 : "=r"(r0), "=r"(r1), "=r"(r2), "=r"(r3) : "r"(addr));
}
__device__ __forceinline__ void ldm_x4t(uint32_t& r0, uint32_t& r1, uint32_t& r2, uint32_t& r3,
                                        uint32_t addr) {
    asm volatile("ldmatrix.sync.aligned.m8n8.x4.trans.shared.b16 {%0,%1,%2,%3}, [%4];"
                 : "=r"(r0), "=r"(r1), "=r"(r2), "=r"(r3) : "r"(addr));
}
// bf16 m16n8k16 (projection)
__device__ __forceinline__ void mma16bf(float* c, const uint32_t* a, uint32_t b0, uint32_t b1) {
    asm volatile(
        "mma.sync.aligned.m16n8k16.row.col.f32.bf16.bf16.f32 "
        "{%0,%1,%2,%3},{%4,%5,%6,%7},{%8,%9},{%0,%1,%2,%3};\n"
        : "+f"(c[0]), "+f"(c[1]), "+f"(c[2]), "+f"(c[3])
        : "r"(a[0]), "r"(a[1]), "r"(a[2]), "r"(a[3]), "r"(b0), "r"(b1));
}
// fp16 m16n8k16 (attention)
__device__ __forceinline__ void mma16h(float* c, const uint32_t* a, uint32_t b0, uint32_t b1) {
    asm volatile(
        "mma.sync.aligned.m16n8k16.row.col.f32.f16.f16.f32 "
        "{%0,%1,%2,%3},{%4,%5,%6,%7},{%8,%9},{%0,%1,%2,%3};\n"
        : "+f"(c[0]), "+f"(c[1]), "+f"(c[2]), "+f"(c[3])
        : "r"(a[0]), "r"(a[1]), "r"(a[2]), "r"(a[3]), "r"(b0), "r"(b1));
}
__device__ __forceinline__ uint32_t h2pack(float lo, float hi) {
    __half2 h = __floats2half2_rn(lo, hi);
    return *reinterpret_cast<uint32_t*>(&h);
}

// ---------------------------------------------------------------------------
// Pre-convert fp32 -> bf16 hi/lo (once per input, not per tile-restage)
// sel: 0 = X, 1..3 = Wq/Wk/Wv
// ---------------------------------------------------------------------------
__global__ void conv_pair(const float* __restrict__ src, int sel, int n4)
{
    int i = blockIdx.x * 256 + threadIdx.x;
    if (i >= n4) return;
    __nv_bfloat16 *hi, *lo;
    if (sel == 0) { hi = gXhi; lo = gXlo; }
    else {
        size_t off = (size_t)(sel - 1) * D_MODEL * D_MODEL;
        hi = gWhi + off; lo = gWlo + off;
    }
    float4 v = reinterpret_cast<const float4*>(src)[i];
    float f[4] = {v.x, v.y, v.z, v.w};
    uint32_t h[4], l[4];
#pragma unroll
    for (int e = 0; e < 4; e++) {
        __nv_bfloat16 hb = __float2bfloat16(f[e]);
        __nv_bfloat16 lb = __float2bfloat16(f[e] - __bfloat162float(hb));
        h[e] = __bfloat16_as_ushort(hb);
        l[e] = __bfloat16_as_ushort(lb);
    }
    uint2 hv = make_uint2(h[0] | (h[1] << 16), h[2] | (h[3] << 16));
    uint2 lv = make_uint2(l[0] | (l[1] << 16), l[2] | (l[3] << 16));
    reinterpret_cast<uint2*>(hi)[i] = hv;
    reinterpret_cast<uint2*>(lo)[i] = lv;
}

// ---------------------------------------------------------------------------
// QKV projection: y = X @ W^T + b (bf16 3-term compensation, m16n8k16).
// Block 128x128, 512 threads, warp tile 32x32, K slab 32, cp.async
// double-buffered from pre-converted bf16 arrays. Output fp16 scattered
// into [B,H,S,HD]; Q scaled by 0.125.
// ---------------------------------------------------------------------------
#define PITCH  80
#define TILEB  10240                 // one 128x32 bf16 tile (pitch 80)
#define BUFSZ  (4 * TILEB)           // Ahi,Alo,Bhi,Blo
#define GEMM_SMEM (2 * BUFSZ)        // 81920

__global__ __launch_bounds__(512, 1) void qkv_bf16(
    const float* __restrict__ bq, const float* __restrict__ bk,
    const float* __restrict__ bv)
{
    extern __shared__ char smem[];
    const uint32_t sb = smem_u32(smem);

    const int z = blockIdx.z;
    const float* bias = (z == 0) ? bq : (z == 1) ? bk : bv;
    __half* out = (z == 0) ? g_Q : (z == 1) ? g_K : g_V;
    const float scale = (z == 0) ? 0.125f : 1.0f;
    const __nv_bfloat16* Whi = gWhi + (size_t)z * D_MODEL * D_MODEL;
    const __nv_bfloat16* Wlo = gWlo + (size_t)z * D_MODEL * D_MODEL;

    const int tid  = threadIdx.x;
    const int lane = tid & 31;
    const int wid  = tid >> 5;
    const int wm   = wid >> 2;
    const int wn   = wid & 3;
    const int g    = lane >> 2;
    const int tig  = lane & 3;
    const int mat  = lane >> 3;
    const int mr   = lane & 7;

    const int m0 = blockIdx.y * 128;
    const int n0 = blockIdx.x * 128;

    const int srow = tid >> 2;        // 0..127
    const int sch  = tid & 3;         // chunk 0..3 (16B each)

    const int gm = m0 + srow;
    const int szA = (gm < M_TOT) ? 16 : 0;
    const size_t arow_off = (size_t)min(gm, M_TOT - 1) * D_MODEL;
    const size_t brow_off = (size_t)(n0 + srow) * D_MODEL;

    float c[2][4][4];
#pragma unroll
    for (int mf = 0; mf < 2; mf++)
#pragma unroll
        for (int nf = 0; nf < 4; nf++)
#pragma unroll
            for (int cc = 0; cc < 4; cc++) c[mf][nf][cc] = 0.0f;

    // issue staging for slab s into buffer buf
    auto issue = [&](int s, int buf) {
        const int k0 = s * 32;
        uint32_t d0 = sb + buf * BUFSZ + (uint32_t)srow * PITCH + sch * 16;
        const char* sAh = (const char*)(gXhi + arow_off + k0) + sch * 16;
        const char* sAl = (const char*)(gXlo + arow_off + k0) + sch * 16;
        const char* sBh = (const char*)(Whi + brow_off + k0) + sch * 16;
        const char* sBl = (const char*)(Wlo + brow_off + k0) + sch * 16;
        cp16(d0,             sAh, szA);
        cp16(d0 + TILEB,     sAl, szA);
        cp16(d0 + 2 * TILEB, sBh, 16);
        cp16(d0 + 3 * TILEB, sBl, 16);
    };

    issue(0, 0);
    cp_commit();

    for (int s = 0; s < 32; s++) {
        if (s + 1 < 32) { issue(s + 1, (s + 1) & 1); cp_commit(); }
        if (s + 1 < 32) cp_wait1(); else cp_wait0();
        __syncthreads();

        const uint32_t base = sb + (s & 1) * BUFSZ;
#pragma unroll
        for (int t = 0; t < 2; t++) {
            uint32_t ahi[2][4], alo[2][4];
#pragma unroll
            for (int mf = 0; mf < 2; mf++) {
                int arow = wm * 32 + mf * 16 + (mat & 1) * 8 + mr;
                uint32_t koff = t * 32 + (mat >> 1) * 16;
                uint32_t addr = base + (uint32_t)arow * PITCH + koff;
                ldm_x4(ahi[mf][0], ahi[mf][1], ahi[mf][2], ahi[mf][3], addr);
                ldm_x4(alo[mf][0], alo[mf][1], alo[mf][2], alo[mf][3], addr + TILEB);
            }
            uint32_t bhi[4][2], blo[4][2];
#pragma unroll
            for (int nfp = 0; nfp < 2; nfp++) {
                int nrow = wn * 32 + nfp * 16 + (mat >> 1) * 8 + mr;
                uint32_t koff = t * 32 + (mat & 1) * 16;
                uint32_t addr = base + (uint32_t)nrow * PITCH + koff;
                ldm_x4(bhi[2*nfp][0], bhi[2*nfp][1], bhi[2*nfp+1][0], bhi[2*nfp+1][1],
                       addr + 2 * TILEB);
                ldm_x4(blo[2*nfp][0], blo[2*nfp][1], blo[2*nfp+1][0], blo[2*nfp+1][1],
                       addr + 3 * TILEB);
            }
#pragma unroll
            for (int mf = 0; mf < 2; mf++)
#pragma unroll
                for (int nf = 0; nf < 4; nf++) {
                    mma16bf(c[mf][nf], ahi[mf], bhi[nf][0], bhi[nf][1]);
                    mma16bf(c[mf][nf], ahi[mf], blo[nf][0], blo[nf][1]);
                    mma16bf(c[mf][nf], alo[mf], bhi[nf][0], bhi[nf][1]);
                }
        }
        __syncthreads();
    }

    // epilogue: bias + scale, fp16 scatter into [B,H,S,HD]
#pragma unroll
    for (int mf = 0; mf < 2; mf++) {
#pragma unroll
        for (int nf = 0; nf < 4; nf++) {
            int n = n0 + wn * 32 + nf * 8 + 2 * tig;
            int h = n >> 6, d = n & 63;
            float bv0 = __ldg(bias + n), bv1 = __ldg(bias + n + 1);
#pragma unroll
            for (int half = 0; half < 2; half++) {
                int m = m0 + wm * 32 + mf * 16 + g + half * 8;
                if (m < M_TOT) {
                    int bb = m / S_LEN;
                    int ss = m - bb * S_LEN;
                    __half2 hv = __floats2half2_rn(
                        (c[mf][nf][half * 2 + 0] + bv0) * scale,
                        (c[mf][nf][half * 2 + 1] + bv1) * scale);
                    *reinterpret_cast<__half2*>(
                        out + (((size_t)(bb * H_NUM + h) * S_LEN + ss) * HD + d)) = hv;
                }
            }
        }
    }
}

// ---------------------------------------------------------------------------
// Flash attention, fp16 m16n8k16. CTA = 64 queries (4 warps x 16),
// K/V tiles of 64 keys cp.async double-buffered. P stays in registers
// (C-fragment layout == A-fragment layout for fp16 k16).
// ---------------------------------------------------------------------------
#define NEG_BIG (-1e30f)
#define APITCH  144                   // bytes per smem row (64 fp16 + 8 pad)

__global__ __launch_bounds__(128) void attn_fp16(float* __restrict__ out)
{
    __shared__ __half Qs[64 * 72];
    __shared__ __half Ks[2][64 * 72];
    __shared__ __half Vs[2][64 * 72];

    const int h  = blockIdx.y;
    const int b  = blockIdx.z;
    const int qt = blockIdx.x;
    const int tid  = threadIdx.x;
    const int lane = tid & 31;
    const int w    = tid >> 5;
    const int g    = lane >> 2;
    const int tig  = lane & 3;
    const int mat  = lane >> 3;
    const int mr   = lane & 7;

    const size_t base = (size_t)(b * H_NUM + h) * S_LEN * HD;
    const __half* Qb = g_Q + base;
    const __half* Kb = g_K + base;
    const __half* Vb = g_V + base;

    const uint32_t sbQ = smem_u32(Qs);

    // stage Q tile (rows qt*64 .. +63), zero-filled OOB
#pragma unroll
    for (int p = 0; p < 4; p++) {
        int idx = tid + 128 * p;       // 0..511
        int row = idx >> 3;
        int ch  = idx & 7;
        int qi = qt * 64 + row;
        int sz = (qi < S_LEN) ? 16 : 0;
        const char* src = (const char*)(Qb + (size_t)min(qi, S_LEN - 1) * HD) + ch * 16;
        cp16(sbQ + (uint32_t)row * APITCH + ch * 16, src, sz);
    }
    cp_commit();

    auto issue_kv = [&](int kt, int bb) {
        const uint32_t sbK = smem_u32(Ks[bb]);
        const uint32_t sbV = smem_u32(Vs[bb]);
#pragma unroll
        for (int p = 0; p < 4; p++) {
            int idx = tid + 128 * p;
            int row = idx >> 3;
            int ch  = idx & 7;
            int ki = kt * 64 + row;
            int sz = (ki < S_LEN) ? 16 : 0;
            size_t roff = (size_t)min(ki, S_LEN - 1) * HD;
            cp16(sbK + (uint32_t)row * APITCH + ch * 16, (const char*)(Kb + roff) + ch * 16, sz);
            cp16(sbV + (uint32_t)row * APITCH + ch * 16, (const char*)(Vb + roff) + ch * 16, sz);
        }
    };

    issue_kv(0, 0);
    cp_commit();
    cp_wait1();            // Q group done
    __syncthreads();

    // load Q fragments (rows w*16..+15)
    uint32_t qa[4][4];
#pragma unroll
    for (int ks = 0; ks < 4; ks++) {
        uint32_t addr = sbQ + (uint32_t)(w * 16 + (mat & 1) * 8 + mr) * APITCH
                      + ks * 32 + (mat >> 1) * 16;
        ldm_x4(qa[ks][0], qa[ks][1], qa[ks][2], qa[ks][3], addr);
    }

    const int r1 = qt * 64 + w * 16 + g;
    const int r2 = r1 + 8;

    float oc[8][4];
#pragma unroll
    for (int nf = 0; nf < 8; nf++)
#pragma unroll
        for (int cc = 0; cc < 4; cc++) oc[nf][cc] = 0.0f;
    float m1 = NEG_BIG, m2 = NEG_BIG, l1 = 0.0f, l2 = 0.0f;

    const int ntiles = (S_LEN + 63) / 64;    // 22
    for (int kt = 0; kt < ntiles; kt++) {
        if (kt + 1 < ntiles) { issue_kv(kt + 1, (kt + 1) & 1); cp_commit(); }
        if (kt + 1 < ntiles) cp_wait1(); else cp_wait0();
        __syncthreads();

        const int rem = min(64, S_LEN - kt * 64);
        const uint32_t sbK = smem_u32(Ks[kt & 1]);
        const uint32_t sbV = smem_u32(Vs[kt & 1]);

        // ---- S = Q K^T ----
        float sc[8][4];
#pragma unroll
        for (int nf = 0; nf < 8; nf++)
#pragma unroll
            for (int cc = 0; cc < 4; cc++) sc[nf][cc] = 0.0f;

#pragma unroll
        for (int ks = 0; ks < 4; ks++) {
#pragma unroll
            for (int nf2 = 0; nf2 < 4; nf2++) {
                uint32_t r0, rr1, rr2, rr3;
                uint32_t addr = sbK + (uint32_t)(nf2 * 16 + (mat >> 1) * 8 + mr) * APITCH
                              + ks * 32 + (mat & 1) * 16;
                ldm_x4(r0, rr1, rr2, rr3, addr);
                mma16h(sc[2 * nf2],     qa[ks], r0,  rr1);
                mma16h(sc[2 * nf2 + 1], qa[ks], rr2, rr3);
            }
        }

        // mask tail columns
        if (rem < 64) {
#pragma unroll
            for (int nf = 0; nf < 8; nf++) {
                int col = nf * 8 + 2 * tig;
                if (col     >= rem) { sc[nf][0] = NEG_BIG; sc[nf][2] = NEG_BIG; }
                if (col + 1 >= rem) { sc[nf][1] = NEG_BIG; sc[nf][3] = NEG_BIG; }
            }
        }

        // ---- online softmax ----
        float rmax1 = NEG_BIG, rmax2 = NEG_BIG;
#pragma unroll
        for (int nf = 0; nf < 8; nf++) {
            rmax1 = fmaxf(rmax1, fmaxf(sc[nf][0], sc[nf][1]));
            rmax2 = fmaxf(rmax2, fmaxf(sc[nf][2], sc[nf][3]));
        }
        rmax1 = fmaxf(rmax1, __shfl_xor_sync(0xffffffffu, rmax1, 1));
        rmax1 = fmaxf(rmax1, __shfl_xor_sync(0xffffffffu, rmax1, 2));
        rmax2 = fmaxf(rmax2, __shfl_xor_sync(0xffffffffu, rmax2, 1));
        rmax2 = fmaxf(rmax2, __shfl_xor_sync(0xffffffffu, rmax2, 2));

        float nm1 = fmaxf(m1, rmax1);
        float nm2 = fmaxf(m2, rmax2);
        float corr1 = __expf(m1 - nm1);
        float corr2 = __expf(m2 - nm2);

        float ps1 = 0.0f, ps2 = 0.0f;
#pragma unroll
        for (int nf = 0; nf < 8; nf++) {
            sc[nf][0] = __expf(sc[nf][0] - nm1); ps1 += sc[nf][0];
            sc[nf][1] = __expf(sc[nf][1] - nm1); ps1 += sc[nf][1];
            sc[nf][2] = __expf(sc[nf][2] - nm2); ps2 += sc[nf][2];
            sc[nf][3] = __expf(sc[nf][3] - nm2); ps2 += sc[nf][3];
        }
        ps1 += __shfl_xor_sync(0xffffffffu, ps1, 1);
        ps1 += __shfl_xor_sync(0xffffffffu, ps1, 2);
        ps2 += __shfl_xor_sync(0xffffffffu, ps2, 1);
        ps2 += __shfl_xor_sync(0xffffffffu, ps2, 2);

        l1 = l1 * corr1 + ps1;
        l2 = l2 * corr2 + ps2;
#pragma unroll
        for (int nf = 0; nf < 8; nf++) {
            oc[nf][0] *= corr1; oc[nf][1] *= corr1;
            oc[nf][2] *= corr2; oc[nf][3] *= corr2;
        }
        m1 = nm1; m2 = nm2;

        // ---- O += P V (P from registers, fp16 pack) ----
#pragma unroll
        for (int ks = 0; ks < 4; ks++) {
            uint32_t pa[4];
            pa[0] = h2pack(sc[2*ks][0],     sc[2*ks][1]);
            pa[1] = h2pack(sc[2*ks][2],     sc[2*ks][3]);
            pa[2] = h2pack(sc[2*ks+1][0],   sc[2*ks+1][1]);
            pa[3] = h2pack(sc[2*ks+1][2],   sc[2*ks+1][3]);
#pragma unroll
            for (int nf2 = 0; nf2 < 4; nf2++) {
                uint32_t r0, rr1, rr2, rr3;
                uint32_t addr = sbV + (uint32_t)(ks * 16 + (mat & 1) * 8 + mr) * APITCH
                              + nf2 * 32 + (mat >> 1) * 16;
                ldm_x4t(r0, rr1, rr2, rr3, addr);
                mma16h(oc[2 * nf2],     pa, r0,  rr1);
                mma16h(oc[2 * nf2 + 1], pa, rr2, rr3);
            }
        }
        __syncthreads();
    }

    // ---- normalize + write [B,S,H*HD] fp32 ----
    float inv1 = 1.0f / l1;
    float inv2 = 1.0f / l2;
#pragma unroll
    for (int nf = 0; nf < 8; nf++) {
        int d = nf * 8 + 2 * tig;
        if (r1 < S_LEN) {
            float2 v; v.x = oc[nf][0] * inv1; v.y = oc[nf][1] * inv1;
            *reinterpret_cast<float2*>(out + (size_t)(b * S_LEN + r1) * D_MODEL + h * HD + d) = v;
        }
        if (r2 < S_LEN) {
            float2 v; v.x = oc[nf][2] * inv2; v.y = oc[nf][3] * inv2;
            *reinterpret_cast<float2*>(out + (size_t)(b * S_LEN + r2) * D_MODEL + h * HD + d) = v;
        }
    }
}

// ---------------------------------------------------------------------------
extern "C" void kernel_launch(void* const* d_in, const int* in_sizes, int n_in,
                              void* d_out, int out_size)
{
    const float* X  = (const float*)d_in[0];
    const float* Wq = (const float*)d_in[1];
    const float* bq = (const float*)d_in[2];
    const float* Wk = (const float*)d_in[3];
    const float* bk = (const float*)d_in[4];
    const float* Wv = (const float*)d_in[5];
    const float* bv = (const float*)d_in[6];
    float* out = (float*)d_out;

    static int once = 0;
    if (!once) {
        cudaFuncSetAttribute(qkv_bf16, cudaFuncAttributeMaxDynamicSharedMemorySize, GEMM_SMEM);
        once = 1;
    }

    // pre-convert inputs to bf16 hi/lo
    const int n4x = M_TOT * D_MODEL / 4;          // 2,805,760
    const int n4w = D_MODEL * D_MODEL / 4;        // 262,144
    conv_pair<<<(n4x + 255) / 256, 256>>>(X,  0, n4x);
    conv_pair<<<(n4w + 255) / 256, 256>>>(Wq, 1, n4w);
    conv_pair<<<(n4w + 255) / 256, 256>>>(Wk, 2, n4w);
    conv_pair<<<(n4w + 255) / 256, 256>>>(Wv, 3, n4w);

    dim3 g1(D_MODEL / 128, (M_TOT + 127) / 128, 3);
    qkv_bf16<<<g1, 512, GEMM_SMEM>>>(bq, bk, bv);

    dim3 g2((S_LEN + 63) / 64, H_NUM, B_SZ);
    attn_fp16<<<g2, 128>>>(out);
}

// round 6
// speedup vs baseline: 5.0979x; 1.2201x over previous
#include <cuda_runtime.h>
#include <cuda_fp16.h>
#include <stdint.h>

#define S_LEN   1370
#define B_SZ    8
#define D_MODEL 1024
#define H_NUM   16
#define HD      64
#define M_TOT   (B_SZ * S_LEN)   // 10960
#define LOG2E   1.4426950408889634f

// pre-converted GEMM operands
__device__ __half gXhi[(size_t)M_TOT * D_MODEL];
__device__ __half gXlo[(size_t)M_TOT * D_MODEL];
__device__ __half gW[3ull * D_MODEL * D_MODEL];
// projected Q/K/V in fp16, [B,H,S,HD]; Q pre-scaled by 0.125*log2(e)
__device__ __half g_Q[(size_t)M_TOT * D_MODEL];
__device__ __half g_K[(size_t)M_TOT * D_MODEL];
__device__ __half g_V[(size_t)M_TOT * D_MODEL];

// ---------------------------------------------------------------------------
// helpers
// ---------------------------------------------------------------------------
__device__ __forceinline__ uint32_t smem_u32(const void* p) {
    return (uint32_t)__cvta_generic_to_shared(p);
}
__device__ __forceinline__ void cp16(uint32_t dst, const void* src, int sz) {
    asm volatile("cp.async.cg.shared.global [%0], [%1], 16, %2;"
                 :: "r"(dst), "l"(src), "r"(sz) : "memory");
}
__device__ __forceinline__ void cp_commit() {
    asm volatile("cp.async.commit_group;" ::: "memory");
}
__device__ __forceinline__ void cp_wait1() {
    asm volatile("cp.async.wait_group 1;" ::: "memory");
}
__device__ __forceinline__ void cp_wait0() {
    asm volatile("cp.async.wait_group 0;" ::: "memory");
}
__device__ __forceinline__ void ldm_x4(uint32_t& r0, uint32_t& r1, uint32_t& r2, uint32_t& r3,
                                       uint32_t addr) {
    asm volatile("ldmatrix.sync.aligned.m8n8.x4.shared.b16 {%0,%1,%2,%3}, [%4];"
                 : "=r"(r0), "=r"(r1), "=r"(r2), "=r"(r3) : "r"(addr));
}
__device__ __forceinline__ void ldm_x4t(uint32_t& r0, uint32_t& r1, uint32_t& r2, uint32_t& r3,
                                        uint32_t addr) {
    asm volatile("ldmatrix.sync.aligned.m8n8.x4.trans.shared.b16 {%0,%1,%2,%3}, [%4];"
                 : "=r"(r0), "=r"(r1), "=r"(r2), "=r"(r3) : "r"(addr));
}
__device__ __forceinline__ void mma16h(float* c, const uint32_t* a, uint32_t b0, uint32_t b1) {
    asm volatile(
        "mma.sync.aligned.m16n8k16.row.col.f32.f16.f16.f32 "
        "{%0,%1,%2,%3},{%4,%5,%6,%7},{%8,%9},{%0,%1,%2,%3};\n"
        : "+f"(c[0]), "+f"(c[1]), "+f"(c[2]), "+f"(c[3])
        : "r"(a[0]), "r"(a[1]), "r"(a[2]), "r"(a[3]), "r"(b0), "r"(b1));
}
__device__ __forceinline__ uint32_t h2pack(float lo, float hi) {
    __half2 h = __floats2half2_rn(lo, hi);
    return *reinterpret_cast<uint32_t*>(&h);
}

// ---------------------------------------------------------------------------
// Pre-convert: X -> fp16 hi/lo pair; W -> single fp16
// ---------------------------------------------------------------------------
__global__ void conv_x(const float* __restrict__ src, int n4)
{
    int i = blockIdx.x * 256 + threadIdx.x;
    if (i >= n4) return;
    float4 v = reinterpret_cast<const float4*>(src)[i];
    float f[4] = {v.x, v.y, v.z, v.w};
    uint32_t h[4], l[4];
#pragma unroll
    for (int e = 0; e < 4; e++) {
        __half hb = __float2half_rn(f[e]);
        __half lb = __float2half_rn(f[e] - __half2float(hb));
        h[e] = __half_as_ushort(hb);
        l[e] = __half_as_ushort(lb);
    }
    reinterpret_cast<uint2*>(gXhi)[i] = make_uint2(h[0] | (h[1] << 16), h[2] | (h[3] << 16));
    reinterpret_cast<uint2*>(gXlo)[i] = make_uint2(l[0] | (l[1] << 16), l[2] | (l[3] << 16));
}

__global__ void conv_w(const float* __restrict__ src, int plane, int n4)
{
    int i = blockIdx.x * 256 + threadIdx.x;
    if (i >= n4) return;
    __half* dst = gW + (size_t)plane * D_MODEL * D_MODEL;
    float4 v = reinterpret_cast<const float4*>(src)[i];
    uint32_t h0 = __half_as_ushort(__float2half_rn(v.x)) |
                  ((uint32_t)__half_as_ushort(__float2half_rn(v.y)) << 16);
    uint32_t h1 = __half_as_ushort(__float2half_rn(v.z)) |
                  ((uint32_t)__half_as_ushort(__float2half_rn(v.w)) << 16);
    reinterpret_cast<uint2*>(dst)[i] = make_uint2(h0, h1);
}

// ---------------------------------------------------------------------------
// QKV projection: y = X @ W^T + b (fp16 2-term: Ahi*B + Alo*B).
// Block 128x128, 512 threads, warp tile 32x32, K slab 32,
// cp.async double-buffered. Output fp16 scattered into [B,H,S,HD].
// ---------------------------------------------------------------------------
#define PITCH  80
#define TILEB  10240                 // one 128x32 fp16 tile (pitch 80)
#define BUFSZ  (3 * TILEB)           // Ahi, Alo, B
#define GEMM_SMEM (2 * BUFSZ)        // 61440

__global__ __launch_bounds__(512, 1) void qkv_fp16(
    const float* __restrict__ bq, const float* __restrict__ bk,
    const float* __restrict__ bv)
{
    extern __shared__ char smem[];
    const uint32_t sb = smem_u32(smem);

    const int z = blockIdx.z;
    const float* bias = (z == 0) ? bq : (z == 1) ? bk : bv;
    __half* out = (z == 0) ? g_Q : (z == 1) ? g_K : g_V;
    const float scale = (z == 0) ? 0.125f * LOG2E : 1.0f;
    const __half* W = gW + (size_t)z * D_MODEL * D_MODEL;

    const int tid  = threadIdx.x;
    const int lane = tid & 31;
    const int wid  = tid >> 5;
    const int wm   = wid >> 2;
    const int wn   = wid & 3;
    const int g    = lane >> 2;
    const int tig  = lane & 3;
    const int mat  = lane >> 3;
    const int mr   = lane & 7;

    const int m0 = blockIdx.y * 128;
    const int n0 = blockIdx.x * 128;

    const int srow = tid >> 2;        // 0..127
    const int sch  = tid & 3;         // chunk 0..3 (16B each)

    const int gm = m0 + srow;
    const int szA = (gm < M_TOT) ? 16 : 0;
    const size_t arow_off = (size_t)min(gm, M_TOT - 1) * D_MODEL;
    const size_t brow_off = (size_t)(n0 + srow) * D_MODEL;

    float c[2][4][4];
#pragma unroll
    for (int mf = 0; mf < 2; mf++)
#pragma unroll
        for (int nf = 0; nf < 4; nf++)
#pragma unroll
            for (int cc = 0; cc < 4; cc++) c[mf][nf][cc] = 0.0f;

    auto issue = [&](int s, int buf) {
        const int k0 = s * 32;
        uint32_t d0 = sb + buf * BUFSZ + (uint32_t)srow * PITCH + sch * 16;
        cp16(d0,             (const char*)(gXhi + arow_off + k0) + sch * 16, szA);
        cp16(d0 + TILEB,     (const char*)(gXlo + arow_off + k0) + sch * 16, szA);
        cp16(d0 + 2 * TILEB, (const char*)(W + brow_off + k0) + sch * 16, 16);
    };

    issue(0, 0);
    cp_commit();

    for (int s = 0; s < 32; s++) {
        if (s + 1 < 32) { issue(s + 1, (s + 1) & 1); cp_commit(); cp_wait1(); }
        else cp_wait0();
        __syncthreads();

        const uint32_t base = sb + (s & 1) * BUFSZ;
#pragma unroll
        for (int t = 0; t < 2; t++) {
            uint32_t ahi[2][4], alo[2][4];
#pragma unroll
            for (int mf = 0; mf < 2; mf++) {
                int arow = wm * 32 + mf * 16 + (mat & 1) * 8 + mr;
                uint32_t koff = t * 32 + (mat >> 1) * 16;
                uint32_t addr = base + (uint32_t)arow * PITCH + koff;
                ldm_x4(ahi[mf][0], ahi[mf][1], ahi[mf][2], ahi[mf][3], addr);
                ldm_x4(alo[mf][0], alo[mf][1], alo[mf][2], alo[mf][3], addr + TILEB);
            }
            uint32_t bf[4][2];
#pragma unroll
            for (int nfp = 0; nfp < 2; nfp++) {
                int nrow = wn * 32 + nfp * 16 + (mat >> 1) * 8 + mr;
                uint32_t koff = t * 32 + (mat & 1) * 16;
                uint32_t addr = base + (uint32_t)nrow * PITCH + koff;
                ldm_x4(bf[2*nfp][0], bf[2*nfp][1], bf[2*nfp+1][0], bf[2*nfp+1][1],
                       addr + 2 * TILEB);
            }
#pragma unroll
            for (int mf = 0; mf < 2; mf++)
#pragma unroll
                for (int nf = 0; nf < 4; nf++) {
                    mma16h(c[mf][nf], ahi[mf], bf[nf][0], bf[nf][1]);
                    mma16h(c[mf][nf], alo[mf], bf[nf][0], bf[nf][1]);
                }
        }
        __syncthreads();
    }

    // epilogue: bias + scale, fp16 scatter into [B,H,S,HD]
#pragma unroll
    for (int mf = 0; mf < 2; mf++) {
#pragma unroll
        for (int nf = 0; nf < 4; nf++) {
            int n = n0 + wn * 32 + nf * 8 + 2 * tig;
            int h = n >> 6, d = n & 63;
            float bv0 = __ldg(bias + n), bv1 = __ldg(bias + n + 1);
#pragma unroll
            for (int half = 0; half < 2; half++) {
                int m = m0 + wm * 32 + mf * 16 + g + half * 8;
                if (m < M_TOT) {
                    int bb = m / S_LEN;
                    int ss = m - bb * S_LEN;
                    __half2 hv = __floats2half2_rn(
                        (c[mf][nf][half * 2 + 0] + bv0) * scale,
                        (c[mf][nf][half * 2 + 1] + bv1) * scale);
                    *reinterpret_cast<__half2*>(
                        out + (((size_t)(bb * H_NUM + h) * S_LEN + ss) * HD + d)) = hv;
                }
            }
        }
    }
}

// ---------------------------------------------------------------------------
// Flash attention, fp16 m16n8k16. CTA = 128 queries, 4 warps, each warp
// owns TWO 16-row query tiles (u=0,1) so every K/V ldmatrix feeds 4 mmas.
// Scores arrive in log2 domain (Q pre-scaled by 0.125*log2e) -> exp2f.
// ---------------------------------------------------------------------------
#define NEG_BIG (-1e30f)
#define APITCH  144                   // bytes per smem row (64 fp16 + 8 pad)
#define OFF_Q   0
#define OFF_K(bb) (18432 + (bb) * 9216)
#define OFF_V(bb) (36864 + (bb) * 9216)
#define ATTN_SMEM 55296

__global__ __launch_bounds__(128) void attn_fp16(float* __restrict__ out)
{
    extern __shared__ char asmem[];
    const uint32_t sbase = smem_u32(asmem);

    const int h  = blockIdx.y;
    const int b  = blockIdx.z;
    const int qt = blockIdx.x;
    const int tid  = threadIdx.x;
    const int lane = tid & 31;
    const int w    = tid >> 5;
    const int g    = lane >> 2;
    const int tig  = lane & 3;
    const int mat  = lane >> 3;
    const int mr   = lane & 7;

    const size_t base = (size_t)(b * H_NUM + h) * S_LEN * HD;
    const __half* Qb = g_Q + base;
    const __half* Kb = g_K + base;
    const __half* Vb = g_V + base;

    // stage Q tile (128 rows), zero-filled OOB
#pragma unroll
    for (int p = 0; p < 8; p++) {
        int idx = tid + 128 * p;       // 0..1023
        int row = idx >> 3;
        int ch  = idx & 7;
        int qi = qt * 128 + row;
        int sz = (qi < S_LEN) ? 16 : 0;
        const char* src = (const char*)(Qb + (size_t)min(qi, S_LEN - 1) * HD) + ch * 16;
        cp16(sbase + OFF_Q + (uint32_t)row * APITCH + ch * 16, src, sz);
    }
    cp_commit();

    auto issue_kv = [&](int kt, int bb) {
#pragma unroll
        for (int p = 0; p < 4; p++) {
            int idx = tid + 128 * p;
            int row = idx >> 3;
            int ch  = idx & 7;
            int ki = kt * 64 + row;
            int sz = (ki < S_LEN) ? 16 : 0;
            size_t roff = (size_t)min(ki, S_LEN - 1) * HD;
            cp16(sbase + OFF_K(bb) + (uint32_t)row * APITCH + ch * 16,
                 (const char*)(Kb + roff) + ch * 16, sz);
            cp16(sbase + OFF_V(bb) + (uint32_t)row * APITCH + ch * 16,
                 (const char*)(Vb + roff) + ch * 16, sz);
        }
    };

    issue_kv(0, 0);
    cp_commit();
    cp_wait1();            // Q group done
    __syncthreads();

    // load Q fragments: two 16-row tiles per warp
    uint32_t qa[2][4][4];
#pragma unroll
    for (int u = 0; u < 2; u++)
#pragma unroll
        for (int ks = 0; ks < 4; ks++) {
            uint32_t addr = sbase + OFF_Q
                + (uint32_t)(w * 32 + u * 16 + (mat & 1) * 8 + mr) * APITCH
                + ks * 32 + (mat >> 1) * 16;
            ldm_x4(qa[u][ks][0], qa[u][ks][1], qa[u][ks][2], qa[u][ks][3], addr);
        }

    float oc[2][8][4];
#pragma unroll
    for (int u = 0; u < 2; u++)
#pragma unroll
        for (int nf = 0; nf < 8; nf++)
#pragma unroll
            for (int cc = 0; cc < 4; cc++) oc[u][nf][cc] = 0.0f;
    float m1[2] = {NEG_BIG, NEG_BIG}, m2[2] = {NEG_BIG, NEG_BIG};
    float l1[2] = {0.f, 0.f}, l2[2] = {0.f, 0.f};

    const int ntiles = (S_LEN + 63) / 64;    // 22
    for (int kt = 0; kt < ntiles; kt++) {
        if (kt + 1 < ntiles) { issue_kv(kt + 1, (kt + 1) & 1); cp_commit(); cp_wait1(); }
        else cp_wait0();
        __syncthreads();

        const int rem = min(64, S_LEN - kt * 64);
        const uint32_t sbK = sbase + OFF_K(kt & 1);
        const uint32_t sbV = sbase + OFF_V(kt & 1);

        // ---- S = Q K^T (log2-domain) ----
        float sc[2][8][4];
#pragma unroll
        for (int u = 0; u < 2; u++)
#pragma unroll
            for (int nf = 0; nf < 8; nf++)
#pragma unroll
                for (int cc = 0; cc < 4; cc++) sc[u][nf][cc] = 0.0f;

#pragma unroll
        for (int ks = 0; ks < 4; ks++) {
#pragma unroll
            for (int nf2 = 0; nf2 < 4; nf2++) {
                uint32_t r0, rr1, rr2, rr3;
                uint32_t addr = sbK + (uint32_t)(nf2 * 16 + (mat >> 1) * 8 + mr) * APITCH
                              + ks * 32 + (mat & 1) * 16;
                ldm_x4(r0, rr1, rr2, rr3, addr);
#pragma unroll
                for (int u = 0; u < 2; u++) {
                    mma16h(sc[u][2 * nf2],     qa[u][ks], r0,  rr1);
                    mma16h(sc[u][2 * nf2 + 1], qa[u][ks], rr2, rr3);
                }
            }
        }

#pragma unroll
        for (int u = 0; u < 2; u++) {
            // mask tail columns
            if (rem < 64) {
#pragma unroll
                for (int nf = 0; nf < 8; nf++) {
                    int col = nf * 8 + 2 * tig;
                    if (col     >= rem) { sc[u][nf][0] = NEG_BIG; sc[u][nf][2] = NEG_BIG; }
                    if (col + 1 >= rem) { sc[u][nf][1] = NEG_BIG; sc[u][nf][3] = NEG_BIG; }
                }
            }

            float rmax1 = NEG_BIG, rmax2 = NEG_BIG;
#pragma unroll
            for (int nf = 0; nf < 8; nf++) {
                rmax1 = fmaxf(rmax1, fmaxf(sc[u][nf][0], sc[u][nf][1]));
                rmax2 = fmaxf(rmax2, fmaxf(sc[u][nf][2], sc[u][nf][3]));
            }
            rmax1 = fmaxf(rmax1, __shfl_xor_sync(0xffffffffu, rmax1, 1));
            rmax1 = fmaxf(rmax1, __shfl_xor_sync(0xffffffffu, rmax1, 2));
            rmax2 = fmaxf(rmax2, __shfl_xor_sync(0xffffffffu, rmax2, 1));
            rmax2 = fmaxf(rmax2, __shfl_xor_sync(0xffffffffu, rmax2, 2));

            float nm1 = fmaxf(m1[u], rmax1);
            float nm2 = fmaxf(m2[u], rmax2);
            float corr1 = exp2f(m1[u] - nm1);
            float corr2 = exp2f(m2[u] - nm2);

            float ps1 = 0.0f, ps2 = 0.0f;
#pragma unroll
            for (int nf = 0; nf < 8; nf++) {
                sc[u][nf][0] = exp2f(sc[u][nf][0] - nm1); ps1 += sc[u][nf][0];
                sc[u][nf][1] = exp2f(sc[u][nf][1] - nm1); ps1 += sc[u][nf][1];
                sc[u][nf][2] = exp2f(sc[u][nf][2] - nm2); ps2 += sc[u][nf][2];
                sc[u][nf][3] = exp2f(sc[u][nf][3] - nm2); ps2 += sc[u][nf][3];
            }
            ps1 += __shfl_xor_sync(0xffffffffu, ps1, 1);
            ps1 += __shfl_xor_sync(0xffffffffu, ps1, 2);
            ps2 += __shfl_xor_sync(0xffffffffu, ps2, 1);
            ps2 += __shfl_xor_sync(0xffffffffu, ps2, 2);

            l1[u] = l1[u] * corr1 + ps1;
            l2[u] = l2[u] * corr2 + ps2;
#pragma unroll
            for (int nf = 0; nf < 8; nf++) {
                oc[u][nf][0] *= corr1; oc[u][nf][1] *= corr1;
                oc[u][nf][2] *= corr2; oc[u][nf][3] *= corr2;
            }
            m1[u] = nm1; m2[u] = nm2;
        }

        // ---- O += P V ----
#pragma unroll
        for (int ks = 0; ks < 4; ks++) {
            uint32_t pa[2][4];
#pragma unroll
            for (int u = 0; u < 2; u++) {
                pa[u][0] = h2pack(sc[u][2*ks][0],   sc[u][2*ks][1]);
                pa[u][1] = h2pack(sc[u][2*ks][2],   sc[u][2*ks][3]);
                pa[u][2] = h2pack(sc[u][2*ks+1][0], sc[u][2*ks+1][1]);
                pa[u][3] = h2pack(sc[u][2*ks+1][2], sc[u][2*ks+1][3]);
            }
#pragma unroll
            for (int nf2 = 0; nf2 < 4; nf2++) {
                uint32_t r0, rr1, rr2, rr3;
                uint32_t addr = sbV + (uint32_t)(ks * 16 + (mat & 1) * 8 + mr) * APITCH
                              + nf2 * 32 + (mat >> 1) * 16;
                ldm_x4t(r0, rr1, rr2, rr3, addr);
#pragma unroll
                for (int u = 0; u < 2; u++) {
                    mma16h(oc[u][2 * nf2],     pa[u], r0,  rr1);
                    mma16h(oc[u][2 * nf2 + 1], pa[u], rr2, rr3);
                }
            }
        }
        __syncthreads();
    }

    // ---- normalize + write [B,S,H*HD] fp32 ----
#pragma unroll
    for (int u = 0; u < 2; u++) {
        const int r1 = qt * 128 + w * 32 + u * 16 + g;
        const int r2 = r1 + 8;
        float inv1 = 1.0f / l1[u];
        float inv2 = 1.0f / l2[u];
#pragma unroll
        for (int nf = 0; nf < 8; nf++) {
            int d = nf * 8 + 2 * tig;
            if (r1 < S_LEN) {
                float2 v; v.x = oc[u][nf][0] * inv1; v.y = oc[u][nf][1] * inv1;
                *reinterpret_cast<float2*>(
                    out + (size_t)(b * S_LEN + r1) * D_MODEL + h * HD + d) = v;
            }
            if (r2 < S_LEN) {
                float2 v; v.x = oc[u][nf][2] * inv2; v.y = oc[u][nf][3] * inv2;
                *reinterpret_cast<float2*>(
                    out + (size_t)(b * S_LEN + r2) * D_MODEL + h * HD + d) = v;
            }
        }
    }
}

// ---------------------------------------------------------------------------
extern "C" void kernel_launch(void* const* d_in, const int* in_sizes, int n_in,
                              void* d_out, int out_size)
{
    const float* X  = (const float*)d_in[0];
    const float* Wq = (const float*)d_in[1];
    const float* bq = (const float*)d_in[2];
    const float* Wk = (const float*)d_in[3];
    const float* bk = (const float*)d_in[4];
    const float* Wv = (const float*)d_in[5];
    const float* bv = (const float*)d_in[6];
    float* out = (float*)d_out;

    static int once = 0;
    if (!once) {
        cudaFuncSetAttribute(qkv_fp16, cudaFuncAttributeMaxDynamicSharedMemorySize, GEMM_SMEM);
        cudaFuncSetAttribute(attn_fp16, cudaFuncAttributeMaxDynamicSharedMemorySize, ATTN_SMEM);
        once = 1;
    }

    const int n4x = M_TOT * D_MODEL / 4;
    const int n4w = D_MODEL * D_MODEL / 4;
    conv_x<<<(n4x + 255) / 256, 256>>>(X, n4x);
    conv_w<<<(n4w + 255) / 256, 256>>>(Wq, 0, n4w);
    conv_w<<<(n4w + 255) / 256, 256>>>(Wk, 1, n4w);
    conv_w<<<(n4w + 255) / 256, 256>>>(Wv, 2, n4w);

    dim3 g1(D_MODEL / 128, (M_TOT + 127) / 128, 3);
    qkv_fp16<<<g1, 512, GEMM_SMEM>>>(bq, bk, bv);

    dim3 g2((S_LEN + 127) / 128, H_NUM, B_SZ);
    attn_fp16<<<g2, 128, ATTN_SMEM>>>(out);
}

// round 7
// speedup vs baseline: 6.9762x; 1.3684x over previous
#include <cuda_runtime.h>
#include <cuda_fp16.h>
#include <stdint.h>

#define S_LEN   1370
#define B_SZ    8
#define D_MODEL 1024
#define H_NUM   16
#define HD      64
#define M_TOT   (B_SZ * S_LEN)   // 10960
#define LOG2E   1.4426950408889634f

// pre-converted GEMM operands (single fp16)
__device__ __half gX[(size_t)M_TOT * D_MODEL];
__device__ __half gW[3ull * D_MODEL * D_MODEL];
// projected Q/K/V in fp16, [B,H,S,HD]; Q pre-scaled by 0.125*log2(e)
__device__ __half g_Q[(size_t)M_TOT * D_MODEL];
__device__ __half g_K[(size_t)M_TOT * D_MODEL];
__device__ __half g_V[(size_t)M_TOT * D_MODEL];

// ---------------------------------------------------------------------------
// helpers
// ---------------------------------------------------------------------------
__device__ __forceinline__ uint32_t smem_u32(const void* p) {
    return (uint32_t)__cvta_generic_to_shared(p);
}
__device__ __forceinline__ void cp16(uint32_t dst, const void* src, int sz) {
    asm volatile("cp.async.cg.shared.global [%0], [%1], 16, %2;"
                 :: "r"(dst), "l"(src), "r"(sz) : "memory");
}
__device__ __forceinline__ void cp_commit() {
    asm volatile("cp.async.commit_group;" ::: "memory");
}
__device__ __forceinline__ void cp_wait1() {
    asm volatile("cp.async.wait_group 1;" ::: "memory");
}
__device__ __forceinline__ void cp_wait0() {
    asm volatile("cp.async.wait_group 0;" ::: "memory");
}
__device__ __forceinline__ void ldm_x4(uint32_t& r0, uint32_t& r1, uint32_t& r2, uint32_t& r3,
                                       uint32_t addr) {
    asm volatile("ldmatrix.sync.aligned.m8n8.x4.shared.b16 {%0,%1,%2,%3}, [%4];"
                 : "=r"(r0), "=r"(r1), "=r"(r2), "=r"(r3) : "r"(addr));
}
__device__ __forceinline__ void ldm_x4t(uint32_t& r0, uint32_t& r1, uint32_t& r2, uint32_t& r3,
                                        uint32_t addr) {
    asm volatile("ldmatrix.sync.aligned.m8n8.x4.trans.shared.b16 {%0,%1,%2,%3}, [%4];"
                 : "=r"(r0), "=r"(r1), "=r"(r2), "=r"(r3) : "r"(addr));
}
__device__ __forceinline__ void mma16h(float* c, const uint32_t* a, uint32_t b0, uint32_t b1) {
    asm volatile(
        "mma.sync.aligned.m16n8k16.row.col.f32.f16.f16.f32 "
        "{%0,%1,%2,%3},{%4,%5,%6,%7},{%8,%9},{%0,%1,%2,%3};\n"
        : "+f"(c[0]), "+f"(c[1]), "+f"(c[2]), "+f"(c[3])
        : "r"(a[0]), "r"(a[1]), "r"(a[2]), "r"(a[3]), "r"(b0), "r"(b1));
}
__device__ __forceinline__ uint32_t h2pack(float lo, float hi) {
    __half2 h = __floats2half2_rn(lo, hi);
    return *reinterpret_cast<uint32_t*>(&h);
}

// ---------------------------------------------------------------------------
// Pre-convert fp32 -> fp16. sel 0 = X, 1..3 = Wq/Wk/Wv plane
// ---------------------------------------------------------------------------
__global__ void conv_h(const float* __restrict__ src, int sel, int n4)
{
    int i = blockIdx.x * 256 + threadIdx.x;
    if (i >= n4) return;
    __half* dst = (sel == 0) ? gX : gW + (size_t)(sel - 1) * D_MODEL * D_MODEL;
    float4 v = reinterpret_cast<const float4*>(src)[i];
    uint32_t h0 = __half_as_ushort(__float2half_rn(v.x)) |
                  ((uint32_t)__half_as_ushort(__float2half_rn(v.y)) << 16);
    uint32_t h1 = __half_as_ushort(__float2half_rn(v.z)) |
                  ((uint32_t)__half_as_ushort(__float2half_rn(v.w)) << 16);
    reinterpret_cast<uint2*>(dst)[i] = make_uint2(h0, h1);
}

// ---------------------------------------------------------------------------
// QKV projection: y = X @ W^T + b (single-pass fp16 m16n8k16).
// Block 128x128, 512 threads, warp tile 32x32, K slab 32,
// cp.async double-buffered. Output fp16 scattered into [B,H,S,HD].
// ---------------------------------------------------------------------------
#define PITCH  80
#define TILEB  10240                 // one 128x32 fp16 tile (pitch 80)
#define BUFSZ  (2 * TILEB)           // A, B
#define GEMM_SMEM (2 * BUFSZ)        // 40960

__global__ __launch_bounds__(512, 1) void qkv_fp16(
    const float* __restrict__ bq, const float* __restrict__ bk,
    const float* __restrict__ bv)
{
    extern __shared__ char smem[];
    const uint32_t sb = smem_u32(smem);

    const int z = blockIdx.z;
    const float* bias = (z == 0) ? bq : (z == 1) ? bk : bv;
    __half* out = (z == 0) ? g_Q : (z == 1) ? g_K : g_V;
    const float scale = (z == 0) ? 0.125f * LOG2E : 1.0f;
    const __half* W = gW + (size_t)z * D_MODEL * D_MODEL;

    const int tid  = threadIdx.x;
    const int lane = tid & 31;
    const int wid  = tid >> 5;
    const int wm   = wid >> 2;
    const int wn   = wid & 3;
    const int g    = lane >> 2;
    const int tig  = lane & 3;
    const int mat  = lane >> 3;
    const int mr   = lane & 7;

    const int m0 = blockIdx.y * 128;
    const int n0 = blockIdx.x * 128;

    const int srow = tid >> 2;        // 0..127
    const int sch  = tid & 3;         // chunk 0..3 (16B each)

    const int gm = m0 + srow;
    const int szA = (gm < M_TOT) ? 16 : 0;
    const size_t arow_off = (size_t)min(gm, M_TOT - 1) * D_MODEL;
    const size_t brow_off = (size_t)(n0 + srow) * D_MODEL;

    float c[2][4][4];
#pragma unroll
    for (int mf = 0; mf < 2; mf++)
#pragma unroll
        for (int nf = 0; nf < 4; nf++)
#pragma unroll
            for (int cc = 0; cc < 4; cc++) c[mf][nf][cc] = 0.0f;

    auto issue = [&](int s, int buf) {
        const int k0 = s * 32;
        uint32_t d0 = sb + buf * BUFSZ + (uint32_t)srow * PITCH + sch * 16;
        cp16(d0,         (const char*)(gX + arow_off + k0) + sch * 16, szA);
        cp16(d0 + TILEB, (const char*)(W + brow_off + k0) + sch * 16, 16);
    };

    issue(0, 0);
    cp_commit();

    for (int s = 0; s < 32; s++) {
        if (s + 1 < 32) { issue(s + 1, (s + 1) & 1); cp_commit(); cp_wait1(); }
        else cp_wait0();
        __syncthreads();

        const uint32_t base = sb + (s & 1) * BUFSZ;
#pragma unroll
        for (int t = 0; t < 2; t++) {
            uint32_t af[2][4];
#pragma unroll
            for (int mf = 0; mf < 2; mf++) {
                int arow = wm * 32 + mf * 16 + (mat & 1) * 8 + mr;
                uint32_t koff = t * 32 + (mat >> 1) * 16;
                uint32_t addr = base + (uint32_t)arow * PITCH + koff;
                ldm_x4(af[mf][0], af[mf][1], af[mf][2], af[mf][3], addr);
            }
            uint32_t bf[4][2];
#pragma unroll
            for (int nfp = 0; nfp < 2; nfp++) {
                int nrow = wn * 32 + nfp * 16 + (mat >> 1) * 8 + mr;
                uint32_t koff = t * 32 + (mat & 1) * 16;
                uint32_t addr = base + (uint32_t)nrow * PITCH + koff;
                ldm_x4(bf[2*nfp][0], bf[2*nfp][1], bf[2*nfp+1][0], bf[2*nfp+1][1],
                       addr + TILEB);
            }
#pragma unroll
            for (int mf = 0; mf < 2; mf++)
#pragma unroll
                for (int nf = 0; nf < 4; nf++)
                    mma16h(c[mf][nf], af[mf], bf[nf][0], bf[nf][1]);
        }
        __syncthreads();
    }

    // epilogue: bias + scale, fp16 scatter into [B,H,S,HD]
#pragma unroll
    for (int mf = 0; mf < 2; mf++) {
#pragma unroll
        for (int nf = 0; nf < 4; nf++) {
            int n = n0 + wn * 32 + nf * 8 + 2 * tig;
            int h = n >> 6, d = n & 63;
            float bv0 = __ldg(bias + n), bv1 = __ldg(bias + n + 1);
#pragma unroll
            for (int half = 0; half < 2; half++) {
                int m = m0 + wm * 32 + mf * 16 + g + half * 8;
                if (m < M_TOT) {
                    int bb = m / S_LEN;
                    int ss = m - bb * S_LEN;
                    __half2 hv = __floats2half2_rn(
                        (c[mf][nf][half * 2 + 0] + bv0) * scale,
                        (c[mf][nf][half * 2 + 1] + bv1) * scale);
                    *reinterpret_cast<__half2*>(
                        out + (((size_t)(bb * H_NUM + h) * S_LEN + ss) * HD + d)) = hv;
                }
            }
        }
    }
}

// ---------------------------------------------------------------------------
// Flash attention, fp16 m16n8k16. CTA = 128 queries, 4 warps, each warp
// owns TWO 16-row query tiles (u=0,1) so every K/V ldmatrix feeds 4 mmas.
// Scores arrive in log2 domain (Q pre-scaled by 0.125*log2e) -> exp2f.
// ---------------------------------------------------------------------------
#define NEG_BIG (-1e30f)
#define APITCH  144                   // bytes per smem row (64 fp16 + 8 pad)
#define OFF_Q   0
#define OFF_K(bb) (18432 + (bb) * 9216)
#define OFF_V(bb) (36864 + (bb) * 9216)
#define ATTN_SMEM 55296

__global__ __launch_bounds__(128) void attn_fp16(float* __restrict__ out)
{
    extern __shared__ char asmem[];
    const uint32_t sbase = smem_u32(asmem);

    const int h  = blockIdx.y;
    const int b  = blockIdx.z;
    const int qt = blockIdx.x;
    const int tid  = threadIdx.x;
    const int lane = tid & 31;
    const int w    = tid >> 5;
    const int g    = lane >> 2;
    const int tig  = lane & 3;
    const int mat  = lane >> 3;
    const int mr   = lane & 7;

    const size_t base = (size_t)(b * H_NUM + h) * S_LEN * HD;
    const __half* Qb = g_Q + base;
    const __half* Kb = g_K + base;
    const __half* Vb = g_V + base;

    // stage Q tile (128 rows), zero-filled OOB
#pragma unroll
    for (int p = 0; p < 8; p++) {
        int idx = tid + 128 * p;       // 0..1023
        int row = idx >> 3;
        int ch  = idx & 7;
        int qi = qt * 128 + row;
        int sz = (qi < S_LEN) ? 16 : 0;
        const char* src = (const char*)(Qb + (size_t)min(qi, S_LEN - 1) * HD) + ch * 16;
        cp16(sbase + OFF_Q + (uint32_t)row * APITCH + ch * 16, src, sz);
    }
    cp_commit();

    auto issue_kv = [&](int kt, int bb) {
#pragma unroll
        for (int p = 0; p < 4; p++) {
            int idx = tid + 128 * p;
            int row = idx >> 3;
            int ch  = idx & 7;
            int ki = kt * 64 + row;
            int sz = (ki < S_LEN) ? 16 : 0;
            size_t roff = (size_t)min(ki, S_LEN - 1) * HD;
            cp16(sbase + OFF_K(bb) + (uint32_t)row * APITCH + ch * 16,
                 (const char*)(Kb + roff) + ch * 16, sz);
            cp16(sbase + OFF_V(bb) + (uint32_t)row * APITCH + ch * 16,
                 (const char*)(Vb + roff) + ch * 16, sz);
        }
    };

    issue_kv(0, 0);
    cp_commit();
    cp_wait1();            // Q group done
    __syncthreads();

    // load Q fragments: two 16-row tiles per warp
    uint32_t qa[2][4][4];
#pragma unroll
    for (int u = 0; u < 2; u++)
#pragma unroll
        for (int ks = 0; ks < 4; ks++) {
            uint32_t addr = sbase + OFF_Q
                + (uint32_t)(w * 32 + u * 16 + (mat & 1) * 8 + mr) * APITCH
                + ks * 32 + (mat >> 1) * 16;
            ldm_x4(qa[u][ks][0], qa[u][ks][1], qa[u][ks][2], qa[u][ks][3], addr);
        }

    float oc[2][8][4];
#pragma unroll
    for (int u = 0; u < 2; u++)
#pragma unroll
        for (int nf = 0; nf < 8; nf++)
#pragma unroll
            for (int cc = 0; cc < 4; cc++) oc[u][nf][cc] = 0.0f;
    float m1[2] = {NEG_BIG, NEG_BIG}, m2[2] = {NEG_BIG, NEG_BIG};
    float l1[2] = {0.f, 0.f}, l2[2] = {0.f, 0.f};

    const int ntiles = (S_LEN + 63) / 64;    // 22
    for (int kt = 0; kt < ntiles; kt++) {
        if (kt + 1 < ntiles) { issue_kv(kt + 1, (kt + 1) & 1); cp_commit(); cp_wait1(); }
        else cp_wait0();
        __syncthreads();

        const int rem = min(64, S_LEN - kt * 64);
        const uint32_t sbK = sbase + OFF_K(kt & 1);
        const uint32_t sbV = sbase + OFF_V(kt & 1);

        // ---- S = Q K^T (log2-domain) ----
        float sc[2][8][4];
#pragma unroll
        for (int u = 0; u < 2; u++)
#pragma unroll
            for (int nf = 0; nf < 8; nf++)
#pragma unroll
                for (int cc = 0; cc < 4; cc++) sc[u][nf][cc] = 0.0f;

#pragma unroll
        for (int ks = 0; ks < 4; ks++) {
#pragma unroll
            for (int nf2 = 0; nf2 < 4; nf2++) {
                uint32_t r0, rr1, rr2, rr3;
                uint32_t addr = sbK + (uint32_t)(nf2 * 16 + (mat >> 1) * 8 + mr) * APITCH
                              + ks * 32 + (mat & 1) * 16;
                ldm_x4(r0, rr1, rr2, rr3, addr);
#pragma unroll
                for (int u = 0; u < 2; u++) {
                    mma16h(sc[u][2 * nf2],     qa[u][ks], r0,  rr1);
                    mma16h(sc[u][2 * nf2 + 1], qa[u][ks], rr2, rr3);
                }
            }
        }

#pragma unroll
        for (int u = 0; u < 2; u++) {
            // mask tail columns
            if (rem < 64) {
#pragma unroll
                for (int nf = 0; nf < 8; nf++) {
                    int col = nf * 8 + 2 * tig;
                    if (col     >= rem) { sc[u][nf][0] = NEG_BIG; sc[u][nf][2] = NEG_BIG; }
                    if (col + 1 >= rem) { sc[u][nf][1] = NEG_BIG; sc[u][nf][3] = NEG_BIG; }
                }
            }

            float rmax1 = NEG_BIG, rmax2 = NEG_BIG;
#pragma unroll
            for (int nf = 0; nf < 8; nf++) {
                rmax1 = fmaxf(rmax1, fmaxf(sc[u][nf][0], sc[u][nf][1]));
                rmax2 = fmaxf(rmax2, fmaxf(sc[u][nf][2], sc[u][nf][3]));
            }
            rmax1 = fmaxf(rmax1, __shfl_xor_sync(0xffffffffu, rmax1, 1));
            rmax1 = fmaxf(rmax1, __shfl_xor_sync(0xffffffffu, rmax1, 2));
            rmax2 = fmaxf(rmax2, __shfl_xor_sync(0xffffffffu, rmax2, 1));
            rmax2 = fmaxf(rmax2, __shfl_xor_sync(0xffffffffu, rmax2, 2));

            float nm1 = fmaxf(m1[u], rmax1);
            float nm2 = fmaxf(m2[u], rmax2);
            float corr1 = exp2f(m1[u] - nm1);
            float corr2 = exp2f(m2[u] - nm2);

            float ps1 = 0.0f, ps2 = 0.0f;
#pragma unroll
            for (int nf = 0; nf < 8; nf++) {
                sc[u][nf][0] = exp2f(sc[u][nf][0] - nm1); ps1 += sc[u][nf][0];
                sc[u][nf][1] = exp2f(sc[u][nf][1] - nm1); ps1 += sc[u][nf][1];
                sc[u][nf][2] = exp2f(sc[u][nf][2] - nm2); ps2 += sc[u][nf][2];
                sc[u][nf][3] = exp2f(sc[u][nf][3] - nm2); ps2 += sc[u][nf][3];
            }
            ps1 += __shfl_xor_sync(0xffffffffu, ps1, 1);
            ps1 += __shfl_xor_sync(0xffffffffu, ps1, 2);
            ps2 += __shfl_xor_sync(0xffffffffu, ps2, 1);
            ps2 += __shfl_xor_sync(0xffffffffu, ps2, 2);

            l1[u] = l1[u] * corr1 + ps1;
            l2[u] = l2[u] * corr2 + ps2;
#pragma unroll
            for (int nf = 0; nf < 8; nf++) {
                oc[u][nf][0] *= corr1; oc[u][nf][1] *= corr1;
                oc[u][nf][2] *= corr2; oc[u][nf][3] *= corr2;
            }
            m1[u] = nm1; m2[u] = nm2;
        }

        // ---- O += P V ----
#pragma unroll
        for (int ks = 0; ks < 4; ks++) {
            uint32_t pa[2][4];
#pragma unroll
            for (int u = 0; u < 2; u++) {
                pa[u][0] = h2pack(sc[u][2*ks][0],   sc[u][2*ks][1]);
                pa[u][1] = h2pack(sc[u][2*ks][2],   sc[u][2*ks][3]);
                pa[u][2] = h2pack(sc[u][2*ks+1][0], sc[u][2*ks+1][1]);
                pa[u][3] = h2pack(sc[u][2*ks+1][2], sc[u][2*ks+1][3]);
            }
#pragma unroll
            for (int nf2 = 0; nf2 < 4; nf2++) {
                uint32_t r0, rr1, rr2, rr3;
                uint32_t addr = sbV + (uint32_t)(ks * 16 + (mat & 1) * 8 + mr) * APITCH
                              + nf2 * 32 + (mat >> 1) * 16;
                ldm_x4t(r0, rr1, rr2, rr3, addr);
#pragma unroll
                for (int u = 0; u < 2; u++) {
                    mma16h(oc[u][2 * nf2],     pa[u], r0,  rr1);
                    mma16h(oc[u][2 * nf2 + 1], pa[u], rr2, rr3);
                }
            }
        }
        __syncthreads();
    }

    // ---- normalize + write [B,S,H*HD] fp32 ----
#pragma unroll
    for (int u = 0; u < 2; u++) {
        const int r1 = qt * 128 + w * 32 + u * 16 + g;
        const int r2 = r1 + 8;
        float inv1 = 1.0f / l1[u];
        float inv2 = 1.0f / l2[u];
#pragma unroll
        for (int nf = 0; nf < 8; nf++) {
            int d = nf * 8 + 2 * tig;
            if (r1 < S_LEN) {
                float2 v; v.x = oc[u][nf][0] * inv1; v.y = oc[u][nf][1] * inv1;
                *reinterpret_cast<float2*>(
                    out + (size_t)(b * S_LEN + r1) * D_MODEL + h * HD + d) = v;
            }
            if (r2 < S_LEN) {
                float2 v; v.x = oc[u][nf][2] * inv2; v.y = oc[u][nf][3] * inv2;
                *reinterpret_cast<float2*>(
                    out + (size_t)(b * S_LEN + r2) * D_MODEL + h * HD + d) = v;
            }
        }
    }
}

// ---------------------------------------------------------------------------
extern "C" void kernel_launch(void* const* d_in, const int* in_sizes, int n_in,
                              void* d_out, int out_size)
{
    const float* X  = (const float*)d_in[0];
    const float* Wq = (const float*)d_in[1];
    const float* bq = (const float*)d_in[2];
    const float* Wk = (const float*)d_in[3];
    const float* bk = (const float*)d_in[4];
    const float* Wv = (const float*)d_in[5];
    const float* bv = (const float*)d_in[6];
    float* out = (float*)d_out;

    static int once = 0;
    if (!once) {
        cudaFuncSetAttribute(qkv_fp16, cudaFuncAttributeMaxDynamicSharedMemorySize, GEMM_SMEM);
        cudaFuncSetAttribute(attn_fp16, cudaFuncAttributeMaxDynamicSharedMemorySize, ATTN_SMEM);
        once = 1;
    }

    const int n4x = M_TOT * D_MODEL / 4;
    const int n4w = D_MODEL * D_MODEL / 4;
    conv_h<<<(n4x + 255) / 256, 256>>>(X,  0, n4x);
    conv_h<<<(n4w + 255) / 256, 256>>>(Wq, 1, n4w);
    conv_h<<<(n4w + 255) / 256, 256>>>(Wk, 2, n4w);
    conv_h<<<(n4w + 255) / 256, 256>>>(Wv, 3, n4w);

    dim3 g1(D_MODEL / 128, (M_TOT + 127) / 128, 3);
    qkv_fp16<<<g1, 512, GEMM_SMEM>>>(bq, bk, bv);

    dim3 g2((S_LEN + 127) / 128, H_NUM, B_SZ);
    attn_fp16<<<g2, 128, ATTN_SMEM>>>(out);
}

// round 8
// speedup vs baseline: 7.1038x; 1.0183x over previous
#include <cuda_runtime.h>
#include <cuda_fp16.h>
#include <stdint.h>

#define S_LEN   1370
#define B_SZ    8
#define D_MODEL 1024
#define H_NUM   16
#define HD      64
#define M_TOT   (B_SZ * S_LEN)   // 10960
#define LOG2E   1.4426950408889634f

// pre-converted GEMM operands (single fp16)
__device__ __half gX[(size_t)M_TOT * D_MODEL];
__device__ __half gW[3ull * D_MODEL * D_MODEL];
// projected Q/K/V in fp16, [B,H,S,HD]; Q pre-scaled by 0.125*log2(e)
__device__ __half g_Q[(size_t)M_TOT * D_MODEL];
__device__ __half g_K[(size_t)M_TOT * D_MODEL];
__device__ __half g_V[(size_t)M_TOT * D_MODEL];

// ---------------------------------------------------------------------------
// helpers
// ---------------------------------------------------------------------------
__device__ __forceinline__ uint32_t smem_u32(const void* p) {
    return (uint32_t)__cvta_generic_to_shared(p);
}
__device__ __forceinline__ void cp16(uint32_t dst, const void* src, int sz) {
    asm volatile("cp.async.cg.shared.global [%0], [%1], 16, %2;"
                 :: "r"(dst), "l"(src), "r"(sz) : "memory");
}
__device__ __forceinline__ void cp_commit() {
    asm volatile("cp.async.commit_group;" ::: "memory");
}
__device__ __forceinline__ void cp_wait1() {
    asm volatile("cp.async.wait_group 1;" ::: "memory");
}
__device__ __forceinline__ void cp_wait0() {
    asm volatile("cp.async.wait_group 0;" ::: "memory");
}
__device__ __forceinline__ void ldm_x4(uint32_t& r0, uint32_t& r1, uint32_t& r2, uint32_t& r3,
                                       uint32_t addr) {
    asm volatile("ldmatrix.sync.aligned.m8n8.x4.shared.b16 {%0,%1,%2,%3}, [%4];"
                 : "=r"(r0), "=r"(r1), "=r"(r2), "=r"(r3) : "r"(addr));
}
__device__ __forceinline__ void ldm_x4t(uint32_t& r0, uint32_t& r1, uint32_t& r2, uint32_t& r3,
                                        uint32_t addr) {
    asm volatile("ldmatrix.sync.aligned.m8n8.x4.trans.shared.b16 {%0,%1,%2,%3}, [%4];"
                 : "=r"(r0), "=r"(r1), "=r"(r2), "=r"(r3) : "r"(addr));
}
__device__ __forceinline__ void mma16h(float* c, const uint32_t* a, uint32_t b0, uint32_t b1) {
    asm volatile(
        "mma.sync.aligned.m16n8k16.row.col.f32.f16.f16.f32 "
        "{%0,%1,%2,%3},{%4,%5,%6,%7},{%8,%9},{%0,%1,%2,%3};\n"
        : "+f"(c[0]), "+f"(c[1]), "+f"(c[2]), "+f"(c[3])
        : "r"(a[0]), "r"(a[1]), "r"(a[2]), "r"(a[3]), "r"(b0), "r"(b1));
}
__device__ __forceinline__ uint32_t h2pack(float lo, float hi) {
    __half2 h = __floats2half2_rn(lo, hi);
    return *reinterpret_cast<uint32_t*>(&h);
}
__device__ __forceinline__ float ex2(float x) {
    float y;
    asm("ex2.approx.f32 %0, %1;" : "=f"(y) : "f"(x));
    return y;
}

// ---------------------------------------------------------------------------
// Pre-convert fp32 -> fp16
// ---------------------------------------------------------------------------
__global__ void conv_x(const float* __restrict__ src, int n4)
{
    int i = blockIdx.x * 256 + threadIdx.x;
    if (i >= n4) return;
    float4 v = reinterpret_cast<const float4*>(src)[i];
    uint32_t h0 = __half_as_ushort(__float2half_rn(v.x)) |
                  ((uint32_t)__half_as_ushort(__float2half_rn(v.y)) << 16);
    uint32_t h1 = __half_as_ushort(__float2half_rn(v.z)) |
                  ((uint32_t)__half_as_ushort(__float2half_rn(v.w)) << 16);
    reinterpret_cast<uint2*>(gX)[i] = make_uint2(h0, h1);
}

__global__ void conv_w3(const float* __restrict__ w0, const float* __restrict__ w1,
                        const float* __restrict__ w2, int n4)
{
    int i = blockIdx.x * 256 + threadIdx.x;
    if (i >= n4) return;
    int plane = blockIdx.y;
    const float* src = (plane == 0) ? w0 : (plane == 1) ? w1 : w2;
    __half* dst = gW + (size_t)plane * D_MODEL * D_MODEL;
    float4 v = reinterpret_cast<const float4*>(src)[i];
    uint32_t h0 = __half_as_ushort(__float2half_rn(v.x)) |
                  ((uint32_t)__half_as_ushort(__float2half_rn(v.y)) << 16);
    uint32_t h1 = __half_as_ushort(__float2half_rn(v.z)) |
                  ((uint32_t)__half_as_ushort(__float2half_rn(v.w)) << 16);
    reinterpret_cast<uint2*>(dst)[i] = make_uint2(h0, h1);
}

// ---------------------------------------------------------------------------
// QKV projection: y = X @ W^T + b (single-pass fp16 m16n8k16).
// Block 128x128, 512 threads, warp tile 32x32, K slab 32,
// cp.async double-buffered. Output fp16 scattered into [B,H,S,HD].
// ---------------------------------------------------------------------------
#define PITCH  80
#define TILEB  10240                 // one 128x32 fp16 tile (pitch 80)
#define BUFSZ  (2 * TILEB)           // A, B
#define GEMM_SMEM (2 * BUFSZ)        // 40960

__global__ __launch_bounds__(512, 1) void qkv_fp16(
    const float* __restrict__ bq, const float* __restrict__ bk,
    const float* __restrict__ bv)
{
    extern __shared__ char smem[];
    const uint32_t sb = smem_u32(smem);

    const int z = blockIdx.z;
    const float* bias = (z == 0) ? bq : (z == 1) ? bk : bv;
    __half* out = (z == 0) ? g_Q : (z == 1) ? g_K : g_V;
    const float scale = (z == 0) ? 0.125f * LOG2E : 1.0f;
    const __half* W = gW + (size_t)z * D_MODEL * D_MODEL;

    const int tid  = threadIdx.x;
    const int lane = tid & 31;
    const int wid  = tid >> 5;
    const int wm   = wid >> 2;
    const int wn   = wid & 3;
    const int g    = lane >> 2;
    const int tig  = lane & 3;
    const int mat  = lane >> 3;
    const int mr   = lane & 7;

    const int m0 = blockIdx.y * 128;
    const int n0 = blockIdx.x * 128;

    const int srow = tid >> 2;        // 0..127
    const int sch  = tid & 3;         // chunk 0..3 (16B each)

    const int gm = m0 + srow;
    const int szA = (gm < M_TOT) ? 16 : 0;
    const size_t arow_off = (size_t)min(gm, M_TOT - 1) * D_MODEL;
    const size_t brow_off = (size_t)(n0 + srow) * D_MODEL;

    float c[2][4][4];
#pragma unroll
    for (int mf = 0; mf < 2; mf++)
#pragma unroll
        for (int nf = 0; nf < 4; nf++)
#pragma unroll
            for (int cc = 0; cc < 4; cc++) c[mf][nf][cc] = 0.0f;

    auto issue = [&](int s, int buf) {
        const int k0 = s * 32;
        uint32_t d0 = sb + buf * BUFSZ + (uint32_t)srow * PITCH + sch * 16;
        cp16(d0,         (const char*)(gX + arow_off + k0) + sch * 16, szA);
        cp16(d0 + TILEB, (const char*)(W + brow_off + k0) + sch * 16, 16);
    };

    issue(0, 0);
    cp_commit();

    for (int s = 0; s < 32; s++) {
        if (s + 1 < 32) { issue(s + 1, (s + 1) & 1); cp_commit(); cp_wait1(); }
        else cp_wait0();
        __syncthreads();

        const uint32_t base = sb + (s & 1) * BUFSZ;
#pragma unroll
        for (int t = 0; t < 2; t++) {
            uint32_t af[2][4];
#pragma unroll
            for (int mf = 0; mf < 2; mf++) {
                int arow = wm * 32 + mf * 16 + (mat & 1) * 8 + mr;
                uint32_t koff = t * 32 + (mat >> 1) * 16;
                uint32_t addr = base + (uint32_t)arow * PITCH + koff;
                ldm_x4(af[mf][0], af[mf][1], af[mf][2], af[mf][3], addr);
            }
            uint32_t bf[4][2];
#pragma unroll
            for (int nfp = 0; nfp < 2; nfp++) {
                int nrow = wn * 32 + nfp * 16 + (mat >> 1) * 8 + mr;
                uint32_t koff = t * 32 + (mat & 1) * 16;
                uint32_t addr = base + (uint32_t)nrow * PITCH + koff;
                ldm_x4(bf[2*nfp][0], bf[2*nfp][1], bf[2*nfp+1][0], bf[2*nfp+1][1],
                       addr + TILEB);
            }
#pragma unroll
            for (int mf = 0; mf < 2; mf++)
#pragma unroll
                for (int nf = 0; nf < 4; nf++)
                    mma16h(c[mf][nf], af[mf], bf[nf][0], bf[nf][1]);
        }
        __syncthreads();
    }

    // epilogue: bias + scale, fp16 scatter into [B,H,S,HD]
#pragma unroll
    for (int mf = 0; mf < 2; mf++) {
#pragma unroll
        for (int nf = 0; nf < 4; nf++) {
            int n = n0 + wn * 32 + nf * 8 + 2 * tig;
            int h = n >> 6, d = n & 63;
            float bv0 = __ldg(bias + n), bv1 = __ldg(bias + n + 1);
#pragma unroll
            for (int half = 0; half < 2; half++) {
                int m = m0 + wm * 32 + mf * 16 + g + half * 8;
                if (m < M_TOT) {
                    int bb = m / S_LEN;
                    int ss = m - bb * S_LEN;
                    __half2 hv = __floats2half2_rn(
                        (c[mf][nf][half * 2 + 0] + bv0) * scale,
                        (c[mf][nf][half * 2 + 1] + bv1) * scale);
                    *reinterpret_cast<__half2*>(
                        out + (((size_t)(bb * H_NUM + h) * S_LEN + ss) * HD + d)) = hv;
                }
            }
        }
    }
}

// ---------------------------------------------------------------------------
// Flash attention, fp16 m16n8k16. CTA = 128 queries, 4 warps x two 16-row
// query tiles. Row-sum l computed BY the tensor core (constant ones-column
// B fragment). Rescale skipped via warp vote when running max unchanged.
// Q staged into the K double-buffer region (freed before KV pipeline).
// ---------------------------------------------------------------------------
#define NEG_BIG (-1e30f)
#define APITCH  144                   // bytes per smem row (64 fp16 + 8 pad)
#define KVSTG   9216                  // one 64-row K or V stage
// layout: K0 [0,9216) K1 [9216,18432) V0 [18432,27648) V1 [27648,36864)
// Q staged transiently at [0,18432) before the KV pipeline starts.
#define ATTN_SMEM 36864

__global__ __launch_bounds__(128) void attn_fp16(float* __restrict__ out)
{
    __shared__ char asmem[ATTN_SMEM];
    const uint32_t sbase = smem_u32(asmem);

    const int h  = blockIdx.y;
    const int b  = blockIdx.z;
    const int qt = blockIdx.x;
    const int tid  = threadIdx.x;
    const int lane = tid & 31;
    const int w    = tid >> 5;
    const int g    = lane >> 2;
    const int tig  = lane & 3;
    const int mat  = lane >> 3;
    const int mr   = lane & 7;

    const size_t base = (size_t)(b * H_NUM + h) * S_LEN * HD;
    const __half* Qb = g_Q + base;
    const __half* Kb = g_K + base;
    const __half* Vb = g_V + base;

    // ---- stage Q (128 rows) into [0,18432), consume into registers ----
#pragma unroll
    for (int p = 0; p < 8; p++) {
        int idx = tid + 128 * p;       // 0..1023
        int row = idx >> 3;
        int ch  = idx & 7;
        int qi = qt * 128 + row;
        int sz = (qi < S_LEN) ? 16 : 0;
        const char* src = (const char*)(Qb + (size_t)min(qi, S_LEN - 1) * HD) + ch * 16;
        cp16(sbase + (uint32_t)row * APITCH + ch * 16, src, sz);
    }
    cp_commit();
    cp_wait0();
    __syncthreads();

    uint32_t qa[2][4][4];
#pragma unroll
    for (int u = 0; u < 2; u++)
#pragma unroll
        for (int ks = 0; ks < 4; ks++) {
            uint32_t addr = sbase
                + (uint32_t)(w * 32 + u * 16 + (mat & 1) * 8 + mr) * APITCH
                + ks * 32 + (mat >> 1) * 16;
            ldm_x4(qa[u][ks][0], qa[u][ks][1], qa[u][ks][2], qa[u][ks][3], addr);
        }
    __syncthreads();   // Q reads done; region reusable as K stages

    auto issue_kv = [&](int kt, int bb) {
#pragma unroll
        for (int p = 0; p < 4; p++) {
            int idx = tid + 128 * p;
            int row = idx >> 3;
            int ch  = idx & 7;
            int ki = kt * 64 + row;
            int sz = (ki < S_LEN) ? 16 : 0;
            size_t roff = (size_t)min(ki, S_LEN - 1) * HD;
            cp16(sbase + bb * KVSTG + (uint32_t)row * APITCH + ch * 16,
                 (const char*)(Kb + roff) + ch * 16, sz);
            cp16(sbase + 18432 + bb * KVSTG + (uint32_t)row * APITCH + ch * 16,
                 (const char*)(Vb + roff) + ch * 16, sz);
        }
    };

    issue_kv(0, 0);
    cp_commit();

    // constant ones-column B fragment (B[k][0]=1 for all k): n = lane>>2 == 0
    const uint32_t bone = (g == 0) ? 0x3C003C00u : 0u;

    float oc[2][8][4];
    float lc[2][4];
#pragma unroll
    for (int u = 0; u < 2; u++) {
#pragma unroll
        for (int nf = 0; nf < 8; nf++)
#pragma unroll
            for (int cc = 0; cc < 4; cc++) oc[u][nf][cc] = 0.0f;
#pragma unroll
        for (int cc = 0; cc < 4; cc++) lc[u][cc] = 0.0f;
    }
    float m1[2] = {NEG_BIG, NEG_BIG}, m2[2] = {NEG_BIG, NEG_BIG};

    const int ntiles = (S_LEN + 63) / 64;    // 22
    for (int kt = 0; kt < ntiles; kt++) {
        if (kt + 1 < ntiles) { issue_kv(kt + 1, (kt + 1) & 1); cp_commit(); cp_wait1(); }
        else cp_wait0();
        __syncthreads();

        const int rem = min(64, S_LEN - kt * 64);
        const uint32_t sbK = sbase + (kt & 1) * KVSTG;
        const uint32_t sbV = sbase + 18432 + (kt & 1) * KVSTG;

        // ---- S = Q K^T (log2-domain) ----
        float sc[2][8][4];
#pragma unroll
        for (int u = 0; u < 2; u++)
#pragma unroll
            for (int nf = 0; nf < 8; nf++)
#pragma unroll
                for (int cc = 0; cc < 4; cc++) sc[u][nf][cc] = 0.0f;

#pragma unroll
        for (int ks = 0; ks < 4; ks++) {
#pragma unroll
            for (int nf2 = 0; nf2 < 4; nf2++) {
                uint32_t r0, rr1, rr2, rr3;
                uint32_t addr = sbK + (uint32_t)(nf2 * 16 + (mat >> 1) * 8 + mr) * APITCH
                              + ks * 32 + (mat & 1) * 16;
                ldm_x4(r0, rr1, rr2, rr3, addr);
#pragma unroll
                for (int u = 0; u < 2; u++) {
                    mma16h(sc[u][2 * nf2],     qa[u][ks], r0,  rr1);
                    mma16h(sc[u][2 * nf2 + 1], qa[u][ks], rr2, rr3);
                }
            }
        }

#pragma unroll
        for (int u = 0; u < 2; u++) {
            // mask tail columns
            if (rem < 64) {
#pragma unroll
                for (int nf = 0; nf < 8; nf++) {
                    int col = nf * 8 + 2 * tig;
                    if (col     >= rem) { sc[u][nf][0] = NEG_BIG; sc[u][nf][2] = NEG_BIG; }
                    if (col + 1 >= rem) { sc[u][nf][1] = NEG_BIG; sc[u][nf][3] = NEG_BIG; }
                }
            }

            float rmax1 = NEG_BIG, rmax2 = NEG_BIG;
#pragma unroll
            for (int nf = 0; nf < 8; nf++) {
                rmax1 = fmaxf(rmax1, fmaxf(sc[u][nf][0], sc[u][nf][1]));
                rmax2 = fmaxf(rmax2, fmaxf(sc[u][nf][2], sc[u][nf][3]));
            }
            rmax1 = fmaxf(rmax1, __shfl_xor_sync(0xffffffffu, rmax1, 1));
            rmax1 = fmaxf(rmax1, __shfl_xor_sync(0xffffffffu, rmax1, 2));
            rmax2 = fmaxf(rmax2, __shfl_xor_sync(0xffffffffu, rmax2, 1));
            rmax2 = fmaxf(rmax2, __shfl_xor_sync(0xffffffffu, rmax2, 2));

            float nm1 = fmaxf(m1[u], rmax1);
            float nm2 = fmaxf(m2[u], rmax2);

            // rescale only when a max actually moved (warp-uniform vote)
            bool moved = (nm1 > m1[u]) || (nm2 > m2[u]);
            if (__any_sync(0xffffffffu, moved)) {
                float corr1 = ex2(m1[u] - nm1);
                float corr2 = ex2(m2[u] - nm2);
#pragma unroll
                for (int nf = 0; nf < 8; nf++) {
                    oc[u][nf][0] *= corr1; oc[u][nf][1] *= corr1;
                    oc[u][nf][2] *= corr2; oc[u][nf][3] *= corr2;
                }
                lc[u][0] *= corr1; lc[u][1] *= corr1;
                lc[u][2] *= corr2; lc[u][3] *= corr2;
                m1[u] = nm1; m2[u] = nm2;
            }

#pragma unroll
            for (int nf = 0; nf < 8; nf++) {
                sc[u][nf][0] = ex2(sc[u][nf][0] - m1[u]);
                sc[u][nf][1] = ex2(sc[u][nf][1] - m1[u]);
                sc[u][nf][2] = ex2(sc[u][nf][2] - m2[u]);
                sc[u][nf][3] = ex2(sc[u][nf][3] - m2[u]);
            }
        }

        // ---- O += P V ; l += P 1 (tensor-core row sums) ----
#pragma unroll
        for (int ks = 0; ks < 4; ks++) {
            uint32_t pa[2][4];
#pragma unroll
            for (int u = 0; u < 2; u++) {
                pa[u][0] = h2pack(sc[u][2*ks][0],   sc[u][2*ks][1]);
                pa[u][1] = h2pack(sc[u][2*ks][2],   sc[u][2*ks][3]);
                pa[u][2] = h2pack(sc[u][2*ks+1][0], sc[u][2*ks+1][1]);
                pa[u][3] = h2pack(sc[u][2*ks+1][2], sc[u][2*ks+1][3]);
                mma16h(lc[u], pa[u], bone, bone);
            }
#pragma unroll
            for (int nf2 = 0; nf2 < 4; nf2++) {
                uint32_t r0, rr1, rr2, rr3;
                uint32_t addr = sbV + (uint32_t)(ks * 16 + (mat & 1) * 8 + mr) * APITCH
                              + nf2 * 32 + (mat >> 1) * 16;
                ldm_x4t(r0, rr1, rr2, rr3, addr);
#pragma unroll
                for (int u = 0; u < 2; u++) {
                    mma16h(oc[u][2 * nf2],     pa[u], r0,  rr1);
                    mma16h(oc[u][2 * nf2 + 1], pa[u], rr2, rr3);
                }
            }
        }
        __syncthreads();
    }

    // ---- normalize + write [B,S,H*HD] fp32 ----
#pragma unroll
    for (int u = 0; u < 2; u++) {
        const int r1 = qt * 128 + w * 32 + u * 16 + g;
        const int r2 = r1 + 8;
        // row sums live in lane (g*4) [tig==0]: c0 = row g, c2 = row g+8
        float l1 = __shfl_sync(0xffffffffu, lc[u][0], lane & ~3);
        float l2 = __shfl_sync(0xffffffffu, lc[u][2], lane & ~3);
        float inv1 = 1.0f / l1;
        float inv2 = 1.0f / l2;
#pragma unroll
        for (int nf = 0; nf < 8; nf++) {
            int d = nf * 8 + 2 * tig;
            if (r1 < S_LEN) {
                float2 v; v.x = oc[u][nf][0] * inv1; v.y = oc[u][nf][1] * inv1;
                *reinterpret_cast<float2*>(
                    out + (size_t)(b * S_LEN + r1) * D_MODEL + h * HD + d) = v;
            }
            if (r2 < S_LEN) {
                float2 v; v.x = oc[u][nf][2] * inv2; v.y = oc[u][nf][3] * inv2;
                *reinterpret_cast<float2*>(
                    out + (size_t)(b * S_LEN + r2) * D_MODEL + h * HD + d) = v;
            }
        }
    }
}

// ---------------------------------------------------------------------------
extern "C" void kernel_launch(void* const* d_in, const int* in_sizes, int n_in,
                              void* d_out, int out_size)
{
    const float* X  = (const float*)d_in[0];
    const float* Wq = (const float*)d_in[1];
    const float* bq = (const float*)d_in[2];
    const float* Wk = (const float*)d_in[3];
    const float* bk = (const float*)d_in[4];
    const float* Wv = (const float*)d_in[5];
    const float* bv = (const float*)d_in[6];
    float* out = (float*)d_out;

    static int once = 0;
    if (!once) {
        cudaFuncSetAttribute(qkv_fp16, cudaFuncAttributeMaxDynamicSharedMemorySize, GEMM_SMEM);
        once = 1;
    }

    const int n4x = M_TOT * D_MODEL / 4;
    const int n4w = D_MODEL * D_MODEL / 4;
    conv_x<<<(n4x + 255) / 256, 256>>>(X, n4x);
    dim3 gw((n4w + 255) / 256, 3);
    conv_w3<<<gw, 256>>>(Wq, Wk, Wv, n4w);

    dim3 g1(D_MODEL / 128, (M_TOT + 127) / 128, 3);
    qkv_fp16<<<g1, 512, GEMM_SMEM>>>(bq, bk, bv);

    dim3 g2((S_LEN + 127) / 128, H_NUM, B_SZ);
    attn_fp16<<<g2, 128>>>(out);
}

// round 9
// speedup vs baseline: 7.4214x; 1.0447x over previous
#include <cuda_runtime.h>
#include <cuda_fp16.h>
#include <stdint.h>

#define S_LEN   1370
#define B_SZ    8
#define D_MODEL 1024
#define H_NUM   16
#define HD      64
#define M_TOT   (B_SZ * S_LEN)   // 10960
#define LOG2E   1.4426950408889634f

// pre-converted GEMM operands (single fp16)
__device__ __half gX[(size_t)M_TOT * D_MODEL];
__device__ __half gW[3ull * D_MODEL * D_MODEL];
// projected Q/K/V in fp16, [B,H,S,HD]; Q pre-scaled by 0.125*log2(e)
__device__ __half g_Q[(size_t)M_TOT * D_MODEL];
__device__ __half g_K[(size_t)M_TOT * D_MODEL];
__device__ __half g_V[(size_t)M_TOT * D_MODEL];

// ---------------------------------------------------------------------------
// helpers
// ---------------------------------------------------------------------------
__device__ __forceinline__ uint32_t smem_u32(const void* p) {
    return (uint32_t)__cvta_generic_to_shared(p);
}
__device__ __forceinline__ void cp16(uint32_t dst, const void* src, int sz) {
    asm volatile("cp.async.cg.shared.global [%0], [%1], 16, %2;"
                 :: "r"(dst), "l"(src), "r"(sz) : "memory");
}
__device__ __forceinline__ void cp_commit() {
    asm volatile("cp.async.commit_group;" ::: "memory");
}
__device__ __forceinline__ void cp_wait1() {
    asm volatile("cp.async.wait_group 1;" ::: "memory");
}
__device__ __forceinline__ void cp_wait0() {
    asm volatile("cp.async.wait_group 0;" ::: "memory");
}
__device__ __forceinline__ void ldm_x4(uint32_t& r0, uint32_t& r1, uint32_t& r2, uint32_t& r3,
                                       uint32_t addr) {
    asm volatile("ldmatrix.sync.aligned.m8n8.x4.shared.b16 {%0,%1,%2,%3}, [%4];"
                 : "=r"(r0), "=r"(r1), "=r"(r2), "=r"(r3) : "r"(addr));
}
__device__ __forceinline__ void ldm_x4t(uint32_t& r0, uint32_t& r1, uint32_t& r2, uint32_t& r3,
                                        uint32_t addr) {
    asm volatile("ldmatrix.sync.aligned.m8n8.x4.trans.shared.b16 {%0,%1,%2,%3}, [%4];"
                 : "=r"(r0), "=r"(r1), "=r"(r2), "=r"(r3) : "r"(addr));
}
__device__ __forceinline__ void mma16h(float* c, const uint32_t* a, uint32_t b0, uint32_t b1) {
    asm volatile(
        "mma.sync.aligned.m16n8k16.row.col.f32.f16.f16.f32 "
        "{%0,%1,%2,%3},{%4,%5,%6,%7},{%8,%9},{%0,%1,%2,%3};\n"
        : "+f"(c[0]), "+f"(c[1]), "+f"(c[2]), "+f"(c[3])
        : "r"(a[0]), "r"(a[1]), "r"(a[2]), "r"(a[3]), "r"(b0), "r"(b1));
}
__device__ __forceinline__ uint32_t h2pack(float lo, float hi) {
    __half2 h = __floats2half2_rn(lo, hi);
    return *reinterpret_cast<uint32_t*>(&h);
}
__device__ __forceinline__ float ex2(float x) {
    float y;
    asm("ex2.approx.f32 %0, %1;" : "=f"(y) : "f"(x));
    return y;
}

// ---------------------------------------------------------------------------
// Pre-convert fp32 -> fp16, single fused launch.
// i < n4x -> X; else plane = (i-n4x)>>18 (n4w = 2^18), idx = & mask.
// ---------------------------------------------------------------------------
#define N4X (M_TOT * D_MODEL / 4)          // 2,805,760
#define N4W (D_MODEL * D_MODEL / 4)        // 262,144 = 2^18

__global__ void conv_all(const float* __restrict__ X,
                         const float* __restrict__ w0,
                         const float* __restrict__ w1,
                         const float* __restrict__ w2)
{
    int i = blockIdx.x * 256 + threadIdx.x;
    if (i >= N4X + 3 * N4W) return;
    const float* src;
    __half* dst;
    int idx;
    if (i < N4X) {
        src = X; dst = gX; idx = i;
    } else {
        int j = i - N4X;
        int plane = j >> 18;
        idx = j & (N4W - 1);
        src = (plane == 0) ? w0 : (plane == 1) ? w1 : w2;
        dst = gW + (size_t)plane * D_MODEL * D_MODEL;
    }
    float4 v = reinterpret_cast<const float4*>(src)[idx];
    uint32_t h0 = __half_as_ushort(__float2half_rn(v.x)) |
                  ((uint32_t)__half_as_ushort(__float2half_rn(v.y)) << 16);
    uint32_t h1 = __half_as_ushort(__float2half_rn(v.z)) |
                  ((uint32_t)__half_as_ushort(__float2half_rn(v.w)) << 16);
    reinterpret_cast<uint2*>(dst)[idx] = make_uint2(h0, h1);
}

// ---------------------------------------------------------------------------
// QKV projection: y = X @ W^T + b (single-pass fp16 m16n8k16).
// Block 128x128, 256 threads (8 warps, 2x4), warp tile 64x32, K slab 32,
// cp.async double-buffered, 2 CTAs/SM. Output fp16 into [B,H,S,HD].
// ---------------------------------------------------------------------------
#define PITCH  80
#define TILEB  10240                 // one 128x32 fp16 tile (pitch 80)
#define BUFSZ  (2 * TILEB)           // A, B
#define GEMM_SMEM (2 * BUFSZ)        // 40960

__global__ __launch_bounds__(256, 2) void qkv_fp16(
    const float* __restrict__ bq, const float* __restrict__ bk,
    const float* __restrict__ bv)
{
    extern __shared__ char smem[];
    const uint32_t sb = smem_u32(smem);

    const int z = blockIdx.z;
    const float* bias = (z == 0) ? bq : (z == 1) ? bk : bv;
    __half* out = (z == 0) ? g_Q : (z == 1) ? g_K : g_V;
    const float scale = (z == 0) ? 0.125f * LOG2E : 1.0f;
    const __half* W = gW + (size_t)z * D_MODEL * D_MODEL;

    const int tid  = threadIdx.x;
    const int lane = tid & 31;
    const int wid  = tid >> 5;
    const int wm   = wid >> 2;        // 0..1 : 64-row strip
    const int wn   = wid & 3;         // 0..3 : 32-col strip
    const int g    = lane >> 2;
    const int tig  = lane & 3;
    const int mat  = lane >> 3;
    const int mr   = lane & 7;

    const int m0 = blockIdx.y * 128;
    const int n0 = blockIdx.x * 128;

    // staging: 256 threads, each 2x16B chunks per tile per slab
    const int srow = tid >> 1;        // 0..127
    const int sch  = (tid & 1) * 32;  // byte offset 0 or 32

    const int gm = m0 + srow;
    const int szA = (gm < M_TOT) ? 16 : 0;
    const size_t arow_off = (size_t)min(gm, M_TOT - 1) * D_MODEL;
    const size_t brow_off = (size_t)(n0 + srow) * D_MODEL;

    float c[4][4][4];
#pragma unroll
    for (int mf = 0; mf < 4; mf++)
#pragma unroll
        for (int nf = 0; nf < 4; nf++)
#pragma unroll
            for (int cc = 0; cc < 4; cc++) c[mf][nf][cc] = 0.0f;

    auto issue = [&](int s, int buf) {
        const int k0 = s * 32;
        uint32_t d0 = sb + buf * BUFSZ + (uint32_t)srow * PITCH + sch;
        const char* sA = (const char*)(gX + arow_off + k0) + sch;
        const char* sB = (const char*)(W + brow_off + k0) + sch;
        cp16(d0,              sA,      szA);
        cp16(d0 + 16,         sA + 16, szA);
        cp16(d0 + TILEB,      sB,      16);
        cp16(d0 + TILEB + 16, sB + 16, 16);
    };

    issue(0, 0);
    cp_commit();

    for (int s = 0; s < 32; s++) {
        if (s + 1 < 32) { issue(s + 1, (s + 1) & 1); cp_commit(); cp_wait1(); }
        else cp_wait0();
        __syncthreads();

        const uint32_t base = sb + (s & 1) * BUFSZ;
#pragma unroll
        for (int t = 0; t < 2; t++) {
            uint32_t af[4][4];
#pragma unroll
            for (int mf = 0; mf < 4; mf++) {
                int arow = wm * 64 + mf * 16 + (mat & 1) * 8 + mr;
                uint32_t koff = t * 32 + (mat >> 1) * 16;
                uint32_t addr = base + (uint32_t)arow * PITCH + koff;
                ldm_x4(af[mf][0], af[mf][1], af[mf][2], af[mf][3], addr);
            }
            uint32_t bf[4][2];
#pragma unroll
            for (int nfp = 0; nfp < 2; nfp++) {
                int nrow = wn * 32 + nfp * 16 + (mat >> 1) * 8 + mr;
                uint32_t koff = t * 32 + (mat & 1) * 16;
                uint32_t addr = base + (uint32_t)nrow * PITCH + koff;
                ldm_x4(bf[2*nfp][0], bf[2*nfp][1], bf[2*nfp+1][0], bf[2*nfp+1][1],
                       addr + TILEB);
            }
#pragma unroll
            for (int mf = 0; mf < 4; mf++)
#pragma unroll
                for (int nf = 0; nf < 4; nf++)
                    mma16h(c[mf][nf], af[mf], bf[nf][0], bf[nf][1]);
        }
        __syncthreads();
    }

    // epilogue: bias + scale, fp16 scatter into [B,H,S,HD]
#pragma unroll
    for (int mf = 0; mf < 4; mf++) {
#pragma unroll
        for (int nf = 0; nf < 4; nf++) {
            int n = n0 + wn * 32 + nf * 8 + 2 * tig;
            int h = n >> 6, d = n & 63;
            float bv0 = __ldg(bias + n), bv1 = __ldg(bias + n + 1);
#pragma unroll
            for (int half = 0; half < 2; half++) {
                int m = m0 + wm * 64 + mf * 16 + g + half * 8;
                if (m < M_TOT) {
                    int bb = m / S_LEN;
                    int ss = m - bb * S_LEN;
                    __half2 hv = __floats2half2_rn(
                        (c[mf][nf][half * 2 + 0] + bv0) * scale,
                        (c[mf][nf][half * 2 + 1] + bv1) * scale);
                    *reinterpret_cast<__half2*>(
                        out + (((size_t)(bb * H_NUM + h) * S_LEN + ss) * HD + d)) = hv;
                }
            }
        }
    }
}

// ---------------------------------------------------------------------------
// Flash attention, fp16 m16n8k16. CTA = 128 queries, 4 warps x two 16-row
// query tiles. Row-sum l via tensor core (ones-column B fragment).
// Rescale skipped via warp vote. Q staged through the K buffer region.
// ---------------------------------------------------------------------------
#define NEG_BIG (-1e30f)
#define APITCH  144                   // bytes per smem row (64 fp16 + 8 pad)
#define KVSTG   9216                  // one 64-row K or V stage
#define ATTN_SMEM 36864

__global__ __launch_bounds__(128) void attn_fp16(float* __restrict__ out)
{
    __shared__ char asmem[ATTN_SMEM];
    const uint32_t sbase = smem_u32(asmem);

    const int h  = blockIdx.y;
    const int b  = blockIdx.z;
    const int qt = blockIdx.x;
    const int tid  = threadIdx.x;
    const int lane = tid & 31;
    const int w    = tid >> 5;
    const int g    = lane >> 2;
    const int tig  = lane & 3;
    const int mat  = lane >> 3;
    const int mr   = lane & 7;

    const size_t base = (size_t)(b * H_NUM + h) * S_LEN * HD;
    const __half* Qb = g_Q + base;
    const __half* Kb = g_K + base;
    const __half* Vb = g_V + base;

    // ---- stage Q (128 rows) into [0,18432), consume into registers ----
#pragma unroll
    for (int p = 0; p < 8; p++) {
        int idx = tid + 128 * p;       // 0..1023
        int row = idx >> 3;
        int ch  = idx & 7;
        int qi = qt * 128 + row;
        int sz = (qi < S_LEN) ? 16 : 0;
        const char* src = (const char*)(Qb + (size_t)min(qi, S_LEN - 1) * HD) + ch * 16;
        cp16(sbase + (uint32_t)row * APITCH + ch * 16, src, sz);
    }
    cp_commit();
    cp_wait0();
    __syncthreads();

    uint32_t qa[2][4][4];
#pragma unroll
    for (int u = 0; u < 2; u++)
#pragma unroll
        for (int ks = 0; ks < 4; ks++) {
            uint32_t addr = sbase
                + (uint32_t)(w * 32 + u * 16 + (mat & 1) * 8 + mr) * APITCH
                + ks * 32 + (mat >> 1) * 16;
            ldm_x4(qa[u][ks][0], qa[u][ks][1], qa[u][ks][2], qa[u][ks][3], addr);
        }
    __syncthreads();   // Q reads done; region reusable as K stages

    auto issue_kv = [&](int kt, int bb) {
#pragma unroll
        for (int p = 0; p < 4; p++) {
            int idx = tid + 128 * p;
            int row = idx >> 3;
            int ch  = idx & 7;
            int ki = kt * 64 + row;
            int sz = (ki < S_LEN) ? 16 : 0;
            size_t roff = (size_t)min(ki, S_LEN - 1) * HD;
            cp16(sbase + bb * KVSTG + (uint32_t)row * APITCH + ch * 16,
                 (const char*)(Kb + roff) + ch * 16, sz);
            cp16(sbase + 18432 + bb * KVSTG + (uint32_t)row * APITCH + ch * 16,
                 (const char*)(Vb + roff) + ch * 16, sz);
        }
    };

    issue_kv(0, 0);
    cp_commit();

    // constant ones-column B fragment (B[k][0]=1 for all k)
    const uint32_t bone = (g == 0) ? 0x3C003C00u : 0u;

    float oc[2][8][4];
    float lc[2][4];
#pragma unroll
    for (int u = 0; u < 2; u++) {
#pragma unroll
        for (int nf = 0; nf < 8; nf++)
#pragma unroll
            for (int cc = 0; cc < 4; cc++) oc[u][nf][cc] = 0.0f;
#pragma unroll
        for (int cc = 0; cc < 4; cc++) lc[u][cc] = 0.0f;
    }
    float m1[2] = {NEG_BIG, NEG_BIG}, m2[2] = {NEG_BIG, NEG_BIG};

    const int ntiles = (S_LEN + 63) / 64;    // 22
    for (int kt = 0; kt < ntiles; kt++) {
        if (kt + 1 < ntiles) { issue_kv(kt + 1, (kt + 1) & 1); cp_commit(); cp_wait1(); }
        else cp_wait0();
        __syncthreads();

        const int rem = min(64, S_LEN - kt * 64);
        const uint32_t sbK = sbase + (kt & 1) * KVSTG;
        const uint32_t sbV = sbase + 18432 + (kt & 1) * KVSTG;

        // ---- S = Q K^T (log2-domain) ----
        float sc[2][8][4];
#pragma unroll
        for (int u = 0; u < 2; u++)
#pragma unroll
            for (int nf = 0; nf < 8; nf++)
#pragma unroll
                for (int cc = 0; cc < 4; cc++) sc[u][nf][cc] = 0.0f;

#pragma unroll
        for (int ks = 0; ks < 4; ks++) {
#pragma unroll
            for (int nf2 = 0; nf2 < 4; nf2++) {
                uint32_t r0, rr1, rr2, rr3;
                uint32_t addr = sbK + (uint32_t)(nf2 * 16 + (mat >> 1) * 8 + mr) * APITCH
                              + ks * 32 + (mat & 1) * 16;
                ldm_x4(r0, rr1, rr2, rr3, addr);
#pragma unroll
                for (int u = 0; u < 2; u++) {
                    mma16h(sc[u][2 * nf2],     qa[u][ks], r0,  rr1);
                    mma16h(sc[u][2 * nf2 + 1], qa[u][ks], rr2, rr3);
                }
            }
        }

#pragma unroll
        for (int u = 0; u < 2; u++) {
            if (rem < 64) {
#pragma unroll
                for (int nf = 0; nf < 8; nf++) {
                    int col = nf * 8 + 2 * tig;
                    if (col     >= rem) { sc[u][nf][0] = NEG_BIG; sc[u][nf][2] = NEG_BIG; }
                    if (col + 1 >= rem) { sc[u][nf][1] = NEG_BIG; sc[u][nf][3] = NEG_BIG; }
                }
            }

            float rmax1 = NEG_BIG, rmax2 = NEG_BIG;
#pragma unroll
            for (int nf = 0; nf < 8; nf++) {
                rmax1 = fmaxf(rmax1, fmaxf(sc[u][nf][0], sc[u][nf][1]));
                rmax2 = fmaxf(rmax2, fmaxf(sc[u][nf][2], sc[u][nf][3]));
            }
            rmax1 = fmaxf(rmax1, __shfl_xor_sync(0xffffffffu, rmax1, 1));
            rmax1 = fmaxf(rmax1, __shfl_xor_sync(0xffffffffu, rmax1, 2));
            rmax2 = fmaxf(rmax2, __shfl_xor_sync(0xffffffffu, rmax2, 1));
            rmax2 = fmaxf(rmax2, __shfl_xor_sync(0xffffffffu, rmax2, 2));

            float nm1 = fmaxf(m1[u], rmax1);
            float nm2 = fmaxf(m2[u], rmax2);

            bool moved = (nm1 > m1[u]) || (nm2 > m2[u]);
            if (__any_sync(0xffffffffu, moved)) {
                float corr1 = ex2(m1[u] - nm1);
                float corr2 = ex2(m2[u] - nm2);
#pragma unroll
                for (int nf = 0; nf < 8; nf++) {
                    oc[u][nf][0] *= corr1; oc[u][nf][1] *= corr1;
                    oc[u][nf][2] *= corr2; oc[u][nf][3] *= corr2;
                }
                lc[u][0] *= corr1; lc[u][1] *= corr1;
                lc[u][2] *= corr2; lc[u][3] *= corr2;
                m1[u] = nm1; m2[u] = nm2;
            }

#pragma unroll
            for (int nf = 0; nf < 8; nf++) {
                sc[u][nf][0] = ex2(sc[u][nf][0] - m1[u]);
                sc[u][nf][1] = ex2(sc[u][nf][1] - m1[u]);
                sc[u][nf][2] = ex2(sc[u][nf][2] - m2[u]);
                sc[u][nf][3] = ex2(sc[u][nf][3] - m2[u]);
            }
        }

        // ---- O += P V ; l += P 1 ----
#pragma unroll
        for (int ks = 0; ks < 4; ks++) {
            uint32_t pa[2][4];
#pragma unroll
            for (int u = 0; u < 2; u++) {
                pa[u][0] = h2pack(sc[u][2*ks][0],   sc[u][2*ks][1]);
                pa[u][1] = h2pack(sc[u][2*ks][2],   sc[u][2*ks][3]);
                pa[u][2] = h2pack(sc[u][2*ks+1][0], sc[u][2*ks+1][1]);
                pa[u][3] = h2pack(sc[u][2*ks+1][2], sc[u][2*ks+1][3]);
                mma16h(lc[u], pa[u], bone, bone);
            }
#pragma unroll
            for (int nf2 = 0; nf2 < 4; nf2++) {
                uint32_t r0, rr1, rr2, rr3;
                uint32_t addr = sbV + (uint32_t)(ks * 16 + (mat & 1) * 8 + mr) * APITCH
                              + nf2 * 32 + (mat >> 1) * 16;
                ldm_x4t(r0, rr1, rr2, rr3, addr);
#pragma unroll
                for (int u = 0; u < 2; u++) {
                    mma16h(oc[u][2 * nf2],     pa[u], r0,  rr1);
                    mma16h(oc[u][2 * nf2 + 1], pa[u], rr2, rr3);
                }
            }
        }
        __syncthreads();
    }

    // ---- normalize + write [B,S,H*HD] fp32 ----
#pragma unroll
    for (int u = 0; u < 2; u++) {
        const int r1 = qt * 128 + w * 32 + u * 16 + g;
        const int r2 = r1 + 8;
        float l1 = __shfl_sync(0xffffffffu, lc[u][0], lane & ~3);
        float l2 = __shfl_sync(0xffffffffu, lc[u][2], lane & ~3);
        float inv1 = 1.0f / l1;
        float inv2 = 1.0f / l2;
#pragma unroll
        for (int nf = 0; nf < 8; nf++) {
            int d = nf * 8 + 2 * tig;
            if (r1 < S_LEN) {
                float2 v; v.x = oc[u][nf][0] * inv1; v.y = oc[u][nf][1] * inv1;
                *reinterpret_cast<float2*>(
                    out + (size_t)(b * S_LEN + r1) * D_MODEL + h * HD + d) = v;
            }
            if (r2 < S_LEN) {
                float2 v; v.x = oc[u][nf][2] * inv2; v.y = oc[u][nf][3] * inv2;
                *reinterpret_cast<float2*>(
                    out + (size_t)(b * S_LEN + r2) * D_MODEL + h * HD + d) = v;
            }
        }
    }
}

// ---------------------------------------------------------------------------
extern "C" void kernel_launch(void* const* d_in, const int* in_sizes, int n_in,
                              void* d_out, int out_size)
{
    const float* X  = (const float*)d_in[0];
    const float* Wq = (const float*)d_in[1];
    const float* bq = (const float*)d_in[2];
    const float* Wk = (const float*)d_in[3];
    const float* bk = (const float*)d_in[4];
    const float* Wv = (const float*)d_in[5];
    const float* bv = (const float*)d_in[6];
    float* out = (float*)d_out;

    static int once = 0;
    if (!once) {
        cudaFuncSetAttribute(qkv_fp16, cudaFuncAttributeMaxDynamicSharedMemorySize, GEMM_SMEM);
        once = 1;
    }

    const int ntot = N4X + 3 * N4W;
    conv_all<<<(ntot + 255) / 256, 256>>>(X, Wq, Wk, Wv);

    dim3 g1(D_MODEL / 128, (M_TOT + 127) / 128, 3);
    qkv_fp16<<<g1, 256, GEMM_SMEM>>>(bq, bk, bv);

    dim3 g2((S_LEN + 127) / 128, H_NUM, B_SZ);
    attn_fp16<<<g2, 128>>>(out);
}

// round 10
// speedup vs baseline: 7.5931x; 1.0231x over previous
#include <cuda_runtime.h>
#include <cuda_fp16.h>
#include <stdint.h>

#define S_LEN   1370
#define B_SZ    8
#define D_MODEL 1024
#define H_NUM   16
#define HD      64
#define M_TOT   (B_SZ * S_LEN)   // 10960
#define LOG2E   1.4426950408889634f

// pre-converted GEMM operands (single fp16)
__device__ __half gX[(size_t)M_TOT * D_MODEL];
__device__ __half gW[3ull * D_MODEL * D_MODEL];
// projected Q/K/V in fp16, [B,H,S,HD]; Q pre-scaled by 0.125*log2(e)
__device__ __half g_Q[(size_t)M_TOT * D_MODEL];
__device__ __half g_K[(size_t)M_TOT * D_MODEL];
__device__ __half g_V[(size_t)M_TOT * D_MODEL];

// ---------------------------------------------------------------------------
// helpers
// ---------------------------------------------------------------------------
__device__ __forceinline__ uint32_t smem_u32(const void* p) {
    return (uint32_t)__cvta_generic_to_shared(p);
}
__device__ __forceinline__ void cp16(uint32_t dst, const void* src, int sz) {
    asm volatile("cp.async.cg.shared.global [%0], [%1], 16, %2;"
                 :: "r"(dst), "l"(src), "r"(sz) : "memory");
}
__device__ __forceinline__ void cp_commit() {
    asm volatile("cp.async.commit_group;" ::: "memory");
}
__device__ __forceinline__ void cp_wait2() {
    asm volatile("cp.async.wait_group 2;" ::: "memory");
}
__device__ __forceinline__ void cp_wait1() {
    asm volatile("cp.async.wait_group 1;" ::: "memory");
}
__device__ __forceinline__ void cp_wait0() {
    asm volatile("cp.async.wait_group 0;" ::: "memory");
}
__device__ __forceinline__ void ldm_x4(uint32_t& r0, uint32_t& r1, uint32_t& r2, uint32_t& r3,
                                       uint32_t addr) {
    asm volatile("ldmatrix.sync.aligned.m8n8.x4.shared.b16 {%0,%1,%2,%3}, [%4];"
                 : "=r"(r0), "=r"(r1), "=r"(r2), "=r"(r3) : "r"(addr));
}
__device__ __forceinline__ void ldm_x4t(uint32_t& r0, uint32_t& r1, uint32_t& r2, uint32_t& r3,
                                        uint32_t addr) {
    asm volatile("ldmatrix.sync.aligned.m8n8.x4.trans.shared.b16 {%0,%1,%2,%3}, [%4];"
                 : "=r"(r0), "=r"(r1), "=r"(r2), "=r"(r3) : "r"(addr));
}
__device__ __forceinline__ void mma16h(float* c, const uint32_t* a, uint32_t b0, uint32_t b1) {
    asm volatile(
        "mma.sync.aligned.m16n8k16.row.col.f32.f16.f16.f32 "
        "{%0,%1,%2,%3},{%4,%5,%6,%7},{%8,%9},{%0,%1,%2,%3};\n"
        : "+f"(c[0]), "+f"(c[1]), "+f"(c[2]), "+f"(c[3])
        : "r"(a[0]), "r"(a[1]), "r"(a[2]), "r"(a[3]), "r"(b0), "r"(b1));
}
__device__ __forceinline__ uint32_t h2pack(float lo, float hi) {
    __half2 h = __floats2half2_rn(lo, hi);
    return *reinterpret_cast<uint32_t*>(&h);
}
__device__ __forceinline__ float ex2(float x) {
    float y;
    asm("ex2.approx.f32 %0, %1;" : "=f"(y) : "f"(x));
    return y;
}

// ---------------------------------------------------------------------------
// Pre-convert fp32 -> fp16, single fused launch.
// ---------------------------------------------------------------------------
#define N4X (M_TOT * D_MODEL / 4)          // 2,805,760
#define N4W (D_MODEL * D_MODEL / 4)        // 262,144 = 2^18

__global__ void conv_all(const float* __restrict__ X,
                         const float* __restrict__ w0,
                         const float* __restrict__ w1,
                         const float* __restrict__ w2)
{
    int i = blockIdx.x * 256 + threadIdx.x;
    if (i >= N4X + 3 * N4W) return;
    const float* src;
    __half* dst;
    int idx;
    if (i < N4X) {
        src = X; dst = gX; idx = i;
    } else {
        int j = i - N4X;
        int plane = j >> 18;
        idx = j & (N4W - 1);
        src = (plane == 0) ? w0 : (plane == 1) ? w1 : w2;
        dst = gW + (size_t)plane * D_MODEL * D_MODEL;
    }
    float4 v = reinterpret_cast<const float4*>(src)[idx];
    uint32_t h0 = __half_as_ushort(__float2half_rn(v.x)) |
                  ((uint32_t)__half_as_ushort(__float2half_rn(v.y)) << 16);
    uint32_t h1 = __half_as_ushort(__float2half_rn(v.z)) |
                  ((uint32_t)__half_as_ushort(__float2half_rn(v.w)) << 16);
    reinterpret_cast<uint2*>(dst)[idx] = make_uint2(h0, h1);
}

// ---------------------------------------------------------------------------
// QKV projection: y = X @ W^T + b (single-pass fp16 m16n8k16).
// Block 128x128, 256 threads (8 warps, 2x4), warp tile 64x32, K slab 32,
// cp.async 3-stage pipelined, 2 CTAs/SM. Output fp16 into [B,H,S,HD].
// ---------------------------------------------------------------------------
#define PITCH  80
#define TILEB  10240                 // one 128x32 fp16 tile (pitch 80)
#define BUFSZ  (2 * TILEB)           // A, B
#define NSTG   3
#define GEMM_SMEM (NSTG * BUFSZ)     // 61440

__global__ __launch_bounds__(256, 2) void qkv_fp16(
    const float* __restrict__ bq, const float* __restrict__ bk,
    const float* __restrict__ bv)
{
    extern __shared__ char smem[];
    const uint32_t sb = smem_u32(smem);

    const int z = blockIdx.z;
    const float* bias = (z == 0) ? bq : (z == 1) ? bk : bv;
    __half* out = (z == 0) ? g_Q : (z == 1) ? g_K : g_V;
    const float scale = (z == 0) ? 0.125f * LOG2E : 1.0f;
    const __half* W = gW + (size_t)z * D_MODEL * D_MODEL;

    const int tid  = threadIdx.x;
    const int lane = tid & 31;
    const int wid  = tid >> 5;
    const int wm   = wid >> 2;        // 0..1 : 64-row strip
    const int wn   = wid & 3;         // 0..3 : 32-col strip
    const int g    = lane >> 2;
    const int tig  = lane & 3;
    const int mat  = lane >> 3;
    const int mr   = lane & 7;

    const int m0 = blockIdx.y * 128;
    const int n0 = blockIdx.x * 128;

    const int srow = tid >> 1;        // 0..127
    const int sch  = (tid & 1) * 32;  // byte offset 0 or 32

    const int gm = m0 + srow;
    const int szA = (gm < M_TOT) ? 16 : 0;
    const size_t arow_off = (size_t)min(gm, M_TOT - 1) * D_MODEL;
    const size_t brow_off = (size_t)(n0 + srow) * D_MODEL;

    float c[4][4][4];
#pragma unroll
    for (int mf = 0; mf < 4; mf++)
#pragma unroll
        for (int nf = 0; nf < 4; nf++)
#pragma unroll
            for (int cc = 0; cc < 4; cc++) c[mf][nf][cc] = 0.0f;

    auto issue = [&](int s) {
        const int k0 = s * 32;
        uint32_t d0 = sb + (s % NSTG) * BUFSZ + (uint32_t)srow * PITCH + sch;
        const char* sA = (const char*)(gX + arow_off + k0) + sch;
        const char* sB = (const char*)(W + brow_off + k0) + sch;
        cp16(d0,              sA,      szA);
        cp16(d0 + 16,         sA + 16, szA);
        cp16(d0 + TILEB,      sB,      16);
        cp16(d0 + TILEB + 16, sB + 16, 16);
    };

    issue(0); cp_commit();
    issue(1); cp_commit();

    for (int s = 0; s < 32; s++) {
        if (s + 2 < 32)      { issue(s + 2); cp_commit(); cp_wait2(); }
        else if (s + 1 < 32) cp_wait1();
        else                 cp_wait0();
        __syncthreads();

        const uint32_t base = sb + (s % NSTG) * BUFSZ;
#pragma unroll
        for (int t = 0; t < 2; t++) {
            uint32_t af[4][4];
#pragma unroll
            for (int mf = 0; mf < 4; mf++) {
                int arow = wm * 64 + mf * 16 + (mat & 1) * 8 + mr;
                uint32_t koff = t * 32 + (mat >> 1) * 16;
                uint32_t addr = base + (uint32_t)arow * PITCH + koff;
                ldm_x4(af[mf][0], af[mf][1], af[mf][2], af[mf][3], addr);
            }
            uint32_t bf[4][2];
#pragma unroll
            for (int nfp = 0; nfp < 2; nfp++) {
                int nrow = wn * 32 + nfp * 16 + (mat >> 1) * 8 + mr;
                uint32_t koff = t * 32 + (mat & 1) * 16;
                uint32_t addr = base + (uint32_t)nrow * PITCH + koff;
                ldm_x4(bf[2*nfp][0], bf[2*nfp][1], bf[2*nfp+1][0], bf[2*nfp+1][1],
                       addr + TILEB);
            }
#pragma unroll
            for (int mf = 0; mf < 4; mf++)
#pragma unroll
                for (int nf = 0; nf < 4; nf++)
                    mma16h(c[mf][nf], af[mf], bf[nf][0], bf[nf][1]);
        }
        __syncthreads();
    }

    // epilogue: bias + scale, fp16 scatter into [B,H,S,HD]
#pragma unroll
    for (int mf = 0; mf < 4; mf++) {
#pragma unroll
        for (int nf = 0; nf < 4; nf++) {
            int n = n0 + wn * 32 + nf * 8 + 2 * tig;
            int h = n >> 6, d = n & 63;
            float bv0 = __ldg(bias + n), bv1 = __ldg(bias + n + 1);
#pragma unroll
            for (int half = 0; half < 2; half++) {
                int m = m0 + wm * 64 + mf * 16 + g + half * 8;
                if (m < M_TOT) {
                    int bb = m / S_LEN;
                    int ss = m - bb * S_LEN;
                    __half2 hv = __floats2half2_rn(
                        (c[mf][nf][half * 2 + 0] + bv0) * scale,
                        (c[mf][nf][half * 2 + 1] + bv1) * scale);
                    *reinterpret_cast<__half2*>(
                        out + (((size_t)(bb * H_NUM + h) * S_LEN + ss) * HD + d)) = hv;
                }
            }
        }
    }
}

// ---------------------------------------------------------------------------
// Flash attention, fp16 m16n8k16. CTA = 128 queries, 4 warps x two 16-row
// query tiles. Row-sums kept as per-thread partials across all tiles
// (reduced once at the end). Rescale skipped via warp vote.
// ---------------------------------------------------------------------------
#define NEG_BIG (-1e30f)
#define APITCH  144                   // bytes per smem row (64 fp16 + 8 pad)
#define KVSTG   9216                  // one 64-row K or V stage
#define ATTN_SMEM 36864

__global__ __launch_bounds__(128) void attn_fp16(float* __restrict__ out)
{
    __shared__ char asmem[ATTN_SMEM];
    const uint32_t sbase = smem_u32(asmem);

    const int h  = blockIdx.y;
    const int b  = blockIdx.z;
    const int qt = blockIdx.x;
    const int tid  = threadIdx.x;
    const int lane = tid & 31;
    const int w    = tid >> 5;
    const int g    = lane >> 2;
    const int tig  = lane & 3;
    const int mat  = lane >> 3;
    const int mr   = lane & 7;

    const size_t base = (size_t)(b * H_NUM + h) * S_LEN * HD;
    const __half* Qb = g_Q + base;
    const __half* Kb = g_K + base;
    const __half* Vb = g_V + base;

    // ---- stage Q (128 rows) into [0,18432), consume into registers ----
#pragma unroll
    for (int p = 0; p < 8; p++) {
        int idx = tid + 128 * p;       // 0..1023
        int row = idx >> 3;
        int ch  = idx & 7;
        int qi = qt * 128 + row;
        int sz = (qi < S_LEN) ? 16 : 0;
        const char* src = (const char*)(Qb + (size_t)min(qi, S_LEN - 1) * HD) + ch * 16;
        cp16(sbase + (uint32_t)row * APITCH + ch * 16, src, sz);
    }
    cp_commit();
    cp_wait0();
    __syncthreads();

    uint32_t qa[2][4][4];
#pragma unroll
    for (int u = 0; u < 2; u++)
#pragma unroll
        for (int ks = 0; ks < 4; ks++) {
            uint32_t addr = sbase
                + (uint32_t)(w * 32 + u * 16 + (mat & 1) * 8 + mr) * APITCH
                + ks * 32 + (mat >> 1) * 16;
            ldm_x4(qa[u][ks][0], qa[u][ks][1], qa[u][ks][2], qa[u][ks][3], addr);
        }
    __syncthreads();   // Q reads done; region reusable as K stages

    auto issue_kv = [&](int kt, int bb) {
#pragma unroll
        for (int p = 0; p < 4; p++) {
            int idx = tid + 128 * p;
            int row = idx >> 3;
            int ch  = idx & 7;
            int ki = kt * 64 + row;
            int sz = (ki < S_LEN) ? 16 : 0;
            size_t roff = (size_t)min(ki, S_LEN - 1) * HD;
            cp16(sbase + bb * KVSTG + (uint32_t)row * APITCH + ch * 16,
                 (const char*)(Kb + roff) + ch * 16, sz);
            cp16(sbase + 18432 + bb * KVSTG + (uint32_t)row * APITCH + ch * 16,
                 (const char*)(Vb + roff) + ch * 16, sz);
        }
    };

    issue_kv(0, 0);
    cp_commit();

    // hoisted per-thread ldmatrix offsets
    const uint32_t koffb = (uint32_t)((mat >> 1) * 8 + mr) * APITCH + (mat & 1) * 16;
    const uint32_t voffb = (uint32_t)((mat & 1) * 8 + mr) * APITCH + (mat >> 1) * 16;

    float oc[2][8][4];
    float l1[2] = {0.f, 0.f}, l2[2] = {0.f, 0.f};
#pragma unroll
    for (int u = 0; u < 2; u++)
#pragma unroll
        for (int nf = 0; nf < 8; nf++)
#pragma unroll
            for (int cc = 0; cc < 4; cc++) oc[u][nf][cc] = 0.0f;
    float m1[2] = {NEG_BIG, NEG_BIG}, m2[2] = {NEG_BIG, NEG_BIG};

    const int ntiles = (S_LEN + 63) / 64;    // 22
    for (int kt = 0; kt < ntiles; kt++) {
        if (kt + 1 < ntiles) { issue_kv(kt + 1, (kt + 1) & 1); cp_commit(); cp_wait1(); }
        else cp_wait0();
        __syncthreads();

        const int rem = min(64, S_LEN - kt * 64);
        const uint32_t sbK = sbase + (kt & 1) * KVSTG;
        const uint32_t sbV = sbase + 18432 + (kt & 1) * KVSTG;

        // ---- S = Q K^T (log2-domain) ----
        float sc[2][8][4];
#pragma unroll
        for (int u = 0; u < 2; u++)
#pragma unroll
            for (int nf = 0; nf < 8; nf++)
#pragma unroll
                for (int cc = 0; cc < 4; cc++) sc[u][nf][cc] = 0.0f;

#pragma unroll
        for (int ks = 0; ks < 4; ks++) {
#pragma unroll
            for (int nf2 = 0; nf2 < 4; nf2++) {
                uint32_t r0, rr1, rr2, rr3;
                uint32_t addr = sbK + koffb + (uint32_t)(nf2 * 16) * APITCH + ks * 32;
                ldm_x4(r0, rr1, rr2, rr3, addr);
#pragma unroll
                for (int u = 0; u < 2; u++) {
                    mma16h(sc[u][2 * nf2],     qa[u][ks], r0,  rr1);
                    mma16h(sc[u][2 * nf2 + 1], qa[u][ks], rr2, rr3);
                }
            }
        }

#pragma unroll
        for (int u = 0; u < 2; u++) {
            if (rem < 64) {
#pragma unroll
                for (int nf = 0; nf < 8; nf++) {
                    int col = nf * 8 + 2 * tig;
                    if (col     >= rem) { sc[u][nf][0] = NEG_BIG; sc[u][nf][2] = NEG_BIG; }
                    if (col + 1 >= rem) { sc[u][nf][1] = NEG_BIG; sc[u][nf][3] = NEG_BIG; }
                }
            }

            float rmax1 = NEG_BIG, rmax2 = NEG_BIG;
#pragma unroll
            for (int nf = 0; nf < 8; nf++) {
                rmax1 = fmaxf(rmax1, fmaxf(sc[u][nf][0], sc[u][nf][1]));
                rmax2 = fmaxf(rmax2, fmaxf(sc[u][nf][2], sc[u][nf][3]));
            }
            rmax1 = fmaxf(rmax1, __shfl_xor_sync(0xffffffffu, rmax1, 1));
            rmax1 = fmaxf(rmax1, __shfl_xor_sync(0xffffffffu, rmax1, 2));
            rmax2 = fmaxf(rmax2, __shfl_xor_sync(0xffffffffu, rmax2, 1));
            rmax2 = fmaxf(rmax2, __shfl_xor_sync(0xffffffffu, rmax2, 2));

            float nm1 = fmaxf(m1[u], rmax1);
            float nm2 = fmaxf(m2[u], rmax2);

            bool moved = (nm1 > m1[u]) || (nm2 > m2[u]);
            if (__any_sync(0xffffffffu, moved)) {
                float corr1 = ex2(m1[u] - nm1);
                float corr2 = ex2(m2[u] - nm2);
#pragma unroll
                for (int nf = 0; nf < 8; nf++) {
                    oc[u][nf][0] *= corr1; oc[u][nf][1] *= corr1;
                    oc[u][nf][2] *= corr2; oc[u][nf][3] *= corr2;
                }
                l1[u] *= corr1;
                l2[u] *= corr2;
                m1[u] = nm1; m2[u] = nm2;
            }

            float ps1 = 0.f, ps2 = 0.f;
#pragma unroll
            for (int nf = 0; nf < 8; nf++) {
                sc[u][nf][0] = ex2(sc[u][nf][0] - m1[u]);
                sc[u][nf][1] = ex2(sc[u][nf][1] - m1[u]);
                sc[u][nf][2] = ex2(sc[u][nf][2] - m2[u]);
                sc[u][nf][3] = ex2(sc[u][nf][3] - m2[u]);
                ps1 += sc[u][nf][0] + sc[u][nf][1];
                ps2 += sc[u][nf][2] + sc[u][nf][3];
            }
            l1[u] += ps1;
            l2[u] += ps2;
        }

        // ---- O += P V ----
#pragma unroll
        for (int ks = 0; ks < 4; ks++) {
            uint32_t pa[2][4];
#pragma unroll
            for (int u = 0; u < 2; u++) {
                pa[u][0] = h2pack(sc[u][2*ks][0],   sc[u][2*ks][1]);
                pa[u][1] = h2pack(sc[u][2*ks][2],   sc[u][2*ks][3]);
                pa[u][2] = h2pack(sc[u][2*ks+1][0], sc[u][2*ks+1][1]);
                pa[u][3] = h2pack(sc[u][2*ks+1][2], sc[u][2*ks+1][3]);
            }
#pragma unroll
            for (int nf2 = 0; nf2 < 4; nf2++) {
                uint32_t r0, rr1, rr2, rr3;
                uint32_t addr = sbV + voffb + (uint32_t)(ks * 16) * APITCH + nf2 * 32;
                ldm_x4t(r0, rr1, rr2, rr3, addr);
#pragma unroll
                for (int u = 0; u < 2; u++) {
                    mma16h(oc[u][2 * nf2],     pa[u], r0,  rr1);
                    mma16h(oc[u][2 * nf2 + 1], pa[u], rr2, rr3);
                }
            }
        }
        __syncthreads();
    }

    // ---- final row-sum reduction + normalize + write [B,S,H*HD] fp32 ----
#pragma unroll
    for (int u = 0; u < 2; u++) {
        float s1 = l1[u], s2 = l2[u];
        s1 += __shfl_xor_sync(0xffffffffu, s1, 1);
        s1 += __shfl_xor_sync(0xffffffffu, s1, 2);
        s2 += __shfl_xor_sync(0xffffffffu, s2, 1);
        s2 += __shfl_xor_sync(0xffffffffu, s2, 2);
        const int r1 = qt * 128 + w * 32 + u * 16 + g;
        const int r2 = r1 + 8;
        float inv1 = 1.0f / s1;
        float inv2 = 1.0f / s2;
#pragma unroll
        for (int nf = 0; nf < 8; nf++) {
            int d = nf * 8 + 2 * tig;
            if (r1 < S_LEN) {
                float2 v; v.x = oc[u][nf][0] * inv1; v.y = oc[u][nf][1] * inv1;
                *reinterpret_cast<float2*>(
                    out + (size_t)(b * S_LEN + r1) * D_MODEL + h * HD + d) = v;
            }
            if (r2 < S_LEN) {
                float2 v; v.x = oc[u][nf][2] * inv2; v.y = oc[u][nf][3] * inv2;
                *reinterpret_cast<float2*>(
                    out + (size_t)(b * S_LEN + r2) * D_MODEL + h * HD + d) = v;
            }
        }
    }
}

// ---------------------------------------------------------------------------
extern "C" void kernel_launch(void* const* d_in, const int* in_sizes, int n_in,
                              void* d_out, int out_size)
{
    const float* X  = (const float*)d_in[0];
    const float* Wq = (const float*)d_in[1];
    const float* bq = (const float*)d_in[2];
    const float* Wk = (const float*)d_in[3];
    const float* bk = (const float*)d_in[4];
    const float* Wv = (const float*)d_in[5];
    const float* bv = (const float*)d_in[6];
    float* out = (float*)d_out;

    static int once = 0;
    if (!once) {
        cudaFuncSetAttribute(qkv_fp16, cudaFuncAttributeMaxDynamicSharedMemorySize, GEMM_SMEM);
        once = 1;
    }

    const int ntot = N4X + 3 * N4W;
    conv_all<<<(ntot + 255) / 256, 256>>>(X, Wq, Wk, Wv);

    dim3 g1(D_MODEL / 128, (M_TOT + 127) / 128, 3);
    qkv_fp16<<<g1, 256, GEMM_SMEM>>>(bq, bk, bv);

    dim3 g2((S_LEN + 127) / 128, H_NUM, B_SZ);
    attn_fp16<<<g2, 128>>>(out);
}

// round 11
// speedup vs baseline: 8.1382x; 1.0718x over previous
#include <cuda_runtime.h>
#include <cuda_fp16.h>
#include <stdint.h>

#define S_LEN   1370
#define B_SZ    8
#define D_MODEL 1024
#define H_NUM   16
#define HD      64
#define M_TOT   (B_SZ * S_LEN)   // 10960
#define LOG2E   1.4426950408889634f

// pre-converted GEMM operands (single fp16)
__device__ __half gX[(size_t)M_TOT * D_MODEL];
__device__ __half gW[3ull * D_MODEL * D_MODEL];
// projected Q/K/V in fp16, [B,H,S,HD]; Q pre-scaled by 0.125*log2(e)
__device__ __half g_Q[(size_t)M_TOT * D_MODEL];
__device__ __half g_K[(size_t)M_TOT * D_MODEL];
__device__ __half g_V[(size_t)M_TOT * D_MODEL];

// ---------------------------------------------------------------------------
// helpers
// ---------------------------------------------------------------------------
__device__ __forceinline__ uint32_t smem_u32(const void* p) {
    return (uint32_t)__cvta_generic_to_shared(p);
}
__device__ __forceinline__ void cp16(uint32_t dst, const void* src, int sz) {
    asm volatile("cp.async.cg.shared.global [%0], [%1], 16, %2;"
                 :: "r"(dst), "l"(src), "r"(sz) : "memory");
}
__device__ __forceinline__ void cp_commit() {
    asm volatile("cp.async.commit_group;" ::: "memory");
}
__device__ __forceinline__ void cp_wait1() {
    asm volatile("cp.async.wait_group 1;" ::: "memory");
}
__device__ __forceinline__ void cp_wait0() {
    asm volatile("cp.async.wait_group 0;" ::: "memory");
}
__device__ __forceinline__ void ldm_x4(uint32_t& r0, uint32_t& r1, uint32_t& r2, uint32_t& r3,
                                       uint32_t addr) {
    asm volatile("ldmatrix.sync.aligned.m8n8.x4.shared.b16 {%0,%1,%2,%3}, [%4];"
                 : "=r"(r0), "=r"(r1), "=r"(r2), "=r"(r3) : "r"(addr));
}
__device__ __forceinline__ void ldm_x4t(uint32_t& r0, uint32_t& r1, uint32_t& r2, uint32_t& r3,
                                        uint32_t addr) {
    asm volatile("ldmatrix.sync.aligned.m8n8.x4.trans.shared.b16 {%0,%1,%2,%3}, [%4];"
                 : "=r"(r0), "=r"(r1), "=r"(r2), "=r"(r3) : "r"(addr));
}
__device__ __forceinline__ void mma16h(float* c, const uint32_t* a, uint32_t b0, uint32_t b1) {
    asm volatile(
        "mma.sync.aligned.m16n8k16.row.col.f32.f16.f16.f32 "
        "{%0,%1,%2,%3},{%4,%5,%6,%7},{%8,%9},{%0,%1,%2,%3};\n"
        : "+f"(c[0]), "+f"(c[1]), "+f"(c[2]), "+f"(c[3])
        : "r"(a[0]), "r"(a[1]), "r"(a[2]), "r"(a[3]), "r"(b0), "r"(b1));
}
__device__ __forceinline__ uint32_t h2pack(float lo, float hi) {
    __half2 h = __floats2half2_rn(lo, hi);
    return *reinterpret_cast<uint32_t*>(&h);
}
__device__ __forceinline__ float ex2(float x) {
    float y;
    asm("ex2.approx.f32 %0, %1;" : "=f"(y) : "f"(x));
    return y;
}
// two fp16 exponentials in one MUFU op
__device__ __forceinline__ uint32_t ex2h2(uint32_t x) {
    uint32_t y;
    asm("ex2.approx.f16x2 %0, %1;" : "=r"(y) : "r"(x));
    return y;
}
__device__ __forceinline__ __half2 u2h(uint32_t x) {
    return *reinterpret_cast<__half2*>(&x);
}

// ---------------------------------------------------------------------------
// Pre-convert fp32 -> fp16, single fused launch.
// ---------------------------------------------------------------------------
#define N4X (M_TOT * D_MODEL / 4)          // 2,805,760
#define N4W (D_MODEL * D_MODEL / 4)        // 262,144 = 2^18

__global__ void conv_all(const float* __restrict__ X,
                         const float* __restrict__ w0,
                         const float* __restrict__ w1,
                         const float* __restrict__ w2)
{
    int i = blockIdx.x * 256 + threadIdx.x;
    if (i >= N4X + 3 * N4W) return;
    const float* src;
    __half* dst;
    int idx;
    if (i < N4X) {
        src = X; dst = gX; idx = i;
    } else {
        int j = i - N4X;
        int plane = j >> 18;
        idx = j & (N4W - 1);
        src = (plane == 0) ? w0 : (plane == 1) ? w1 : w2;
        dst = gW + (size_t)plane * D_MODEL * D_MODEL;
    }
    float4 v = reinterpret_cast<const float4*>(src)[idx];
    uint32_t h0 = __half_as_ushort(__float2half_rn(v.x)) |
                  ((uint32_t)__half_as_ushort(__float2half_rn(v.y)) << 16);
    uint32_t h1 = __half_as_ushort(__float2half_rn(v.z)) |
                  ((uint32_t)__half_as_ushort(__float2half_rn(v.w)) << 16);
    reinterpret_cast<uint2*>(dst)[idx] = make_uint2(h0, h1);
}

// ---------------------------------------------------------------------------
// QKV projection: y = X @ W^T + b (single-pass fp16 m16n8k16).
// Block 128x128, 256 threads (8 warps, 2x4), warp tile 64x32, K slab 32,
// cp.async 3-stage pipelined (race-free: issue AFTER barrier), 2 CTAs/SM.
// ---------------------------------------------------------------------------
#define PITCH  80
#define TILEB  10240                 // one 128x32 fp16 tile (pitch 80)
#define BUFSZ  (2 * TILEB)           // A, B
#define NSTG   3
#define GEMM_SMEM (NSTG * BUFSZ)     // 61440

__global__ __launch_bounds__(256, 2) void qkv_fp16(
    const float* __restrict__ bq, const float* __restrict__ bk,
    const float* __restrict__ bv)
{
    extern __shared__ char smem[];
    const uint32_t sb = smem_u32(smem);

    const int z = blockIdx.z;
    const float* bias = (z == 0) ? bq : (z == 1) ? bk : bv;
    __half* out = (z == 0) ? g_Q : (z == 1) ? g_K : g_V;
    const float scale = (z == 0) ? 0.125f * LOG2E : 1.0f;
    const __half* W = gW + (size_t)z * D_MODEL * D_MODEL;

    const int tid  = threadIdx.x;
    const int lane = tid & 31;
    const int wid  = tid >> 5;
    const int wm   = wid >> 2;        // 0..1 : 64-row strip
    const int wn   = wid & 3;         // 0..3 : 32-col strip
    const int g    = lane >> 2;
    const int tig  = lane & 3;
    const int mat  = lane >> 3;
    const int mr   = lane & 7;

    const int m0 = blockIdx.y * 128;
    const int n0 = blockIdx.x * 128;

    const int srow = tid >> 1;        // 0..127
    const int sch  = (tid & 1) * 32;  // byte offset 0 or 32

    const int gm = m0 + srow;
    const int szA = (gm < M_TOT) ? 16 : 0;
    const size_t arow_off = (size_t)min(gm, M_TOT - 1) * D_MODEL;
    const size_t brow_off = (size_t)(n0 + srow) * D_MODEL;

    float c[4][4][4];
#pragma unroll
    for (int mf = 0; mf < 4; mf++)
#pragma unroll
        for (int nf = 0; nf < 4; nf++)
#pragma unroll
            for (int cc = 0; cc < 4; cc++) c[mf][nf][cc] = 0.0f;

    auto issue = [&](int s) {
        const int k0 = s * 32;
        uint32_t d0 = sb + (s % NSTG) * BUFSZ + (uint32_t)srow * PITCH + sch;
        const char* sA = (const char*)(gX + arow_off + k0) + sch;
        const char* sB = (const char*)(W + brow_off + k0) + sch;
        cp16(d0,              sA,      szA);
        cp16(d0 + 16,         sA + 16, szA);
        cp16(d0 + TILEB,      sB,      16);
        cp16(d0 + TILEB + 16, sB + 16, 16);
    };

    issue(0); cp_commit();
    issue(1); cp_commit();

    for (int s = 0; s < 32; s++) {
        if (s + 1 < 32) cp_wait1(); else cp_wait0();
        __syncthreads();
        // issue AFTER barrier: all warps have finished reading buffer (s-1)%3
        // == (s+2)%3, so the prefetch can't race the previous slab's readers.
        if (s + 2 < 32) { issue(s + 2); cp_commit(); }

        const uint32_t base = sb + (s % NSTG) * BUFSZ;
#pragma unroll
        for (int t = 0; t < 2; t++) {
            uint32_t af[4][4];
#pragma unroll
            for (int mf = 0; mf < 4; mf++) {
                int arow = wm * 64 + mf * 16 + (mat & 1) * 8 + mr;
                uint32_t koff = t * 32 + (mat >> 1) * 16;
                uint32_t addr = base + (uint32_t)arow * PITCH + koff;
                ldm_x4(af[mf][0], af[mf][1], af[mf][2], af[mf][3], addr);
            }
            uint32_t bf[4][2];
#pragma unroll
            for (int nfp = 0; nfp < 2; nfp++) {
                int nrow = wn * 32 + nfp * 16 + (mat >> 1) * 8 + mr;
                uint32_t koff = t * 32 + (mat & 1) * 16;
                uint32_t addr = base + (uint32_t)nrow * PITCH + koff;
                ldm_x4(bf[2*nfp][0], bf[2*nfp][1], bf[2*nfp+1][0], bf[2*nfp+1][1],
                       addr + TILEB);
            }
#pragma unroll
            for (int mf = 0; mf < 4; mf++)
#pragma unroll
                for (int nf = 0; nf < 4; nf++)
                    mma16h(c[mf][nf], af[mf], bf[nf][0], bf[nf][1]);
        }
    }

    // epilogue: bias + scale, fp16 scatter into [B,H,S,HD]
#pragma unroll
    for (int mf = 0; mf < 4; mf++) {
#pragma unroll
        for (int nf = 0; nf < 4; nf++) {
            int n = n0 + wn * 32 + nf * 8 + 2 * tig;
            int h = n >> 6, d = n & 63;
            float bv0 = __ldg(bias + n), bv1 = __ldg(bias + n + 1);
#pragma unroll
            for (int half = 0; half < 2; half++) {
                int m = m0 + wm * 64 + mf * 16 + g + half * 8;
                if (m < M_TOT) {
                    int bb = m / S_LEN;
                    int ss = m - bb * S_LEN;
                    __half2 hv = __floats2half2_rn(
                        (c[mf][nf][half * 2 + 0] + bv0) * scale,
                        (c[mf][nf][half * 2 + 1] + bv1) * scale);
                    *reinterpret_cast<__half2*>(
                        out + (((size_t)(bb * H_NUM + h) * S_LEN + ss) * HD + d)) = hv;
                }
            }
        }
    }
}

// ---------------------------------------------------------------------------
// Flash attention, fp16 m16n8k16. CTA = 128 queries, 4 warps x two 16-row
// query tiles. Softmax exp via ex2.approx.f16x2 (halves MUFU); P emerges
// fp16-packed for the PV mma; row sums via HADD2 trees. One barrier/tile
// (prefetch issued after the barrier).
// ---------------------------------------------------------------------------
#define NEG_BIG (-30000.0f)
#define APITCH  144                   // bytes per smem row (64 fp16 + 8 pad)
#define KVSTG   9216                  // one 64-row K or V stage
#define ATTN_SMEM 36864

__global__ __launch_bounds__(128) void attn_fp16(float* __restrict__ out)
{
    __shared__ char asmem[ATTN_SMEM];
    const uint32_t sbase = smem_u32(asmem);

    const int h  = blockIdx.y;
    const int b  = blockIdx.z;
    const int qt = blockIdx.x;
    const int tid  = threadIdx.x;
    const int lane = tid & 31;
    const int w    = tid >> 5;
    const int g    = lane >> 2;
    const int tig  = lane & 3;
    const int mat  = lane >> 3;
    const int mr   = lane & 7;

    const size_t base = (size_t)(b * H_NUM + h) * S_LEN * HD;
    const __half* Qb = g_Q + base;
    const __half* Kb = g_K + base;
    const __half* Vb = g_V + base;

    // ---- stage Q (128 rows) into [0,18432), consume into registers ----
#pragma unroll
    for (int p = 0; p < 8; p++) {
        int idx = tid + 128 * p;       // 0..1023
        int row = idx >> 3;
        int ch  = idx & 7;
        int qi = qt * 128 + row;
        int sz = (qi < S_LEN) ? 16 : 0;
        const char* src = (const char*)(Qb + (size_t)min(qi, S_LEN - 1) * HD) + ch * 16;
        cp16(sbase + (uint32_t)row * APITCH + ch * 16, src, sz);
    }
    cp_commit();
    cp_wait0();
    __syncthreads();

    uint32_t qa[2][4][4];
#pragma unroll
    for (int u = 0; u < 2; u++)
#pragma unroll
        for (int ks = 0; ks < 4; ks++) {
            uint32_t addr = sbase
                + (uint32_t)(w * 32 + u * 16 + (mat & 1) * 8 + mr) * APITCH
                + ks * 32 + (mat >> 1) * 16;
            ldm_x4(qa[u][ks][0], qa[u][ks][1], qa[u][ks][2], qa[u][ks][3], addr);
        }
    __syncthreads();   // Q reads done; region reusable as K stages

    auto issue_kv = [&](int kt, int bb) {
#pragma unroll
        for (int p = 0; p < 4; p++) {
            int idx = tid + 128 * p;
            int row = idx >> 3;
            int ch  = idx & 7;
            int ki = kt * 64 + row;
            int sz = (ki < S_LEN) ? 16 : 0;
            size_t roff = (size_t)min(ki, S_LEN - 1) * HD;
            cp16(sbase + bb * KVSTG + (uint32_t)row * APITCH + ch * 16,
                 (const char*)(Kb + roff) + ch * 16, sz);
            cp16(sbase + 18432 + bb * KVSTG + (uint32_t)row * APITCH + ch * 16,
                 (const char*)(Vb + roff) + ch * 16, sz);
        }
    };

    issue_kv(0, 0);
    cp_commit();

    // hoisted per-thread ldmatrix offsets
    const uint32_t koffb = (uint32_t)((mat >> 1) * 8 + mr) * APITCH + (mat & 1) * 16;
    const uint32_t voffb = (uint32_t)((mat & 1) * 8 + mr) * APITCH + (mat >> 1) * 16;

    float oc[2][8][4];
    float l1[2] = {0.f, 0.f}, l2[2] = {0.f, 0.f};
#pragma unroll
    for (int u = 0; u < 2; u++)
#pragma unroll
        for (int nf = 0; nf < 8; nf++)
#pragma unroll
            for (int cc = 0; cc < 4; cc++) oc[u][nf][cc] = 0.0f;
    float m1[2] = {NEG_BIG, NEG_BIG}, m2[2] = {NEG_BIG, NEG_BIG};

    const int ntiles = (S_LEN + 63) / 64;    // 22
    for (int kt = 0; kt < ntiles; kt++) {
        cp_wait0();
        __syncthreads();
        // prefetch AFTER barrier: all warps finished reading buffer (kt-1)&1
        if (kt + 1 < ntiles) { issue_kv(kt + 1, (kt + 1) & 1); cp_commit(); }

        const int rem = min(64, S_LEN - kt * 64);
        const uint32_t sbK = sbase + (kt & 1) * KVSTG;
        const uint32_t sbV = sbase + 18432 + (kt & 1) * KVSTG;

        // ---- S = Q K^T (log2-domain) ----
        float sc[2][8][4];
#pragma unroll
        for (int u = 0; u < 2; u++)
#pragma unroll
            for (int nf = 0; nf < 8; nf++)
#pragma unroll
                for (int cc = 0; cc < 4; cc++) sc[u][nf][cc] = 0.0f;

#pragma unroll
        for (int ks = 0; ks < 4; ks++) {
#pragma unroll
            for (int nf2 = 0; nf2 < 4; nf2++) {
                uint32_t r0, rr1, rr2, rr3;
                uint32_t addr = sbK + koffb + (uint32_t)(nf2 * 16) * APITCH + ks * 32;
                ldm_x4(r0, rr1, rr2, rr3, addr);
#pragma unroll
                for (int u = 0; u < 2; u++) {
                    mma16h(sc[u][2 * nf2],     qa[u][ks], r0,  rr1);
                    mma16h(sc[u][2 * nf2 + 1], qa[u][ks], rr2, rr3);
                }
            }
        }

        // ---- softmax: max, (skip-)rescale, fp16x2 exp, half2 row sums ----
        uint32_t pp[2][8][2];
#pragma unroll
        for (int u = 0; u < 2; u++) {
            if (rem < 64) {
#pragma unroll
                for (int nf = 0; nf < 8; nf++) {
                    int col = nf * 8 + 2 * tig;
                    if (col     >= rem) { sc[u][nf][0] = NEG_BIG; sc[u][nf][2] = NEG_BIG; }
                    if (col + 1 >= rem) { sc[u][nf][1] = NEG_BIG; sc[u][nf][3] = NEG_BIG; }
                }
            }

            float rmax1 = NEG_BIG, rmax2 = NEG_BIG;
#pragma unroll
            for (int nf = 0; nf < 8; nf++) {
                rmax1 = fmaxf(rmax1, fmaxf(sc[u][nf][0], sc[u][nf][1]));
                rmax2 = fmaxf(rmax2, fmaxf(sc[u][nf][2], sc[u][nf][3]));
            }
            rmax1 = fmaxf(rmax1, __shfl_xor_sync(0xffffffffu, rmax1, 1));
            rmax1 = fmaxf(rmax1, __shfl_xor_sync(0xffffffffu, rmax1, 2));
            rmax2 = fmaxf(rmax2, __shfl_xor_sync(0xffffffffu, rmax2, 1));
            rmax2 = fmaxf(rmax2, __shfl_xor_sync(0xffffffffu, rmax2, 2));

            float nm1 = fmaxf(m1[u], rmax1);
            float nm2 = fmaxf(m2[u], rmax2);

            bool moved = (nm1 > m1[u]) || (nm2 > m2[u]);
            if (__any_sync(0xffffffffu, moved)) {
                float corr1 = ex2(m1[u] - nm1);
                float corr2 = ex2(m2[u] - nm2);
#pragma unroll
                for (int nf = 0; nf < 8; nf++) {
                    oc[u][nf][0] *= corr1; oc[u][nf][1] *= corr1;
                    oc[u][nf][2] *= corr2; oc[u][nf][3] *= corr2;
                }
                l1[u] *= corr1;
                l2[u] *= corr2;
                m1[u] = nm1; m2[u] = nm2;
            }

            // subtract (f32), pack to f16x2, exponentiate pairwise on MUFU
#pragma unroll
            for (int nf = 0; nf < 8; nf++) {
                pp[u][nf][0] = ex2h2(h2pack(sc[u][nf][0] - m1[u], sc[u][nf][1] - m1[u]));
                pp[u][nf][1] = ex2h2(h2pack(sc[u][nf][2] - m2[u], sc[u][nf][3] - m2[u]));
            }

            // row sums via HADD2 trees (16 halves per row, values <= 1 each)
            __half2 s1 = __hadd2(
                __hadd2(__hadd2(u2h(pp[u][0][0]), u2h(pp[u][1][0])),
                        __hadd2(u2h(pp[u][2][0]), u2h(pp[u][3][0]))),
                __hadd2(__hadd2(u2h(pp[u][4][0]), u2h(pp[u][5][0])),
                        __hadd2(u2h(pp[u][6][0]), u2h(pp[u][7][0]))));
            __half2 s2 = __hadd2(
                __hadd2(__hadd2(u2h(pp[u][0][1]), u2h(pp[u][1][1])),
                        __hadd2(u2h(pp[u][2][1]), u2h(pp[u][3][1]))),
                __hadd2(__hadd2(u2h(pp[u][4][1]), u2h(pp[u][5][1])),
                        __hadd2(u2h(pp[u][6][1]), u2h(pp[u][7][1]))));
            float2 f1 = __half22float2(s1);
            float2 f2 = __half22float2(s2);
            l1[u] += f1.x + f1.y;
            l2[u] += f2.x + f2.y;
        }

        // ---- O += P V (P already fp16-packed in pp) ----
#pragma unroll
        for (int ks = 0; ks < 4; ks++) {
#pragma unroll
            for (int nf2 = 0; nf2 < 4; nf2++) {
                uint32_t r0, rr1, rr2, rr3;
                uint32_t addr = sbV + voffb + (uint32_t)(ks * 16) * APITCH + nf2 * 32;
                ldm_x4t(r0, rr1, rr2, rr3, addr);
#pragma unroll
                for (int u = 0; u < 2; u++) {
                    mma16h(oc[u][2 * nf2],     &pp[u][2 * ks][0], r0,  rr1);
                    mma16h(oc[u][2 * nf2 + 1], &pp[u][2 * ks][0], rr2, rr3);
                }
            }
        }
    }

    // ---- final row-sum reduction + normalize + write [B,S,H*HD] fp32 ----
#pragma unroll
    for (int u = 0; u < 2; u++) {
        float s1 = l1[u], s2 = l2[u];
        s1 += __shfl_xor_sync(0xffffffffu, s1, 1);
        s1 += __shfl_xor_sync(0xffffffffu, s1, 2);
        s2 += __shfl_xor_sync(0xffffffffu, s2, 1);
        s2 += __shfl_xor_sync(0xffffffffu, s2, 2);
        const int r1 = qt * 128 + w * 32 + u * 16 + g;
        const int r2 = r1 + 8;
        float inv1 = 1.0f / s1;
        float inv2 = 1.0f / s2;
#pragma unroll
        for (int nf = 0; nf < 8; nf++) {
            int d = nf * 8 + 2 * tig;
            if (r1 < S_LEN) {
                float2 v; v.x = oc[u][nf][0] * inv1; v.y = oc[u][nf][1] * inv1;
                *reinterpret_cast<float2*>(
                    out + (size_t)(b * S_LEN + r1) * D_MODEL + h * HD + d) = v;
            }
            if (r2 < S_LEN) {
                float2 v; v.x = oc[u][nf][2] * inv2; v.y = oc[u][nf][3] * inv2;
                *reinterpret_cast<float2*>(
                    out + (size_t)(b * S_LEN + r2) * D_MODEL + h * HD + d) = v;
            }
        }
    }
}

// ---------------------------------------------------------------------------
extern "C" void kernel_launch(void* const* d_in, const int* in_sizes, int n_in,
                              void* d_out, int out_size)
{
    const float* X  = (const float*)d_in[0];
    const float* Wq = (const float*)d_in[1];
    const float* bq = (const float*)d_in[2];
    const float* Wk = (const float*)d_in[3];
    const float* bk = (const float*)d_in[4];
    const float* Wv = (const float*)d_in[5];
    const float* bv = (const float*)d_in[6];
    float* out = (float*)d_out;

    static int once = 0;
    if (!once) {
        cudaFuncSetAttribute(qkv_fp16, cudaFuncAttributeMaxDynamicSharedMemorySize, GEMM_SMEM);
        once = 1;
    }

    const int ntot = N4X + 3 * N4W;
    conv_all<<<(ntot + 255) / 256, 256>>>(X, Wq, Wk, Wv);

    dim3 g1(D_MODEL / 128, (M_TOT + 127) / 128, 3);
    qkv_fp16<<<g1, 256, GEMM_SMEM>>>(bq, bk, bv);

    dim3 g2((S_LEN + 127) / 128, H_NUM, B_SZ);
    attn_fp16<<<g2, 128>>>(out);
}